// round 2
// baseline (speedup 1.0000x reference)
#include <cuda_runtime.h>
#include <math.h>

// Problem dims
#define B_   4
#define LQ_  1024
#define LKV_ 2048
#define D_   1024
#define H_   16
#define HD_  64

// ---------------- scratch (no allocs allowed) ----------------
__device__ float g_qn  [B_ * LQ_  * D_];        // 16 MB
__device__ float g_kvn [B_ * LKV_ * D_];        // 32 MB
__device__ float g_qh  [B_ * LQ_  * D_];        // 16 MB
__device__ float g_kvp [B_ * LKV_ * 2 * D_];    // 64 MB
__device__ float g_attn[B_ * LQ_  * D_];        // 16 MB
__device__ int   g_len [B_];

// ---------------- mask dtype sniffing + per-batch lengths ----------------
// mask[b,k] = (k >= length_b), monotone suffix of "true".
// Layout may be bool/int8 (1B), int32 (4B), or float32 (4B). Only the first
// 8192 bytes are read during detection (safe under every layout).
__global__ void compute_lengths_kernel(const unsigned char* __restrict__ mask) {
    __shared__ int det[4];
    __shared__ int cnt[4];
    __shared__ int mode;  // 0 = 1-byte bool, 1 = int32, 2 = float32
    int tid = threadIdx.x;
    if (tid < 4) { det[tid] = 0; cnt[tid] = 0; }
    __syncthreads();
    for (int i = tid; i < B_ * LKV_; i += blockDim.x) {
        if (mask[i]) atomicOr(&det[i & 3], 1);
    }
    __syncthreads();
    if (tid == 0) {
        if (det[1])                   mode = 0;                  // only bool hits residue 1
        else if (det[2] || det[3])    mode = det[0] ? 0 : 2;     // float32 1.0f = 00 00 80 3F
        else if (det[0])              mode = 1;                  // int32 value 1
        else                          mode = 0;                  // all-false
    }
    __syncthreads();
    int md = mode;
    for (int b = 0; b < B_; b++) {
        int local = 0;
        for (int k = tid; k < LKV_; k += blockDim.x) {
            int idx = b * LKV_ + k;
            bool t;
            if      (md == 0) t = mask[idx] != 0;
            else if (md == 1) t = ((const int*)  mask)[idx] != 0;
            else              t = ((const float*)mask)[idx] != 0.0f;
            if (!t) local++;
        }
        atomicAdd(&cnt[b], local);  // monotone suffix => #false == length
    }
    __syncthreads();
    if (tid < B_) g_len[tid] = cnt[tid];
}

// ---------------- layernorm: one block per row of D_=1024 ----------------
__global__ void __launch_bounds__(256) layernorm_kernel(
    const float* __restrict__ x, const float* __restrict__ w,
    const float* __restrict__ bb, float* __restrict__ y)
{
    int row = blockIdx.x;
    int tid = threadIdx.x;
    const float* xr = x + (size_t)row * D_;
    float4 v = *(const float4*)(xr + tid * 4);
    float s  = v.x + v.y + v.z + v.w;
    float sq = v.x * v.x + v.y * v.y + v.z * v.z + v.w * v.w;
    #pragma unroll
    for (int o = 16; o; o >>= 1) {
        s  += __shfl_xor_sync(0xffffffffu, s,  o);
        sq += __shfl_xor_sync(0xffffffffu, sq, o);
    }
    __shared__ float ss[8], ssq[8];
    int wid = tid >> 5, ln = tid & 31;
    if (ln == 0) { ss[wid] = s; ssq[wid] = sq; }
    __syncthreads();
    if (tid == 0) {
        float S = 0.f, SQ = 0.f;
        #pragma unroll
        for (int i = 0; i < 8; i++) { S += ss[i]; SQ += ssq[i]; }
        float mu  = S * (1.0f / D_);
        float var = SQ * (1.0f / D_) - mu * mu;
        ss[0]  = mu;
        ssq[0] = rsqrtf(fmaxf(var, 0.0f) + 1e-5f);
    }
    __syncthreads();
    float mu = ss[0], inv = ssq[0];
    float4 wv = *(const float4*)(w  + tid * 4);
    float4 bv = *(const float4*)(bb + tid * 4);
    float4 o;
    o.x = (v.x - mu) * inv * wv.x + bv.x;
    o.y = (v.y - mu) * inv * wv.y + bv.y;
    o.z = (v.z - mu) * inv * wv.z + bv.z;
    o.w = (v.w - mu) * inv * wv.w + bv.w;
    *(float4*)(y + (size_t)row * D_ + tid * 4) = o;
}

// ---------------- SGEMM (NT): C[M,N] = A[M,K] @ W[N,K]^T + bias (+ R) ----------------
// 128x128 tile, BK=8, 256 threads, 8x8 microtile, double-buffered smem.
__global__ void __launch_bounds__(256) sgemm_nt_kernel(
    const float* __restrict__ A, const float* __restrict__ W,
    const float* __restrict__ bias, const float* __restrict__ R,
    float* __restrict__ C, int M, int N, int K)
{
    __shared__ float As[2][8][128];
    __shared__ float Ws[2][8][128];
    const int tid = threadIdx.x;
    const int tx = tid & 15, ty = tid >> 4;
    const int m0 = blockIdx.y * 128, n0 = blockIdx.x * 128;

    const int lrow = tid >> 1;
    const int lk   = (tid & 1) * 4;
    const float* Ag = A + (size_t)(m0 + lrow) * K + lk;
    const float* Wg = W + (size_t)(n0 + lrow) * K + lk;

    float acc[8][8];
    #pragma unroll
    for (int i = 0; i < 8; i++)
        #pragma unroll
        for (int j = 0; j < 8; j++) acc[i][j] = 0.0f;

    float4 pa = *(const float4*)Ag;
    float4 pw = *(const float4*)Wg;
    As[0][lk + 0][lrow] = pa.x; As[0][lk + 1][lrow] = pa.y;
    As[0][lk + 2][lrow] = pa.z; As[0][lk + 3][lrow] = pa.w;
    Ws[0][lk + 0][lrow] = pw.x; Ws[0][lk + 1][lrow] = pw.y;
    Ws[0][lk + 2][lrow] = pw.z; Ws[0][lk + 3][lrow] = pw.w;
    __syncthreads();

    const int nk = K >> 3;
    for (int kt = 0; kt < nk; kt++) {
        int cur = kt & 1;
        if (kt + 1 < nk) {
            pa = *(const float4*)(Ag + (kt + 1) * 8);
            pw = *(const float4*)(Wg + (kt + 1) * 8);
        }
        #pragma unroll
        for (int kk = 0; kk < 8; kk++) {
            float4 a0 = *(const float4*)&As[cur][kk][ty * 4];
            float4 a1 = *(const float4*)&As[cur][kk][64 + ty * 4];
            float4 b0 = *(const float4*)&Ws[cur][kk][tx * 4];
            float4 b1 = *(const float4*)&Ws[cur][kk][64 + tx * 4];
            float av[8] = {a0.x, a0.y, a0.z, a0.w, a1.x, a1.y, a1.z, a1.w};
            float bv[8] = {b0.x, b0.y, b0.z, b0.w, b1.x, b1.y, b1.z, b1.w};
            #pragma unroll
            for (int i = 0; i < 8; i++)
                #pragma unroll
                for (int j = 0; j < 8; j++)
                    acc[i][j] += av[i] * bv[j];
        }
        if (kt + 1 < nk) {
            int nxt = cur ^ 1;
            As[nxt][lk + 0][lrow] = pa.x; As[nxt][lk + 1][lrow] = pa.y;
            As[nxt][lk + 2][lrow] = pa.z; As[nxt][lk + 3][lrow] = pa.w;
            Ws[nxt][lk + 0][lrow] = pw.x; Ws[nxt][lk + 1][lrow] = pw.y;
            Ws[nxt][lk + 2][lrow] = pw.z; Ws[nxt][lk + 3][lrow] = pw.w;
            __syncthreads();
        }
    }

    #pragma unroll
    for (int i = 0; i < 8; i++) {
        int m = m0 + ((i < 4) ? (ty * 4 + i) : (64 + ty * 4 + (i - 4)));
        #pragma unroll
        for (int jj = 0; jj < 2; jj++) {
            int n = n0 + jj * 64 + tx * 4;
            float4 o;
            o.x = acc[i][jj * 4 + 0] + bias[n + 0];
            o.y = acc[i][jj * 4 + 1] + bias[n + 1];
            o.z = acc[i][jj * 4 + 2] + bias[n + 2];
            o.w = acc[i][jj * 4 + 3] + bias[n + 3];
            if (R) {
                const float4 rv = *(const float4*)(R + (size_t)m * N + n);
                o.x += rv.x; o.y += rv.y; o.z += rv.z; o.w += rv.w;
            }
            *(float4*)(C + (size_t)m * N + n) = o;
        }
    }
}

// ---------------- flash attention ----------------
// Block = (b, h, 64 q-rows), 256 threads. S tile 64x64 in regs (4x4/thread),
// rows = ty*4+r, cols = tx + 16*c (strided). Online softmax; row reductions
// via shfl_xor over the 4 low lane bits (= tx).
#define PAD 68
__global__ void __launch_bounds__(256) flash_attn_kernel(
    const float* __restrict__ qh, const float* __restrict__ kvp,
    float* __restrict__ out)
{
    extern __shared__ float sm[];
    float* Qs = sm;
    float* Ks = sm + 64 * PAD;
    float* Vs = sm + 2 * 64 * PAD;
    float* Ps = sm + 3 * 64 * PAD;

    const int b = blockIdx.z, h = blockIdx.y, qt = blockIdx.x;
    const int tid = threadIdx.x, tx = tid & 15, ty = tid >> 4;

    // load Q tile [64][64]
    #pragma unroll
    for (int rep = 0; rep < 4; rep++) {
        int lin = rep * 256 + tid;
        int i   = lin >> 4;
        int d4  = (lin & 15) << 2;
        const float* src = qh + ((size_t)(b * LQ_ + qt * 64 + i)) * D_ + h * HD_ + d4;
        *(float4*)&Qs[i * PAD + d4] = *(const float4*)src;
    }

    const int len   = g_len[b];
    const int ntile = (len + 63) >> 6;

    float m_r[4], l_r[4], O[4][4];
    #pragma unroll
    for (int r = 0; r < 4; r++) {
        m_r[r] = -1e30f; l_r[r] = 0.0f;
        #pragma unroll
        for (int c = 0; c < 4; c++) O[r][c] = 0.0f;
    }

    for (int kt = 0; kt < ntile; kt++) {
        __syncthreads();
        // load K & V tiles
        #pragma unroll
        for (int rep = 0; rep < 4; rep++) {
            int lin = rep * 256 + tid;
            int j   = lin >> 4;
            int d4  = (lin & 15) << 2;
            size_t base = ((size_t)(b * LKV_ + kt * 64 + j)) * (2 * D_) + h * HD_ + d4;
            *(float4*)&Ks[j * PAD + d4] = *(const float4*)(kvp + base);
            *(float4*)&Vs[j * PAD + d4] = *(const float4*)(kvp + base + D_);
        }
        __syncthreads();

        // S = Q @ K^T (4x4 per thread)
        float S[4][4] = {{0.f,0.f,0.f,0.f},{0.f,0.f,0.f,0.f},
                         {0.f,0.f,0.f,0.f},{0.f,0.f,0.f,0.f}};
        #pragma unroll 4
        for (int d4 = 0; d4 < 64; d4 += 4) {
            float4 qv[4], kf[4];
            #pragma unroll
            for (int r = 0; r < 4; r++) qv[r] = *(const float4*)&Qs[(ty * 4 + r) * PAD + d4];
            #pragma unroll
            for (int c = 0; c < 4; c++) kf[c] = *(const float4*)&Ks[(tx + 16 * c) * PAD + d4];
            #pragma unroll
            for (int r = 0; r < 4; r++)
                #pragma unroll
                for (int c = 0; c < 4; c++)
                    S[r][c] += qv[r].x * kf[c].x + qv[r].y * kf[c].y +
                               qv[r].z * kf[c].z + qv[r].w * kf[c].w;
        }

        const int rem = len - kt * 64;
        #pragma unroll
        for (int r = 0; r < 4; r++)
            #pragma unroll
            for (int c = 0; c < 4; c++) {
                float s = S[r][c] * 0.125f;   // 1/sqrt(HD=64)
                if (tx + 16 * c >= rem) s = -1e9f;
                S[r][c] = s;
            }

        // online softmax update
        #pragma unroll
        for (int r = 0; r < 4; r++) {
            float tm = fmaxf(fmaxf(S[r][0], S[r][1]), fmaxf(S[r][2], S[r][3]));
            #pragma unroll
            for (int o = 1; o < 16; o <<= 1)
                tm = fmaxf(tm, __shfl_xor_sync(0xffffffffu, tm, o));
            float mn = fmaxf(m_r[r], tm);
            float al = __expf(m_r[r] - mn);
            float rs = 0.0f;
            #pragma unroll
            for (int c = 0; c < 4; c++) {
                float p = __expf(S[r][c] - mn);
                S[r][c] = p;
                rs += p;
            }
            #pragma unroll
            for (int o = 1; o < 16; o <<= 1)
                rs += __shfl_xor_sync(0xffffffffu, rs, o);
            l_r[r] = l_r[r] * al + rs;
            m_r[r] = mn;
            #pragma unroll
            for (int c = 0; c < 4; c++) O[r][c] *= al;
        }

        // P -> shared (conflict-free: bank = 16*ty + 4*r + tx + 16*c distinct per warp)
        #pragma unroll
        for (int r = 0; r < 4; r++)
            #pragma unroll
            for (int c = 0; c < 4; c++)
                Ps[(ty * 4 + r) * PAD + tx + 16 * c] = S[r][c];
        __syncthreads();

        // O += P @ V
        #pragma unroll 2
        for (int j4 = 0; j4 < 16; j4++) {
            float pr[4][4];
            #pragma unroll
            for (int r = 0; r < 4; r++) {
                float4 t = *(const float4*)&Ps[(ty * 4 + r) * PAD + j4 * 4];
                pr[r][0] = t.x; pr[r][1] = t.y; pr[r][2] = t.z; pr[r][3] = t.w;
            }
            #pragma unroll
            for (int jj = 0; jj < 4; jj++) {
                float vv[4];
                #pragma unroll
                for (int c = 0; c < 4; c++)
                    vv[c] = Vs[(j4 * 4 + jj) * PAD + tx + 16 * c];
                #pragma unroll
                for (int r = 0; r < 4; r++)
                    #pragma unroll
                    for (int c = 0; c < 4; c++)
                        O[r][c] += pr[r][jj] * vv[c];
            }
        }
    }

    // write normalized output
    #pragma unroll
    for (int r = 0; r < 4; r++) {
        float inv = 1.0f / l_r[r];
        size_t rowoff = ((size_t)(b * LQ_ + qt * 64 + ty * 4 + r)) * D_ + h * HD_;
        #pragma unroll
        for (int c = 0; c < 4; c++)
            out[rowoff + tx + 16 * c] = O[r][c] * inv;
    }
}

// ---------------- host launcher ----------------
extern "C" void kernel_launch(void* const* d_in, const int* in_sizes, int n_in,
                              void* d_out, int out_size) {
    const float*         q    = (const float*)d_in[0];
    const float*         kv   = (const float*)d_in[1];
    const unsigned char* mask = (const unsigned char*)d_in[2];
    const float*         nqw  = (const float*)d_in[3];
    const float*         nqb  = (const float*)d_in[4];
    const float*         nkw  = (const float*)d_in[5];
    const float*         nkb  = (const float*)d_in[6];
    const float*         Wq   = (const float*)d_in[7];
    const float*         bq   = (const float*)d_in[8];
    const float*         Wkv  = (const float*)d_in[9];
    const float*         bkv  = (const float*)d_in[10];
    const float*         Wo   = (const float*)d_in[11];
    const float*         bo   = (const float*)d_in[12];
    float* out = (float*)d_out;

    float *qn, *kvn, *qh, *kvp, *attn;
    cudaGetSymbolAddress((void**)&qn,   g_qn);
    cudaGetSymbolAddress((void**)&kvn,  g_kvn);
    cudaGetSymbolAddress((void**)&qh,   g_qh);
    cudaGetSymbolAddress((void**)&kvp,  g_kvp);
    cudaGetSymbolAddress((void**)&attn, g_attn);

    const int FA_SMEM = 4 * 64 * PAD * (int)sizeof(float);  // 69632
    cudaFuncSetAttribute(flash_attn_kernel,
                         cudaFuncAttributeMaxDynamicSharedMemorySize, FA_SMEM);

    compute_lengths_kernel<<<1, 256>>>(mask);
    layernorm_kernel<<<B_ * LQ_,  256>>>(q,  nqw, nqb, qn);
    layernorm_kernel<<<B_ * LKV_, 256>>>(kv, nkw, nkb, kvn);

    dim3 gq(D_ / 128, (B_ * LQ_) / 128);
    sgemm_nt_kernel<<<gq, 256>>>(qn, Wq, bq, nullptr, qh, B_ * LQ_, D_, D_);

    dim3 gkv((2 * D_) / 128, (B_ * LKV_) / 128);
    sgemm_nt_kernel<<<gkv, 256>>>(kvn, Wkv, bkv, nullptr, kvp, B_ * LKV_, 2 * D_, D_);

    flash_attn_kernel<<<dim3(LQ_ / 64, H_, B_), 256, FA_SMEM>>>(qh, kvp, attn);

    sgemm_nt_kernel<<<gq, 256>>>(attn, Wo, bo, q, out, B_ * LQ_, D_, D_);
}

// round 3
// speedup vs baseline: 1.0247x; 1.0247x over previous
#include <cuda_runtime.h>
#include <math.h>

// Problem dims
#define B_   4
#define LQ_  1024
#define LKV_ 2048
#define D_   1024
#define H_   16
#define HD_  64

// ---------------- packed f32x2 helpers ----------------
typedef unsigned long long u64;

__device__ __forceinline__ u64 pack2(float lo, float hi) {
    u64 r;
    asm("mov.b64 %0, {%1, %2};" : "=l"(r) : "f"(lo), "f"(hi));
    return r;
}
__device__ __forceinline__ u64 pack_dup(float v) {
    u64 r;
    asm("mov.b64 %0, {%1, %1};" : "=l"(r) : "f"(v));
    return r;
}
__device__ __forceinline__ void unpack2(u64 v, float& lo, float& hi) {
    asm("mov.b64 {%0, %1}, %2;" : "=f"(lo), "=f"(hi) : "l"(v));
}
__device__ __forceinline__ void fma2(u64& d, u64 a, u64 b) {
    asm("fma.rn.f32x2 %0, %1, %2, %0;" : "+l"(d) : "l"(a), "l"(b));
}
__device__ __forceinline__ void mul2(u64& d, u64 a, u64 b) {
    asm("mul.rn.f32x2 %0, %1, %2;" : "=l"(d) : "l"(a), "l"(b));
}

// ---------------- scratch (no allocs allowed) ----------------
__device__ float g_qn  [B_ * LQ_  * D_];        // 16 MB
__device__ float g_kvn [B_ * LKV_ * D_];        // 32 MB
__device__ float g_qh  [B_ * LQ_  * D_];        // 16 MB
__device__ float g_kvp [B_ * LKV_ * 2 * D_];    // 64 MB
__device__ float g_attn[B_ * LQ_  * D_];        // 16 MB
__device__ int   g_len [B_];

// ---------------- mask dtype sniffing + per-batch lengths ----------------
__global__ void compute_lengths_kernel(const unsigned char* __restrict__ mask) {
    __shared__ int det[4];
    __shared__ int cnt[4];
    __shared__ int mode;  // 0 = 1-byte bool, 1 = int32, 2 = float32
    int tid = threadIdx.x;
    if (tid < 4) { det[tid] = 0; cnt[tid] = 0; }
    __syncthreads();
    for (int i = tid; i < B_ * LKV_; i += blockDim.x) {
        if (mask[i]) atomicOr(&det[i & 3], 1);
    }
    __syncthreads();
    if (tid == 0) {
        if (det[1])                   mode = 0;
        else if (det[2] || det[3])    mode = det[0] ? 0 : 2;
        else if (det[0])              mode = 1;
        else                          mode = 0;
    }
    __syncthreads();
    int md = mode;
    for (int b = 0; b < B_; b++) {
        int local = 0;
        for (int k = tid; k < LKV_; k += blockDim.x) {
            int idx = b * LKV_ + k;
            bool t;
            if      (md == 0) t = mask[idx] != 0;
            else if (md == 1) t = ((const int*)  mask)[idx] != 0;
            else              t = ((const float*)mask)[idx] != 0.0f;
            if (!t) local++;
        }
        atomicAdd(&cnt[b], local);
    }
    __syncthreads();
    if (tid < B_) g_len[tid] = cnt[tid];
}

// ---------------- layernorm: one block per row of D_=1024 ----------------
__global__ void __launch_bounds__(256) layernorm_kernel(
    const float* __restrict__ x, const float* __restrict__ w,
    const float* __restrict__ bb, float* __restrict__ y)
{
    int row = blockIdx.x;
    int tid = threadIdx.x;
    const float* xr = x + (size_t)row * D_;
    float4 v = *(const float4*)(xr + tid * 4);
    float s  = v.x + v.y + v.z + v.w;
    float sq = v.x * v.x + v.y * v.y + v.z * v.z + v.w * v.w;
    #pragma unroll
    for (int o = 16; o; o >>= 1) {
        s  += __shfl_xor_sync(0xffffffffu, s,  o);
        sq += __shfl_xor_sync(0xffffffffu, sq, o);
    }
    __shared__ float ss[8], ssq[8];
    int wid = tid >> 5, ln = tid & 31;
    if (ln == 0) { ss[wid] = s; ssq[wid] = sq; }
    __syncthreads();
    if (tid == 0) {
        float S = 0.f, SQ = 0.f;
        #pragma unroll
        for (int i = 0; i < 8; i++) { S += ss[i]; SQ += ssq[i]; }
        float mu  = S * (1.0f / D_);
        float var = SQ * (1.0f / D_) - mu * mu;
        ss[0]  = mu;
        ssq[0] = rsqrtf(fmaxf(var, 0.0f) + 1e-5f);
    }
    __syncthreads();
    float mu = ss[0], inv = ssq[0];
    float4 wv = *(const float4*)(w  + tid * 4);
    float4 bv = *(const float4*)(bb + tid * 4);
    float4 o;
    o.x = (v.x - mu) * inv * wv.x + bv.x;
    o.y = (v.y - mu) * inv * wv.y + bv.y;
    o.z = (v.z - mu) * inv * wv.z + bv.z;
    o.w = (v.w - mu) * inv * wv.w + bv.w;
    *(float4*)(y + (size_t)row * D_ + tid * 4) = o;
}

// ---------------- SGEMM (NT) with packed f32x2 FMA ----------------
// C[M,N] = A[M,K] @ W[N,K]^T + bias (+ R). 128x128 tile, BK=8, 256 threads,
// 8x8 microtile held as 8x4 packed f32x2 accumulators.
__global__ void __launch_bounds__(256) sgemm_nt_kernel(
    const float* __restrict__ A, const float* __restrict__ W,
    const float* __restrict__ bias, const float* __restrict__ R,
    float* __restrict__ C, int M, int N, int K)
{
    __shared__ float As[2][8][128];
    __shared__ float Ws[2][8][128];
    const int tid = threadIdx.x;
    const int tx = tid & 15, ty = tid >> 4;
    const int m0 = blockIdx.y * 128, n0 = blockIdx.x * 128;

    const int lrow = tid >> 1;
    const int lk   = (tid & 1) * 4;
    const float* Ag = A + (size_t)(m0 + lrow) * K + lk;
    const float* Wg = W + (size_t)(n0 + lrow) * K + lk;

    u64 accp[8][4];
    #pragma unroll
    for (int i = 0; i < 8; i++)
        #pragma unroll
        for (int j = 0; j < 4; j++) accp[i][j] = 0ULL;

    float4 pa = *(const float4*)Ag;
    float4 pw = *(const float4*)Wg;
    As[0][lk + 0][lrow] = pa.x; As[0][lk + 1][lrow] = pa.y;
    As[0][lk + 2][lrow] = pa.z; As[0][lk + 3][lrow] = pa.w;
    Ws[0][lk + 0][lrow] = pw.x; Ws[0][lk + 1][lrow] = pw.y;
    Ws[0][lk + 2][lrow] = pw.z; Ws[0][lk + 3][lrow] = pw.w;
    __syncthreads();

    const int nk = K >> 3;
    for (int kt = 0; kt < nk; kt++) {
        int cur = kt & 1;
        if (kt + 1 < nk) {
            pa = *(const float4*)(Ag + (kt + 1) * 8);
            pw = *(const float4*)(Wg + (kt + 1) * 8);
        }
        #pragma unroll
        for (int kk = 0; kk < 8; kk++) {
            float4 a0 = *(const float4*)&As[cur][kk][ty * 4];
            float4 a1 = *(const float4*)&As[cur][kk][64 + ty * 4];
            ulonglong2 w0 = *(const ulonglong2*)&Ws[cur][kk][tx * 4];
            ulonglong2 w1 = *(const ulonglong2*)&Ws[cur][kk][64 + tx * 4];
            u64 bp[4] = {w0.x, w0.y, w1.x, w1.y};
            float av[8] = {a0.x, a0.y, a0.z, a0.w, a1.x, a1.y, a1.z, a1.w};
            u64 ap[8];
            #pragma unroll
            for (int i = 0; i < 8; i++) ap[i] = pack_dup(av[i]);
            #pragma unroll
            for (int i = 0; i < 8; i++)
                #pragma unroll
                for (int j = 0; j < 4; j++)
                    fma2(accp[i][j], ap[i], bp[j]);
        }
        if (kt + 1 < nk) {
            int nxt = cur ^ 1;
            As[nxt][lk + 0][lrow] = pa.x; As[nxt][lk + 1][lrow] = pa.y;
            As[nxt][lk + 2][lrow] = pa.z; As[nxt][lk + 3][lrow] = pa.w;
            Ws[nxt][lk + 0][lrow] = pw.x; Ws[nxt][lk + 1][lrow] = pw.y;
            Ws[nxt][lk + 2][lrow] = pw.z; Ws[nxt][lk + 3][lrow] = pw.w;
            __syncthreads();
        }
    }

    #pragma unroll
    for (int i = 0; i < 8; i++) {
        int m = m0 + ((i < 4) ? (ty * 4 + i) : (64 + ty * 4 + (i - 4)));
        #pragma unroll
        for (int jj = 0; jj < 2; jj++) {
            int n = n0 + jj * 64 + tx * 4;
            float c0, c1, c2, c3;
            unpack2(accp[i][jj * 2 + 0], c0, c1);
            unpack2(accp[i][jj * 2 + 1], c2, c3);
            float4 o;
            o.x = c0 + bias[n + 0];
            o.y = c1 + bias[n + 1];
            o.z = c2 + bias[n + 2];
            o.w = c3 + bias[n + 3];
            if (R) {
                const float4 rv = *(const float4*)(R + (size_t)m * N + n);
                o.x += rv.x; o.y += rv.y; o.z += rv.z; o.w += rv.w;
            }
            *(float4*)(C + (size_t)m * N + n) = o;
        }
    }
}

// ---------------- flash attention (f32x2 in both matmuls) ----------------
// Block = (b, h, 64 q-rows), 256 threads.
// S tile: rows = ty*4+r, S-cols (kv dim) = tx + 16*c          (as before)
// O tile: rows = ty*4+r, O-cols (head dim) = 2*tx + 32*p + e  (paired, e=0/1)
#define PAD 68
__global__ void __launch_bounds__(256) flash_attn_kernel(
    const float* __restrict__ qh, const float* __restrict__ kvp,
    float* __restrict__ out)
{
    extern __shared__ float sm[];
    float* Qs = sm;
    float* Ks = sm + 64 * PAD;
    float* Vs = sm + 2 * 64 * PAD;
    float* Ps = sm + 3 * 64 * PAD;

    const int b = blockIdx.z, h = blockIdx.y, qt = blockIdx.x;
    const int tid = threadIdx.x, tx = tid & 15, ty = tid >> 4;

    // load Q tile [64][64]
    #pragma unroll
    for (int rep = 0; rep < 4; rep++) {
        int lin = rep * 256 + tid;
        int i   = lin >> 4;
        int d4  = (lin & 15) << 2;
        const float* src = qh + ((size_t)(b * LQ_ + qt * 64 + i)) * D_ + h * HD_ + d4;
        *(float4*)&Qs[i * PAD + d4] = *(const float4*)src;
    }

    const int len   = g_len[b];
    const int ntile = (len + 63) >> 6;

    float m_r[4], l_r[4];
    u64 O2[4][2];
    #pragma unroll
    for (int r = 0; r < 4; r++) {
        m_r[r] = -1e30f; l_r[r] = 0.0f;
        O2[r][0] = 0ULL; O2[r][1] = 0ULL;
    }

    for (int kt = 0; kt < ntile; kt++) {
        __syncthreads();
        // load K & V tiles
        #pragma unroll
        for (int rep = 0; rep < 4; rep++) {
            int lin = rep * 256 + tid;
            int j   = lin >> 4;
            int d4  = (lin & 15) << 2;
            size_t base = ((size_t)(b * LKV_ + kt * 64 + j)) * (2 * D_) + h * HD_ + d4;
            *(float4*)&Ks[j * PAD + d4] = *(const float4*)(kvp + base);
            *(float4*)&Vs[j * PAD + d4] = *(const float4*)(kvp + base + D_);
        }
        __syncthreads();

        // S = Q @ K^T, paired along the d (reduction) dim
        u64 S2[4][4];
        #pragma unroll
        for (int r = 0; r < 4; r++)
            #pragma unroll
            for (int c = 0; c < 4; c++) S2[r][c] = 0ULL;

        #pragma unroll 4
        for (int d4 = 0; d4 < 64; d4 += 4) {
            ulonglong2 q2[4], k2[4];
            #pragma unroll
            for (int r = 0; r < 4; r++)
                q2[r] = *(const ulonglong2*)&Qs[(ty * 4 + r) * PAD + d4];
            #pragma unroll
            for (int c = 0; c < 4; c++)
                k2[c] = *(const ulonglong2*)&Ks[(tx + 16 * c) * PAD + d4];
            #pragma unroll
            for (int r = 0; r < 4; r++)
                #pragma unroll
                for (int c = 0; c < 4; c++) {
                    fma2(S2[r][c], q2[r].x, k2[c].x);
                    fma2(S2[r][c], q2[r].y, k2[c].y);
                }
        }

        float S[4][4];
        const int rem = len - kt * 64;
        #pragma unroll
        for (int r = 0; r < 4; r++)
            #pragma unroll
            for (int c = 0; c < 4; c++) {
                float lo, hi;
                unpack2(S2[r][c], lo, hi);
                float s = (lo + hi) * 0.125f;   // 1/sqrt(HD=64)
                if (tx + 16 * c >= rem) s = -1e9f;
                S[r][c] = s;
            }

        // online softmax update
        #pragma unroll
        for (int r = 0; r < 4; r++) {
            float tm = fmaxf(fmaxf(S[r][0], S[r][1]), fmaxf(S[r][2], S[r][3]));
            #pragma unroll
            for (int o = 1; o < 16; o <<= 1)
                tm = fmaxf(tm, __shfl_xor_sync(0xffffffffu, tm, o));
            float mn = fmaxf(m_r[r], tm);
            float al = __expf(m_r[r] - mn);
            float rs = 0.0f;
            #pragma unroll
            for (int c = 0; c < 4; c++) {
                float p = __expf(S[r][c] - mn);
                S[r][c] = p;
                rs += p;
            }
            #pragma unroll
            for (int o = 1; o < 16; o <<= 1)
                rs += __shfl_xor_sync(0xffffffffu, rs, o);
            l_r[r] = l_r[r] * al + rs;
            m_r[r] = mn;
            u64 alp = pack_dup(al);
            mul2(O2[r][0], O2[r][0], alp);
            mul2(O2[r][1], O2[r][1], alp);
        }

        // P -> shared
        #pragma unroll
        for (int r = 0; r < 4; r++)
            #pragma unroll
            for (int c = 0; c < 4; c++)
                Ps[(ty * 4 + r) * PAD + tx + 16 * c] = S[r][c];
        __syncthreads();

        // O += P @ V   (O columns = head dim, paired 2*tx + 32*p)
        #pragma unroll 2
        for (int j4 = 0; j4 < 16; j4++) {
            float pr[4][4];
            #pragma unroll
            for (int r = 0; r < 4; r++) {
                float4 t = *(const float4*)&Ps[(ty * 4 + r) * PAD + j4 * 4];
                pr[r][0] = t.x; pr[r][1] = t.y; pr[r][2] = t.z; pr[r][3] = t.w;
            }
            #pragma unroll
            for (int jj = 0; jj < 4; jj++) {
                const float* vrow = &Vs[(j4 * 4 + jj) * PAD + 2 * tx];
                u64 vv0 = *(const u64*)(vrow);
                u64 vv1 = *(const u64*)(vrow + 32);
                #pragma unroll
                for (int r = 0; r < 4; r++) {
                    u64 pp = pack_dup(pr[r][jj]);
                    fma2(O2[r][0], pp, vv0);
                    fma2(O2[r][1], pp, vv1);
                }
            }
        }
    }

    // write normalized output (float2 stores on paired columns)
    #pragma unroll
    for (int r = 0; r < 4; r++) {
        float inv = 1.0f / l_r[r];
        size_t rowoff = ((size_t)(b * LQ_ + qt * 64 + ty * 4 + r)) * D_ + h * HD_;
        #pragma unroll
        for (int p = 0; p < 2; p++) {
            float lo, hi;
            unpack2(O2[r][p], lo, hi);
            float2 o2 = make_float2(lo * inv, hi * inv);
            *(float2*)(out + rowoff + 2 * tx + 32 * p) = o2;
        }
    }
}

// ---------------- host launcher ----------------
extern "C" void kernel_launch(void* const* d_in, const int* in_sizes, int n_in,
                              void* d_out, int out_size) {
    const float*         q    = (const float*)d_in[0];
    const float*         kv   = (const float*)d_in[1];
    const unsigned char* mask = (const unsigned char*)d_in[2];
    const float*         nqw  = (const float*)d_in[3];
    const float*         nqb  = (const float*)d_in[4];
    const float*         nkw  = (const float*)d_in[5];
    const float*         nkb  = (const float*)d_in[6];
    const float*         Wq   = (const float*)d_in[7];
    const float*         bq   = (const float*)d_in[8];
    const float*         Wkv  = (const float*)d_in[9];
    const float*         bkv  = (const float*)d_in[10];
    const float*         Wo   = (const float*)d_in[11];
    const float*         bo   = (const float*)d_in[12];
    float* out = (float*)d_out;

    float *qn, *kvn, *qh, *kvp, *attn;
    cudaGetSymbolAddress((void**)&qn,   g_qn);
    cudaGetSymbolAddress((void**)&kvn,  g_kvn);
    cudaGetSymbolAddress((void**)&qh,   g_qh);
    cudaGetSymbolAddress((void**)&kvp,  g_kvp);
    cudaGetSymbolAddress((void**)&attn, g_attn);

    const int FA_SMEM = 4 * 64 * PAD * (int)sizeof(float);  // 69632
    cudaFuncSetAttribute(flash_attn_kernel,
                         cudaFuncAttributeMaxDynamicSharedMemorySize, FA_SMEM);

    compute_lengths_kernel<<<1, 256>>>(mask);
    layernorm_kernel<<<B_ * LQ_,  256>>>(q,  nqw, nqb, qn);
    layernorm_kernel<<<B_ * LKV_, 256>>>(kv, nkw, nkb, kvn);

    dim3 gq(D_ / 128, (B_ * LQ_) / 128);
    sgemm_nt_kernel<<<gq, 256>>>(qn, Wq, bq, nullptr, qh, B_ * LQ_, D_, D_);

    dim3 gkv((2 * D_) / 128, (B_ * LKV_) / 128);
    sgemm_nt_kernel<<<gkv, 256>>>(kvn, Wkv, bkv, nullptr, kvp, B_ * LKV_, 2 * D_, D_);

    flash_attn_kernel<<<dim3(LQ_ / 64, H_, B_), 256, FA_SMEM>>>(qh, kvp, attn);

    sgemm_nt_kernel<<<gq, 256>>>(attn, Wo, bo, q, out, B_ * LQ_, D_, D_);
}

// round 7
// speedup vs baseline: 1.4098x; 1.3759x over previous
#include <cuda_runtime.h>
#include <cuda_bf16.h>
#include <math.h>
#include <stdint.h>

// Problem dims
#define B_   4
#define LQ_  1024
#define LKV_ 2048
#define D_   1024
#define H_   16
#define HD_  64
#define K3_  3072   // split-K: [hi, lo, hi] x 1024

// ================= warp-MMA helpers (baseline PTX, sm_80+) =================
__device__ __forceinline__ uint32_t smem_to_u32(const void* p) {
    uint32_t a;
    asm("{ .reg .u64 t; cvta.to.shared.u64 t, %1; cvt.u32.u64 %0, t; }"
        : "=r"(a) : "l"(p));
    return a;
}
__device__ __forceinline__ void ldmatrix_x4(uint32_t* r, uint32_t addr) {
    asm volatile("ldmatrix.sync.aligned.m8n8.x4.shared.b16 {%0,%1,%2,%3}, [%4];"
        : "=r"(r[0]), "=r"(r[1]), "=r"(r[2]), "=r"(r[3]) : "r"(addr));
}
__device__ __forceinline__ void mma_16816(float* d, const uint32_t* a,
                                          uint32_t b0, uint32_t b1) {
    asm volatile("mma.sync.aligned.m16n8k16.row.col.f32.bf16.bf16.f32 "
        "{%0,%1,%2,%3}, {%4,%5,%6,%7}, {%8,%9}, {%0,%1,%2,%3};"
        : "+f"(d[0]), "+f"(d[1]), "+f"(d[2]), "+f"(d[3])
        : "r"(a[0]), "r"(a[1]), "r"(a[2]), "r"(a[3]), "r"(b0), "r"(b1));
}

// ================= packed f32x2 helpers (flash attention) =================
typedef unsigned long long u64;
__device__ __forceinline__ u64 pack_dup(float v) {
    u64 r; asm("mov.b64 %0, {%1, %1};" : "=l"(r) : "f"(v)); return r;
}
__device__ __forceinline__ void unpack2(u64 v, float& lo, float& hi) {
    asm("mov.b64 {%0, %1}, %2;" : "=f"(lo), "=f"(hi) : "l"(v));
}
__device__ __forceinline__ void fma2(u64& d, u64 a, u64 b) {
    asm("fma.rn.f32x2 %0, %1, %2, %0;" : "+l"(d) : "l"(a), "l"(b));
}
__device__ __forceinline__ void mul2(u64& d, u64 a, u64 b) {
    asm("mul.rn.f32x2 %0, %1, %2;" : "=l"(d) : "l"(a), "l"(b));
}

// ================= scratch =================
__device__ __nv_bfloat16 g_q3k   [B_ * LQ_  * K3_];   // 24MB
__device__ __nv_bfloat16 g_kv3k  [B_ * LKV_ * K3_];   // 48MB
__device__ __nv_bfloat16 g_at3k  [B_ * LQ_  * K3_];   // 24MB
__device__ __nv_bfloat16 g_wq3k  [D_ * K3_];          // 6MB
__device__ __nv_bfloat16 g_wkv3k [2 * D_ * K3_];      // 12MB
__device__ __nv_bfloat16 g_wo3k  [D_ * K3_];          // 6MB
__device__ float g_qh [B_ * LQ_  * D_];               // 16MB
__device__ float g_kvp[B_ * LKV_ * 2 * D_];           // 64MB
__device__ int   g_len[B_];

// ================= mask lengths (dtype-sniffing) =================
__global__ void compute_lengths_kernel(const unsigned char* __restrict__ mask) {
    __shared__ int det[4];
    __shared__ int cnt[4];
    __shared__ int mode;
    int tid = threadIdx.x;
    if (tid < 4) { det[tid] = 0; cnt[tid] = 0; }
    __syncthreads();
    for (int i = tid; i < B_ * LKV_; i += blockDim.x)
        if (mask[i]) atomicOr(&det[i & 3], 1);
    __syncthreads();
    if (tid == 0) {
        if (det[1])                mode = 0;
        else if (det[2] || det[3]) mode = det[0] ? 0 : 2;
        else if (det[0])           mode = 1;
        else                       mode = 0;
    }
    __syncthreads();
    int md = mode;
    for (int b = 0; b < B_; b++) {
        int local = 0;
        for (int k = tid; k < LKV_; k += blockDim.x) {
            int idx = b * LKV_ + k;
            bool t;
            if      (md == 0) t = mask[idx] != 0;
            else if (md == 1) t = ((const int*)  mask)[idx] != 0;
            else              t = ((const float*)mask)[idx] != 0.0f;
            if (!t) local++;
        }
        atomicAdd(&cnt[b], local);
    }
    __syncthreads();
    if (tid < B_) g_len[tid] = cnt[tid];
}

// ================= layernorm + hi/lo split: A' = [hi, lo, hi] =================
__global__ void __launch_bounds__(256) layernorm_split_kernel(
    const float* __restrict__ x, const float* __restrict__ w,
    const float* __restrict__ bb, __nv_bfloat16* __restrict__ y)
{
    int row = blockIdx.x;
    int tid = threadIdx.x;
    const float* xr = x + (size_t)row * D_;
    float4 v = *(const float4*)(xr + tid * 4);
    float s  = v.x + v.y + v.z + v.w;
    float sq = v.x * v.x + v.y * v.y + v.z * v.z + v.w * v.w;
    #pragma unroll
    for (int o = 16; o; o >>= 1) {
        s  += __shfl_xor_sync(0xffffffffu, s,  o);
        sq += __shfl_xor_sync(0xffffffffu, sq, o);
    }
    __shared__ float ss[8], ssq[8];
    int wid = tid >> 5, ln = tid & 31;
    if (ln == 0) { ss[wid] = s; ssq[wid] = sq; }
    __syncthreads();
    if (tid == 0) {
        float S = 0.f, SQ = 0.f;
        #pragma unroll
        for (int i = 0; i < 8; i++) { S += ss[i]; SQ += ssq[i]; }
        float mu  = S * (1.0f / D_);
        float var = SQ * (1.0f / D_) - mu * mu;
        ss[0]  = mu;
        ssq[0] = rsqrtf(fmaxf(var, 0.0f) + 1e-5f);
    }
    __syncthreads();
    float mu = ss[0], inv = ssq[0];
    float4 wv = *(const float4*)(w  + tid * 4);
    float4 bv = *(const float4*)(bb + tid * 4);
    float o[4];
    o[0] = (v.x - mu) * inv * wv.x + bv.x;
    o[1] = (v.y - mu) * inv * wv.y + bv.y;
    o[2] = (v.z - mu) * inv * wv.z + bv.z;
    o[3] = (v.w - mu) * inv * wv.w + bv.w;
    __nv_bfloat16 hi[4], lo[4];
    #pragma unroll
    for (int i = 0; i < 4; i++) {
        hi[i] = __float2bfloat16(o[i]);
        lo[i] = __float2bfloat16(o[i] - __bfloat162float(hi[i]));
    }
    __nv_bfloat16* yr = y + (size_t)row * K3_ + tid * 4;
    *(__nv_bfloat162*)(yr + 0)    = __nv_bfloat162(hi[0], hi[1]);
    *(__nv_bfloat162*)(yr + 2)    = __nv_bfloat162(hi[2], hi[3]);
    *(__nv_bfloat162*)(yr + 1024) = __nv_bfloat162(lo[0], lo[1]);
    *(__nv_bfloat162*)(yr + 1026) = __nv_bfloat162(lo[2], lo[3]);
    *(__nv_bfloat162*)(yr + 2048) = __nv_bfloat162(hi[0], hi[1]);
    *(__nv_bfloat162*)(yr + 2050) = __nv_bfloat162(hi[2], hi[3]);
}

// ================= weight split: B' = [Whi, Whi, Wlo] =================
__global__ void __launch_bounds__(256) weight_split_kernel(
    const float* __restrict__ W, __nv_bfloat16* __restrict__ O)
{
    int idx4 = (blockIdx.x * 256 + threadIdx.x) * 4;
    float4 v = *(const float4*)(W + idx4);
    int n = idx4 >> 10;
    int k = idx4 & 1023;
    float vv[4] = {v.x, v.y, v.z, v.w};
    __nv_bfloat16 hi[4], lo[4];
    #pragma unroll
    for (int i = 0; i < 4; i++) {
        hi[i] = __float2bfloat16(vv[i]);
        lo[i] = __float2bfloat16(vv[i] - __bfloat162float(hi[i]));
    }
    __nv_bfloat16* yr = O + (size_t)n * K3_ + k;
    *(__nv_bfloat162*)(yr + 0)    = __nv_bfloat162(hi[0], hi[1]);
    *(__nv_bfloat162*)(yr + 2)    = __nv_bfloat162(hi[2], hi[3]);
    *(__nv_bfloat162*)(yr + 1024) = __nv_bfloat162(hi[0], hi[1]);
    *(__nv_bfloat162*)(yr + 1026) = __nv_bfloat162(hi[2], hi[3]);
    *(__nv_bfloat162*)(yr + 2048) = __nv_bfloat162(lo[0], lo[1]);
    *(__nv_bfloat162*)(yr + 2050) = __nv_bfloat162(lo[2], lo[3]);
}

// ================= bf16 warp-MMA GEMM: C[M,N] = A'[M,3072] @ B'[N,3072]^T =================
// 128x128 CTA tile, 8 warps (4x2 -> 32x64 warp tile), BK=32 (2 k16 steps),
// reg-prefetch double-buffered smem, 80B-padded rows (conflict-free ldmatrix).
#define SSTRIDE 40            // bf16 elements per smem row (80 bytes)
#define STILE   (128 * SSTRIDE)

__global__ void __launch_bounds__(256) gemm_bf16_mma_kernel(
    const __nv_bfloat16* __restrict__ A, const __nv_bfloat16* __restrict__ W,
    const float* __restrict__ bias, const float* __restrict__ R,
    float* __restrict__ C, int M, int N)
{
    __shared__ __nv_bfloat16 sa[2][STILE];
    __shared__ __nv_bfloat16 sb[2][STILE];

    const int tid  = threadIdx.x;
    const int lane = tid & 31;
    const int wid  = tid >> 5;
    const int warp_m = wid & 3;         // 0..3 -> 32-row slices
    const int warp_n = wid >> 2;        // 0..1 -> 64-col slices
    const int m0 = blockIdx.y * 128, n0 = blockIdx.x * 128;

    // loader mapping: 256 threads cover 128 rows x 4 16B-units, twice (rows lr, lr+64)
    const int lr = tid >> 2;            // 0..63
    const int lu = tid & 3;             // 16B unit within 64B row chunk
    const __nv_bfloat16* ag = A + (size_t)(m0 + lr) * K3_ + lu * 8;
    const __nv_bfloat16* bg = W + (size_t)(n0 + lr) * K3_ + lu * 8;

    float acc[2][8][4];
    #pragma unroll
    for (int i = 0; i < 2; i++)
        #pragma unroll
        for (int j = 0; j < 8; j++)
            #pragma unroll
            for (int t = 0; t < 4; t++) acc[i][j][t] = 0.0f;

    const uint32_t sa_u = smem_to_u32(sa);
    const uint32_t sb_u = smem_to_u32(sb);

    // ldmatrix per-lane address components (bytes within tile)
    // A x4 tile: lanes 0-15 rows m0..15 @k0, lanes 16-31 same rows @k0+8
    const uint32_t a_off = (uint32_t)((warp_m * 32 + (lane & 15)) * SSTRIDE * 2
                                      + (lane >> 4) * 16);
    // B x4 tile: lanes 0-7 n0-7@k0, 8-15 n0-7@k8, 16-23 n8-15@k0, 24-31 n8-15@k8
    const uint32_t b_off = (uint32_t)((warp_n * 64 + ((lane >> 4) & 1) * 8 + (lane & 7)) * SSTRIDE * 2
                                      + ((lane >> 3) & 1) * 16);

    uint4 pa0 = *(const uint4*)(ag);
    uint4 pa1 = *(const uint4*)(ag + (size_t)64 * K3_);
    uint4 pb0 = *(const uint4*)(bg);
    uint4 pb1 = *(const uint4*)(bg + (size_t)64 * K3_);
    *(uint4*)&sa[0][lr * SSTRIDE + lu * 8]        = pa0;
    *(uint4*)&sa[0][(lr + 64) * SSTRIDE + lu * 8] = pa1;
    *(uint4*)&sb[0][lr * SSTRIDE + lu * 8]        = pb0;
    *(uint4*)&sb[0][(lr + 64) * SSTRIDE + lu * 8] = pb1;
    __syncthreads();

    const int NK = K3_ / 32;   // 96
    for (int kt = 0; kt < NK; kt++) {
        const int cur = kt & 1;
        if (kt + 1 < NK) {
            const size_t koff = (size_t)(kt + 1) * 32;
            pa0 = *(const uint4*)(ag + koff);
            pa1 = *(const uint4*)(ag + (size_t)64 * K3_ + koff);
            pb0 = *(const uint4*)(bg + koff);
            pb1 = *(const uint4*)(bg + (size_t)64 * K3_ + koff);
        }
        const uint32_t sa_cur = sa_u + (uint32_t)(cur * STILE * 2);
        const uint32_t sb_cur = sb_u + (uint32_t)(cur * STILE * 2);
        #pragma unroll
        for (int ks = 0; ks < 2; ks++) {
            uint32_t a_frag[2][4];
            #pragma unroll
            for (int im = 0; im < 2; im++)
                ldmatrix_x4(a_frag[im], sa_cur + a_off
                            + (uint32_t)(im * 16 * SSTRIDE * 2 + ks * 32));
            uint32_t b_frag[4][4];
            #pragma unroll
            for (int iu = 0; iu < 4; iu++)
                ldmatrix_x4(b_frag[iu], sb_cur + b_off
                            + (uint32_t)(iu * 16 * SSTRIDE * 2 + ks * 32));
            #pragma unroll
            for (int im = 0; im < 2; im++)
                #pragma unroll
                for (int iu = 0; iu < 4; iu++) {
                    mma_16816(acc[im][iu * 2 + 0], a_frag[im], b_frag[iu][0], b_frag[iu][1]);
                    mma_16816(acc[im][iu * 2 + 1], a_frag[im], b_frag[iu][2], b_frag[iu][3]);
                }
        }
        if (kt + 1 < NK) {
            const int nxt = cur ^ 1;
            *(uint4*)&sa[nxt][lr * SSTRIDE + lu * 8]        = pa0;
            *(uint4*)&sa[nxt][(lr + 64) * SSTRIDE + lu * 8] = pa1;
            *(uint4*)&sb[nxt][lr * SSTRIDE + lu * 8]        = pb0;
            *(uint4*)&sb[nxt][(lr + 64) * SSTRIDE + lu * 8] = pb1;
            __syncthreads();
        }
    }

    // epilogue: acc[im][in][c0..c3] -> rows (g, g+8), cols (gc, gc+1)
    const int gr = lane >> 2;
    const int gc = (lane & 3) * 2;
    #pragma unroll
    for (int im = 0; im < 2; im++) {
        const int mrow = m0 + warp_m * 32 + im * 16 + gr;
        #pragma unroll
        for (int in = 0; in < 8; in++) {
            const int n = n0 + warp_n * 64 + in * 8 + gc;
            float b0 = bias[n], b1 = bias[n + 1];
            float2 v0 = make_float2(acc[im][in][0] + b0, acc[im][in][1] + b1);
            float2 v1 = make_float2(acc[im][in][2] + b0, acc[im][in][3] + b1);
            if (R) {
                float2 r0 = *(const float2*)(R + (size_t)mrow * N + n);
                float2 r1 = *(const float2*)(R + (size_t)(mrow + 8) * N + n);
                v0.x += r0.x; v0.y += r0.y;
                v1.x += r1.x; v1.y += r1.y;
            }
            *(float2*)(C + (size_t)mrow * N + n)       = v0;
            *(float2*)(C + (size_t)(mrow + 8) * N + n) = v1;
        }
    }
}

// ================= flash attention (scalar f32x2) =================
// Writes output pre-split as A' = [hi, lo, hi] rows of length 3072 for O-proj.
#define PAD 68
__global__ void __launch_bounds__(256) flash_attn_kernel(
    const float* __restrict__ qh, const float* __restrict__ kvp,
    __nv_bfloat16* __restrict__ out3k)
{
    extern __shared__ float sm[];
    float* Qs = sm;
    float* Ks = sm + 64 * PAD;
    float* Vs = sm + 2 * 64 * PAD;
    float* Ps = sm + 3 * 64 * PAD;

    const int b = blockIdx.z, h = blockIdx.y, qt = blockIdx.x;
    const int tid = threadIdx.x, tx = tid & 15, ty = tid >> 4;

    #pragma unroll
    for (int rep = 0; rep < 4; rep++) {
        int lin = rep * 256 + tid;
        int i   = lin >> 4;
        int d4  = (lin & 15) << 2;
        const float* src = qh + ((size_t)(b * LQ_ + qt * 64 + i)) * D_ + h * HD_ + d4;
        *(float4*)&Qs[i * PAD + d4] = *(const float4*)src;
    }

    const int len   = g_len[b];
    const int ntile = (len + 63) >> 6;

    float m_r[4], l_r[4];
    u64 O2[4][2];
    #pragma unroll
    for (int r = 0; r < 4; r++) {
        m_r[r] = -1e30f; l_r[r] = 0.0f;
        O2[r][0] = 0ULL; O2[r][1] = 0ULL;
    }

    for (int kt = 0; kt < ntile; kt++) {
        __syncthreads();
        #pragma unroll
        for (int rep = 0; rep < 4; rep++) {
            int lin = rep * 256 + tid;
            int j   = lin >> 4;
            int d4  = (lin & 15) << 2;
            size_t base = ((size_t)(b * LKV_ + kt * 64 + j)) * (2 * D_) + h * HD_ + d4;
            *(float4*)&Ks[j * PAD + d4] = *(const float4*)(kvp + base);
            *(float4*)&Vs[j * PAD + d4] = *(const float4*)(kvp + base + D_);
        }
        __syncthreads();

        u64 S2[4][4];
        #pragma unroll
        for (int r = 0; r < 4; r++)
            #pragma unroll
            for (int c = 0; c < 4; c++) S2[r][c] = 0ULL;

        #pragma unroll 4
        for (int d4 = 0; d4 < 64; d4 += 4) {
            ulonglong2 q2[4], k2[4];
            #pragma unroll
            for (int r = 0; r < 4; r++)
                q2[r] = *(const ulonglong2*)&Qs[(ty * 4 + r) * PAD + d4];
            #pragma unroll
            for (int c = 0; c < 4; c++)
                k2[c] = *(const ulonglong2*)&Ks[(tx + 16 * c) * PAD + d4];
            #pragma unroll
            for (int r = 0; r < 4; r++)
                #pragma unroll
                for (int c = 0; c < 4; c++) {
                    fma2(S2[r][c], q2[r].x, k2[c].x);
                    fma2(S2[r][c], q2[r].y, k2[c].y);
                }
        }

        float S[4][4];
        const int rem = len - kt * 64;
        #pragma unroll
        for (int r = 0; r < 4; r++)
            #pragma unroll
            for (int c = 0; c < 4; c++) {
                float lo, hi;
                unpack2(S2[r][c], lo, hi);
                float s = (lo + hi) * 0.125f;
                if (tx + 16 * c >= rem) s = -1e9f;
                S[r][c] = s;
            }

        #pragma unroll
        for (int r = 0; r < 4; r++) {
            float tm = fmaxf(fmaxf(S[r][0], S[r][1]), fmaxf(S[r][2], S[r][3]));
            #pragma unroll
            for (int o = 1; o < 16; o <<= 1)
                tm = fmaxf(tm, __shfl_xor_sync(0xffffffffu, tm, o));
            float mn = fmaxf(m_r[r], tm);
            float al = __expf(m_r[r] - mn);
            float rs = 0.0f;
            #pragma unroll
            for (int c = 0; c < 4; c++) {
                float p = __expf(S[r][c] - mn);
                S[r][c] = p;
                rs += p;
            }
            #pragma unroll
            for (int o = 1; o < 16; o <<= 1)
                rs += __shfl_xor_sync(0xffffffffu, rs, o);
            l_r[r] = l_r[r] * al + rs;
            m_r[r] = mn;
            u64 alp = pack_dup(al);
            mul2(O2[r][0], O2[r][0], alp);
            mul2(O2[r][1], O2[r][1], alp);
        }

        #pragma unroll
        for (int r = 0; r < 4; r++)
            #pragma unroll
            for (int c = 0; c < 4; c++)
                Ps[(ty * 4 + r) * PAD + tx + 16 * c] = S[r][c];
        __syncthreads();

        #pragma unroll 2
        for (int j4 = 0; j4 < 16; j4++) {
            float pr[4][4];
            #pragma unroll
            for (int r = 0; r < 4; r++) {
                float4 t = *(const float4*)&Ps[(ty * 4 + r) * PAD + j4 * 4];
                pr[r][0] = t.x; pr[r][1] = t.y; pr[r][2] = t.z; pr[r][3] = t.w;
            }
            #pragma unroll
            for (int jj = 0; jj < 4; jj++) {
                const float* vrow = &Vs[(j4 * 4 + jj) * PAD + 2 * tx];
                u64 vv0 = *(const u64*)(vrow);
                u64 vv1 = *(const u64*)(vrow + 32);
                #pragma unroll
                for (int r = 0; r < 4; r++) {
                    u64 pp = pack_dup(pr[r][jj]);
                    fma2(O2[r][0], pp, vv0);
                    fma2(O2[r][1], pp, vv1);
                }
            }
        }
    }

    // write normalized output, pre-split to [hi, lo, hi] bf16 rows of length 3072
    #pragma unroll
    for (int r = 0; r < 4; r++) {
        float inv = 1.0f / l_r[r];
        size_t rowoff = ((size_t)(b * LQ_ + qt * 64 + ty * 4 + r)) * K3_;
        #pragma unroll
        for (int p = 0; p < 2; p++) {
            float lo, hi;
            unpack2(O2[r][p], lo, hi);
            float v0 = lo * inv, v1 = hi * inv;
            __nv_bfloat16 h0 = __float2bfloat16(v0);
            __nv_bfloat16 h1 = __float2bfloat16(v1);
            __nv_bfloat16 l0 = __float2bfloat16(v0 - __bfloat162float(h0));
            __nv_bfloat16 l1 = __float2bfloat16(v1 - __bfloat162float(h1));
            int col = h * HD_ + 2 * tx + 32 * p;
            __nv_bfloat16* yp = out3k + rowoff + col;
            *(__nv_bfloat162*)(yp)        = __nv_bfloat162(h0, h1);
            *(__nv_bfloat162*)(yp + 1024) = __nv_bfloat162(l0, l1);
            *(__nv_bfloat162*)(yp + 2048) = __nv_bfloat162(h0, h1);
        }
    }
}

// ================= host launcher =================
extern "C" void kernel_launch(void* const* d_in, const int* in_sizes, int n_in,
                              void* d_out, int out_size) {
    const float*         q    = (const float*)d_in[0];
    const float*         kv   = (const float*)d_in[1];
    const unsigned char* mask = (const unsigned char*)d_in[2];
    const float*         nqw  = (const float*)d_in[3];
    const float*         nqb  = (const float*)d_in[4];
    const float*         nkw  = (const float*)d_in[5];
    const float*         nkb  = (const float*)d_in[6];
    const float*         Wq   = (const float*)d_in[7];
    const float*         bq   = (const float*)d_in[8];
    const float*         Wkv  = (const float*)d_in[9];
    const float*         bkv  = (const float*)d_in[10];
    const float*         Wo   = (const float*)d_in[11];
    const float*         bo   = (const float*)d_in[12];
    float* out = (float*)d_out;

    __nv_bfloat16 *q3k, *kv3k, *at3k, *wq3k, *wkv3k, *wo3k;
    float *qh, *kvp;
    cudaGetSymbolAddress((void**)&q3k,   g_q3k);
    cudaGetSymbolAddress((void**)&kv3k,  g_kv3k);
    cudaGetSymbolAddress((void**)&at3k,  g_at3k);
    cudaGetSymbolAddress((void**)&wq3k,  g_wq3k);
    cudaGetSymbolAddress((void**)&wkv3k, g_wkv3k);
    cudaGetSymbolAddress((void**)&wo3k,  g_wo3k);
    cudaGetSymbolAddress((void**)&qh,    g_qh);
    cudaGetSymbolAddress((void**)&kvp,   g_kvp);

    const int FA_SMEM = 4 * 64 * PAD * (int)sizeof(float);  // 69632
    cudaFuncSetAttribute(flash_attn_kernel,
                         cudaFuncAttributeMaxDynamicSharedMemorySize, FA_SMEM);

    compute_lengths_kernel<<<1, 256>>>(mask);
    layernorm_split_kernel<<<B_ * LQ_,  256>>>(q,  nqw, nqb, q3k);
    layernorm_split_kernel<<<B_ * LKV_, 256>>>(kv, nkw, nkb, kv3k);
    weight_split_kernel<<<(D_ * D_) / 1024,     256>>>(Wq,  wq3k);
    weight_split_kernel<<<(2 * D_ * D_) / 1024, 256>>>(Wkv, wkv3k);
    weight_split_kernel<<<(D_ * D_) / 1024,     256>>>(Wo,  wo3k);

    dim3 gq(D_ / 128, (B_ * LQ_) / 128);          // (8, 32)
    gemm_bf16_mma_kernel<<<gq, 256>>>(q3k, wq3k, bq, nullptr, qh, B_ * LQ_, D_);

    dim3 gkv((2 * D_) / 128, (B_ * LKV_) / 128);  // (16, 64)
    gemm_bf16_mma_kernel<<<gkv, 256>>>(kv3k, wkv3k, bkv, nullptr, kvp,
                                       B_ * LKV_, 2 * D_);

    flash_attn_kernel<<<dim3(LQ_ / 64, H_, B_), 256, FA_SMEM>>>(qh, kvp, at3k);

    gemm_bf16_mma_kernel<<<gq, 256>>>(at3k, wo3k, bo, q, out, B_ * LQ_, D_);
}

// round 8
// speedup vs baseline: 1.4142x; 1.0031x over previous
#include <cuda_runtime.h>
#include <cuda_bf16.h>
#include <math.h>
#include <stdint.h>

// Problem dims
#define B_   4
#define LQ_  1024
#define LKV_ 2048
#define D_   1024
#define H_   16
#define HD_  64
#define K3_  3072   // split-K: [hi, lo, hi] x 1024

// ================= warp-MMA helpers (baseline PTX, sm_80+) =================
__device__ __forceinline__ uint32_t smem_to_u32(const void* p) {
    uint32_t a;
    asm("{ .reg .u64 t; cvta.to.shared.u64 t, %1; cvt.u32.u64 %0, t; }"
        : "=r"(a) : "l"(p));
    return a;
}
__device__ __forceinline__ void ldmatrix_x4(uint32_t* r, uint32_t addr) {
    asm volatile("ldmatrix.sync.aligned.m8n8.x4.shared.b16 {%0,%1,%2,%3}, [%4];"
        : "=r"(r[0]), "=r"(r[1]), "=r"(r[2]), "=r"(r[3]) : "r"(addr));
}
__device__ __forceinline__ void ldmatrix_x4_trans(uint32_t* r, uint32_t addr) {
    asm volatile("ldmatrix.sync.aligned.m8n8.x4.trans.shared.b16 {%0,%1,%2,%3}, [%4];"
        : "=r"(r[0]), "=r"(r[1]), "=r"(r[2]), "=r"(r[3]) : "r"(addr));
}
__device__ __forceinline__ void mma_16816(float* d, const uint32_t* a,
                                          uint32_t b0, uint32_t b1) {
    asm volatile("mma.sync.aligned.m16n8k16.row.col.f32.bf16.bf16.f32 "
        "{%0,%1,%2,%3}, {%4,%5,%6,%7}, {%8,%9}, {%0,%1,%2,%3};"
        : "+f"(d[0]), "+f"(d[1]), "+f"(d[2]), "+f"(d[3])
        : "r"(a[0]), "r"(a[1]), "r"(a[2]), "r"(a[3]), "r"(b0), "r"(b1));
}

// ================= scratch =================
__device__ __nv_bfloat16 g_q3k   [B_ * LQ_  * K3_];           // LN-split q (GEMM A)
__device__ __nv_bfloat16 g_kv3k  [B_ * LKV_ * K3_];           // LN-split kv (GEMM A)
__device__ __nv_bfloat16 g_at3k  [B_ * LQ_  * K3_];           // attn out, split (GEMM A)
__device__ __nv_bfloat16 g_wq3k  [D_ * K3_];
__device__ __nv_bfloat16 g_wkv3k [2 * D_ * K3_];
__device__ __nv_bfloat16 g_wo3k  [D_ * K3_];
__device__ __nv_bfloat16 g_q3 [B_ * H_ * LQ_  * 192];         // Q' per head [hi,lo,hi]
__device__ __nv_bfloat16 g_k3 [B_ * H_ * LKV_ * 192];         // K' per head [hi,hi,lo]
__device__ __nv_bfloat16 g_v2 [B_ * H_ * LKV_ * 128];         // V  per head [hi,lo]
__device__ int g_len[B_];

// ================= mask lengths (dtype-sniffing) =================
__global__ void compute_lengths_kernel(const unsigned char* __restrict__ mask) {
    __shared__ int det[4];
    __shared__ int cnt[4];
    __shared__ int mode;
    int tid = threadIdx.x;
    if (tid < 4) { det[tid] = 0; cnt[tid] = 0; }
    __syncthreads();
    for (int i = tid; i < B_ * LKV_; i += blockDim.x)
        if (mask[i]) atomicOr(&det[i & 3], 1);
    __syncthreads();
    if (tid == 0) {
        if (det[1])                mode = 0;
        else if (det[2] || det[3]) mode = det[0] ? 0 : 2;
        else if (det[0])           mode = 1;
        else                       mode = 0;
    }
    __syncthreads();
    int md = mode;
    for (int b = 0; b < B_; b++) {
        int local = 0;
        for (int k = tid; k < LKV_; k += blockDim.x) {
            int idx = b * LKV_ + k;
            bool t;
            if      (md == 0) t = mask[idx] != 0;
            else if (md == 1) t = ((const int*)  mask)[idx] != 0;
            else              t = ((const float*)mask)[idx] != 0.0f;
            if (!t) local++;
        }
        atomicAdd(&cnt[b], local);
    }
    __syncthreads();
    if (tid < B_) g_len[tid] = cnt[tid];
}

// ================= layernorm + hi/lo split: A' = [hi, lo, hi] =================
__global__ void __launch_bounds__(256) layernorm_split_kernel(
    const float* __restrict__ x, const float* __restrict__ w,
    const float* __restrict__ bb, __nv_bfloat16* __restrict__ y)
{
    int row = blockIdx.x;
    int tid = threadIdx.x;
    const float* xr = x + (size_t)row * D_;
    float4 v = *(const float4*)(xr + tid * 4);
    float s  = v.x + v.y + v.z + v.w;
    float sq = v.x * v.x + v.y * v.y + v.z * v.z + v.w * v.w;
    #pragma unroll
    for (int o = 16; o; o >>= 1) {
        s  += __shfl_xor_sync(0xffffffffu, s,  o);
        sq += __shfl_xor_sync(0xffffffffu, sq, o);
    }
    __shared__ float ss[8], ssq[8];
    int wid = tid >> 5, ln = tid & 31;
    if (ln == 0) { ss[wid] = s; ssq[wid] = sq; }
    __syncthreads();
    if (tid == 0) {
        float S = 0.f, SQ = 0.f;
        #pragma unroll
        for (int i = 0; i < 8; i++) { S += ss[i]; SQ += ssq[i]; }
        float mu  = S * (1.0f / D_);
        float var = SQ * (1.0f / D_) - mu * mu;
        ss[0]  = mu;
        ssq[0] = rsqrtf(fmaxf(var, 0.0f) + 1e-5f);
    }
    __syncthreads();
    float mu = ss[0], inv = ssq[0];
    float4 wv = *(const float4*)(w  + tid * 4);
    float4 bv = *(const float4*)(bb + tid * 4);
    float o[4];
    o[0] = (v.x - mu) * inv * wv.x + bv.x;
    o[1] = (v.y - mu) * inv * wv.y + bv.y;
    o[2] = (v.z - mu) * inv * wv.z + bv.z;
    o[3] = (v.w - mu) * inv * wv.w + bv.w;
    __nv_bfloat16 hi[4], lo[4];
    #pragma unroll
    for (int i = 0; i < 4; i++) {
        hi[i] = __float2bfloat16(o[i]);
        lo[i] = __float2bfloat16(o[i] - __bfloat162float(hi[i]));
    }
    __nv_bfloat16* yr = y + (size_t)row * K3_ + tid * 4;
    *(__nv_bfloat162*)(yr + 0)    = __nv_bfloat162(hi[0], hi[1]);
    *(__nv_bfloat162*)(yr + 2)    = __nv_bfloat162(hi[2], hi[3]);
    *(__nv_bfloat162*)(yr + 1024) = __nv_bfloat162(lo[0], lo[1]);
    *(__nv_bfloat162*)(yr + 1026) = __nv_bfloat162(lo[2], lo[3]);
    *(__nv_bfloat162*)(yr + 2048) = __nv_bfloat162(hi[0], hi[1]);
    *(__nv_bfloat162*)(yr + 2050) = __nv_bfloat162(hi[2], hi[3]);
}

// ================= weight split: B' = [Whi, Whi, Wlo] =================
__global__ void __launch_bounds__(256) weight_split_kernel(
    const float* __restrict__ W, __nv_bfloat16* __restrict__ O)
{
    int idx4 = (blockIdx.x * 256 + threadIdx.x) * 4;
    float4 v = *(const float4*)(W + idx4);
    int n = idx4 >> 10;
    int k = idx4 & 1023;
    float vv[4] = {v.x, v.y, v.z, v.w};
    __nv_bfloat16 hi[4], lo[4];
    #pragma unroll
    for (int i = 0; i < 4; i++) {
        hi[i] = __float2bfloat16(vv[i]);
        lo[i] = __float2bfloat16(vv[i] - __bfloat162float(hi[i]));
    }
    __nv_bfloat16* yr = O + (size_t)n * K3_ + k;
    *(__nv_bfloat162*)(yr + 0)    = __nv_bfloat162(hi[0], hi[1]);
    *(__nv_bfloat162*)(yr + 2)    = __nv_bfloat162(hi[2], hi[3]);
    *(__nv_bfloat162*)(yr + 1024) = __nv_bfloat162(hi[0], hi[1]);
    *(__nv_bfloat162*)(yr + 1026) = __nv_bfloat162(hi[2], hi[3]);
    *(__nv_bfloat162*)(yr + 2048) = __nv_bfloat162(lo[0], lo[1]);
    *(__nv_bfloat162*)(yr + 2050) = __nv_bfloat162(lo[2], lo[3]);
}

// ========== split-write helpers for GEMM epilogues ==========
__device__ __forceinline__ void write_q3_pair(int mrow, int n, float2 v) {
    int b = mrow >> 10, qr = mrow & 1023, h = n >> 6, d = n & 63;
    __nv_bfloat16* dst = g_q3 + ((size_t)((b * H_ + h) * LQ_ + qr)) * 192 + d;
    __nv_bfloat16 h0 = __float2bfloat16(v.x), h1 = __float2bfloat16(v.y);
    __nv_bfloat16 l0 = __float2bfloat16(v.x - __bfloat162float(h0));
    __nv_bfloat16 l1 = __float2bfloat16(v.y - __bfloat162float(h1));
    *(__nv_bfloat162*)(dst)       = __nv_bfloat162(h0, h1);
    *(__nv_bfloat162*)(dst + 64)  = __nv_bfloat162(l0, l1);
    *(__nv_bfloat162*)(dst + 128) = __nv_bfloat162(h0, h1);
}
__device__ __forceinline__ void write_kv_pair(int mrow, int n, float2 v) {
    int b = mrow >> 11, kr = mrow & 2047;
    int h2 = n >> 6, d = n & 63;
    __nv_bfloat16 h0 = __float2bfloat16(v.x), h1 = __float2bfloat16(v.y);
    __nv_bfloat16 l0 = __float2bfloat16(v.x - __bfloat162float(h0));
    __nv_bfloat16 l1 = __float2bfloat16(v.y - __bfloat162float(h1));
    if (h2 < H_) {   // K head: [hi, hi, lo]
        __nv_bfloat16* dst = g_k3 + ((size_t)((b * H_ + h2) * LKV_ + kr)) * 192 + d;
        *(__nv_bfloat162*)(dst)       = __nv_bfloat162(h0, h1);
        *(__nv_bfloat162*)(dst + 64)  = __nv_bfloat162(h0, h1);
        *(__nv_bfloat162*)(dst + 128) = __nv_bfloat162(l0, l1);
    } else {         // V head: [hi, lo]
        __nv_bfloat16* dst = g_v2 + ((size_t)((b * H_ + (h2 - H_)) * LKV_ + kr)) * 128 + d;
        *(__nv_bfloat162*)(dst)      = __nv_bfloat162(h0, h1);
        *(__nv_bfloat162*)(dst + 64) = __nv_bfloat162(l0, l1);
    }
}

// ================= bf16 warp-MMA GEMM: C = A'[M,3072] @ B'[N,3072]^T =================
// mode 0: fp32 C + bias + optional residual; mode 1: Q split; mode 2: KV split.
#define SSTRIDE 40
#define STILE   (128 * SSTRIDE)

__global__ void __launch_bounds__(256) gemm_bf16_mma_kernel(
    const __nv_bfloat16* __restrict__ A, const __nv_bfloat16* __restrict__ W,
    const float* __restrict__ bias, const float* __restrict__ R,
    float* __restrict__ C, int M, int N, int mode)
{
    __shared__ __nv_bfloat16 sa[2][STILE];
    __shared__ __nv_bfloat16 sb[2][STILE];

    const int tid  = threadIdx.x;
    const int lane = tid & 31;
    const int wid  = tid >> 5;
    const int warp_m = wid & 3;
    const int warp_n = wid >> 2;
    const int m0 = blockIdx.y * 128, n0 = blockIdx.x * 128;

    const int lr = tid >> 2;
    const int lu = tid & 3;
    const __nv_bfloat16* ag = A + (size_t)(m0 + lr) * K3_ + lu * 8;
    const __nv_bfloat16* bg = W + (size_t)(n0 + lr) * K3_ + lu * 8;

    float acc[2][8][4];
    #pragma unroll
    for (int i = 0; i < 2; i++)
        #pragma unroll
        for (int j = 0; j < 8; j++)
            #pragma unroll
            for (int t = 0; t < 4; t++) acc[i][j][t] = 0.0f;

    const uint32_t sa_u = smem_to_u32(sa);
    const uint32_t sb_u = smem_to_u32(sb);

    const uint32_t a_off = (uint32_t)((warp_m * 32 + (lane & 15)) * SSTRIDE * 2
                                      + (lane >> 4) * 16);
    const uint32_t b_off = (uint32_t)((warp_n * 64 + ((lane >> 4) & 1) * 8 + (lane & 7)) * SSTRIDE * 2
                                      + ((lane >> 3) & 1) * 16);

    uint4 pa0 = *(const uint4*)(ag);
    uint4 pa1 = *(const uint4*)(ag + (size_t)64 * K3_);
    uint4 pb0 = *(const uint4*)(bg);
    uint4 pb1 = *(const uint4*)(bg + (size_t)64 * K3_);
    *(uint4*)&sa[0][lr * SSTRIDE + lu * 8]        = pa0;
    *(uint4*)&sa[0][(lr + 64) * SSTRIDE + lu * 8] = pa1;
    *(uint4*)&sb[0][lr * SSTRIDE + lu * 8]        = pb0;
    *(uint4*)&sb[0][(lr + 64) * SSTRIDE + lu * 8] = pb1;
    __syncthreads();

    const int NK = K3_ / 32;   // 96
    for (int kt = 0; kt < NK; kt++) {
        const int cur = kt & 1;
        if (kt + 1 < NK) {
            const size_t koff = (size_t)(kt + 1) * 32;
            pa0 = *(const uint4*)(ag + koff);
            pa1 = *(const uint4*)(ag + (size_t)64 * K3_ + koff);
            pb0 = *(const uint4*)(bg + koff);
            pb1 = *(const uint4*)(bg + (size_t)64 * K3_ + koff);
        }
        const uint32_t sa_cur = sa_u + (uint32_t)(cur * STILE * 2);
        const uint32_t sb_cur = sb_u + (uint32_t)(cur * STILE * 2);
        #pragma unroll
        for (int ks = 0; ks < 2; ks++) {
            uint32_t a_frag[2][4];
            #pragma unroll
            for (int im = 0; im < 2; im++)
                ldmatrix_x4(a_frag[im], sa_cur + a_off
                            + (uint32_t)(im * 16 * SSTRIDE * 2 + ks * 32));
            uint32_t b_frag[4][4];
            #pragma unroll
            for (int iu = 0; iu < 4; iu++)
                ldmatrix_x4(b_frag[iu], sb_cur + b_off
                            + (uint32_t)(iu * 16 * SSTRIDE * 2 + ks * 32));
            #pragma unroll
            for (int im = 0; im < 2; im++)
                #pragma unroll
                for (int iu = 0; iu < 4; iu++) {
                    mma_16816(acc[im][iu * 2 + 0], a_frag[im], b_frag[iu][0], b_frag[iu][1]);
                    mma_16816(acc[im][iu * 2 + 1], a_frag[im], b_frag[iu][2], b_frag[iu][3]);
                }
        }
        if (kt + 1 < NK) {
            const int nxt = cur ^ 1;
            *(uint4*)&sa[nxt][lr * SSTRIDE + lu * 8]        = pa0;
            *(uint4*)&sa[nxt][(lr + 64) * SSTRIDE + lu * 8] = pa1;
            *(uint4*)&sb[nxt][lr * SSTRIDE + lu * 8]        = pb0;
            *(uint4*)&sb[nxt][(lr + 64) * SSTRIDE + lu * 8] = pb1;
            __syncthreads();
        }
    }

    const int gr = lane >> 2;
    const int gc = (lane & 3) * 2;
    #pragma unroll
    for (int im = 0; im < 2; im++) {
        const int mrow = m0 + warp_m * 32 + im * 16 + gr;
        #pragma unroll
        for (int in = 0; in < 8; in++) {
            const int n = n0 + warp_n * 64 + in * 8 + gc;
            float b0 = bias[n], b1 = bias[n + 1];
            float2 v0 = make_float2(acc[im][in][0] + b0, acc[im][in][1] + b1);
            float2 v1 = make_float2(acc[im][in][2] + b0, acc[im][in][3] + b1);
            if (mode == 0) {
                if (R) {
                    float2 r0 = *(const float2*)(R + (size_t)mrow * N + n);
                    float2 r1 = *(const float2*)(R + (size_t)(mrow + 8) * N + n);
                    v0.x += r0.x; v0.y += r0.y;
                    v1.x += r1.x; v1.y += r1.y;
                }
                *(float2*)(C + (size_t)mrow * N + n)       = v0;
                *(float2*)(C + (size_t)(mrow + 8) * N + n) = v1;
            } else if (mode == 1) {
                write_q3_pair(mrow,     n, v0);
                write_q3_pair(mrow + 8, n, v1);
            } else {
                write_kv_pair(mrow,     n, v0);
                write_kv_pair(mrow + 8, n, v1);
            }
        }
    }
}

// ================= HMMA flash attention =================
// Block: 128 q-rows x (b,h). 8 warps, warp = 16 q rows x full 64 kv / 64 d.
// QK^T: K=192 split MMA. PV: 3-term split via Phi/Plo smem and Vhi/Vlo.
#define AQ   128
#define SQ3  200   // Q/K smem row stride (bf16)
#define SV   72    // V/P smem row stride (bf16)
// smem layout (bf16 elems): K3s 0..12800, Vhi 12800, Vlo 17408, Phi 22016,
// Plo 31232, Q3s 40448..66048  => 132096 bytes
#define FA_SMEM_BYTES (66048 * 2)

__global__ void __launch_bounds__(256) flash_attn_mma_kernel(
    const __nv_bfloat16* __restrict__ q3, const __nv_bfloat16* __restrict__ k3,
    const __nv_bfloat16* __restrict__ v2, __nv_bfloat16* __restrict__ out3k)
{
    extern __shared__ __nv_bfloat16 smem_bf[];
    __nv_bfloat16* K3s = smem_bf;
    __nv_bfloat16* Vhi = smem_bf + 12800;
    __nv_bfloat16* Vlo = smem_bf + 17408;
    __nv_bfloat16* Phi = smem_bf + 22016;
    __nv_bfloat16* Plo = smem_bf + 31232;
    __nv_bfloat16* Q3s = smem_bf + 40448;

    const int b = blockIdx.z, h = blockIdx.y, qt = blockIdx.x;
    const int tid = threadIdx.x, lane = tid & 31, wid = tid >> 5;
    const int gr = lane >> 2, gc = (lane & 3) * 2;

    // ---- load Q tile [128][192] ----
    const __nv_bfloat16* qg = q3 + ((size_t)((b * H_ + h) * LQ_ + qt * AQ)) * 192;
    for (int idx = tid; idx < AQ * 24; idx += 256) {
        int r = idx / 24, u = idx % 24;
        *(uint4*)&Q3s[r * SQ3 + u * 8] = *(const uint4*)(qg + (size_t)r * 192 + u * 8);
    }
    __syncthreads();

    // ---- preload Q a-frags (12 k16-steps) ----
    uint32_t qfrag[12][4];
    const uint32_t q3s_u = smem_to_u32(Q3s);
    const uint32_t a_base = q3s_u + (uint32_t)((wid * 16 + (lane & 15)) * SQ3 * 2
                                               + (lane >> 4) * 16);
    #pragma unroll
    for (int ks = 0; ks < 12; ks++)
        ldmatrix_x4(qfrag[ks], a_base + (uint32_t)(ks * 32));

    const uint32_t k3s_u = smem_to_u32(K3s);
    const uint32_t vhi_u = smem_to_u32(Vhi);
    const uint32_t vlo_u = smem_to_u32(Vlo);
    const uint32_t phi_u = smem_to_u32(Phi);
    const uint32_t plo_u = smem_to_u32(Plo);
    const uint32_t kb_off = (uint32_t)((((lane >> 4) & 1) * 8 + (lane & 7)) * SQ3 * 2
                                       + ((lane >> 3) & 1) * 16);
    const uint32_t vb_off = (uint32_t)(((lane & 7) + ((lane >> 3) & 1) * 8) * SV * 2
                                       + (lane >> 4) * 16);
    const uint32_t pa_off = (uint32_t)((wid * 16 + (lane & 15)) * SV * 2
                                       + (lane >> 4) * 16);

    const int len   = g_len[b];
    const int ntile = (len + 63) >> 6;

    float m_r[2] = {-1e30f, -1e30f};
    float l_r[2] = {0.0f, 0.0f};
    float acc_o[8][4];
    #pragma unroll
    for (int i = 0; i < 8; i++)
        #pragma unroll
        for (int j = 0; j < 4; j++) acc_o[i][j] = 0.0f;

    for (int kt = 0; kt < ntile; kt++) {
        __syncthreads();
        // ---- load K'[64][192] and V[64][128] (hi|lo) ----
        const __nv_bfloat16* kg = k3 + ((size_t)((b * H_ + h) * LKV_ + kt * 64)) * 192;
        for (int idx = tid; idx < 64 * 24; idx += 256) {
            int r = idx / 24, u = idx % 24;
            *(uint4*)&K3s[r * SQ3 + u * 8] = *(const uint4*)(kg + (size_t)r * 192 + u * 8);
        }
        const __nv_bfloat16* vg = v2 + ((size_t)((b * H_ + h) * LKV_ + kt * 64)) * 128;
        for (int idx = tid; idx < 64 * 16; idx += 256) {
            int r = idx / 16, u = idx % 16;
            uint4 val = *(const uint4*)(vg + (size_t)r * 128 + u * 8);
            if (u < 8) *(uint4*)&Vhi[r * SV + u * 8]       = val;
            else       *(uint4*)&Vlo[r * SV + (u - 8) * 8] = val;
        }
        __syncthreads();

        // ---- S = Q' @ K'^T (12 k16-steps) ----
        float acc_s[8][4];
        #pragma unroll
        for (int i = 0; i < 8; i++)
            #pragma unroll
            for (int j = 0; j < 4; j++) acc_s[i][j] = 0.0f;

        #pragma unroll
        for (int ks = 0; ks < 12; ks++) {
            uint32_t bf[4][4];
            #pragma unroll
            for (int nt4 = 0; nt4 < 4; nt4++)
                ldmatrix_x4(bf[nt4], k3s_u + kb_off
                            + (uint32_t)(nt4 * 16 * SQ3 * 2 + ks * 32));
            #pragma unroll
            for (int nt4 = 0; nt4 < 4; nt4++) {
                mma_16816(acc_s[nt4 * 2 + 0], qfrag[ks], bf[nt4][0], bf[nt4][1]);
                mma_16816(acc_s[nt4 * 2 + 1], qfrag[ks], bf[nt4][2], bf[nt4][3]);
            }
        }

        // ---- scale + mask ----
        const int rem = len - kt * 64;
        #pragma unroll
        for (int nt = 0; nt < 8; nt++) {
            int c0 = nt * 8 + gc;
            bool k0 = (c0 >= rem), k1 = (c0 + 1 >= rem);
            acc_s[nt][0] = k0 ? -1e9f : acc_s[nt][0] * 0.125f;
            acc_s[nt][1] = k1 ? -1e9f : acc_s[nt][1] * 0.125f;
            acc_s[nt][2] = k0 ? -1e9f : acc_s[nt][2] * 0.125f;
            acc_s[nt][3] = k1 ? -1e9f : acc_s[nt][3] * 0.125f;
        }

        // ---- online softmax (rows gr, gr+8; reduce over lane&3 group) ----
        float tmax0 = -1e30f, tmax1 = -1e30f;
        #pragma unroll
        for (int nt = 0; nt < 8; nt++) {
            tmax0 = fmaxf(tmax0, fmaxf(acc_s[nt][0], acc_s[nt][1]));
            tmax1 = fmaxf(tmax1, fmaxf(acc_s[nt][2], acc_s[nt][3]));
        }
        #pragma unroll
        for (int o = 1; o < 4; o <<= 1) {
            tmax0 = fmaxf(tmax0, __shfl_xor_sync(0xffffffffu, tmax0, o));
            tmax1 = fmaxf(tmax1, __shfl_xor_sync(0xffffffffu, tmax1, o));
        }
        float mn0 = fmaxf(m_r[0], tmax0), mn1 = fmaxf(m_r[1], tmax1);
        float al0 = __expf(m_r[0] - mn0), al1 = __expf(m_r[1] - mn1);
        float rs0 = 0.0f, rs1 = 0.0f;
        #pragma unroll
        for (int nt = 0; nt < 8; nt++) {
            acc_s[nt][0] = __expf(acc_s[nt][0] - mn0);
            acc_s[nt][1] = __expf(acc_s[nt][1] - mn0);
            acc_s[nt][2] = __expf(acc_s[nt][2] - mn1);
            acc_s[nt][3] = __expf(acc_s[nt][3] - mn1);
            rs0 += acc_s[nt][0] + acc_s[nt][1];
            rs1 += acc_s[nt][2] + acc_s[nt][3];
        }
        #pragma unroll
        for (int o = 1; o < 4; o <<= 1) {
            rs0 += __shfl_xor_sync(0xffffffffu, rs0, o);
            rs1 += __shfl_xor_sync(0xffffffffu, rs1, o);
        }
        l_r[0] = l_r[0] * al0 + rs0;  m_r[0] = mn0;
        l_r[1] = l_r[1] * al1 + rs1;  m_r[1] = mn1;
        #pragma unroll
        for (int nt = 0; nt < 8; nt++) {
            acc_o[nt][0] *= al0; acc_o[nt][1] *= al0;
            acc_o[nt][2] *= al1; acc_o[nt][3] *= al1;
        }

        // ---- P -> smem split (warp-private rows) ----
        const int pr0 = wid * 16 + gr, pr1 = pr0 + 8;
        #pragma unroll
        for (int nt = 0; nt < 8; nt++) {
            int c0 = nt * 8 + gc;
            __nv_bfloat16 h0 = __float2bfloat16(acc_s[nt][0]);
            __nv_bfloat16 h1 = __float2bfloat16(acc_s[nt][1]);
            __nv_bfloat16 h2 = __float2bfloat16(acc_s[nt][2]);
            __nv_bfloat16 h3 = __float2bfloat16(acc_s[nt][3]);
            *(__nv_bfloat162*)&Phi[pr0 * SV + c0] = __nv_bfloat162(h0, h1);
            *(__nv_bfloat162*)&Phi[pr1 * SV + c0] = __nv_bfloat162(h2, h3);
            __nv_bfloat16 l0 = __float2bfloat16(acc_s[nt][0] - __bfloat162float(h0));
            __nv_bfloat16 l1 = __float2bfloat16(acc_s[nt][1] - __bfloat162float(h1));
            __nv_bfloat16 l2 = __float2bfloat16(acc_s[nt][2] - __bfloat162float(h2));
            __nv_bfloat16 l3 = __float2bfloat16(acc_s[nt][3] - __bfloat162float(h3));
            *(__nv_bfloat162*)&Plo[pr0 * SV + c0] = __nv_bfloat162(l0, l1);
            *(__nv_bfloat162*)&Plo[pr1 * SV + c0] = __nv_bfloat162(l2, l3);
        }
        __syncwarp();

        // ---- O += P @ V  (3 split terms x 4 k16-steps) ----
        #pragma unroll
        for (int t = 0; t < 3; t++) {
            const uint32_t pa_u = ((t == 1) ? plo_u : phi_u) + pa_off;
            const uint32_t vb_u = ((t == 2) ? vlo_u : vhi_u) + vb_off;
            #pragma unroll
            for (int ks4 = 0; ks4 < 4; ks4++) {
                uint32_t af[4];
                ldmatrix_x4(af, pa_u + (uint32_t)(ks4 * 32));
                uint32_t bf[4][4];
                #pragma unroll
                for (int g = 0; g < 4; g++)
                    ldmatrix_x4_trans(bf[g], vb_u
                                      + (uint32_t)(ks4 * 16 * SV * 2 + g * 32));
                #pragma unroll
                for (int g = 0; g < 4; g++) {
                    mma_16816(acc_o[g * 2 + 0], af, bf[g][0], bf[g][1]);
                    mma_16816(acc_o[g * 2 + 1], af, bf[g][2], bf[g][3]);
                }
            }
        }
    }

    // ---- epilogue: normalize + write split [hi,lo,hi] rows to at3k ----
    float inv0 = 1.0f / l_r[0], inv1 = 1.0f / l_r[1];
    const int qrow0 = qt * AQ + wid * 16 + gr;
    const size_t row0 = ((size_t)(b * LQ_ + qrow0)) * K3_;
    const size_t row1 = row0 + (size_t)8 * K3_;
    #pragma unroll
    for (int nt = 0; nt < 8; nt++) {
        int col = h * HD_ + nt * 8 + gc;
        float v00 = acc_o[nt][0] * inv0, v01 = acc_o[nt][1] * inv0;
        float v10 = acc_o[nt][2] * inv1, v11 = acc_o[nt][3] * inv1;
        __nv_bfloat16 a0 = __float2bfloat16(v00), a1 = __float2bfloat16(v01);
        __nv_bfloat16 b0 = __float2bfloat16(v10), b1 = __float2bfloat16(v11);
        __nv_bfloat16 c0 = __float2bfloat16(v00 - __bfloat162float(a0));
        __nv_bfloat16 c1 = __float2bfloat16(v01 - __bfloat162float(a1));
        __nv_bfloat16 d0 = __float2bfloat16(v10 - __bfloat162float(b0));
        __nv_bfloat16 d1 = __float2bfloat16(v11 - __bfloat162float(b1));
        __nv_bfloat16* p0 = out3k + row0 + col;
        __nv_bfloat16* p1 = out3k + row1 + col;
        *(__nv_bfloat162*)(p0)        = __nv_bfloat162(a0, a1);
        *(__nv_bfloat162*)(p0 + 1024) = __nv_bfloat162(c0, c1);
        *(__nv_bfloat162*)(p0 + 2048) = __nv_bfloat162(a0, a1);
        *(__nv_bfloat162*)(p1)        = __nv_bfloat162(b0, b1);
        *(__nv_bfloat162*)(p1 + 1024) = __nv_bfloat162(d0, d1);
        *(__nv_bfloat162*)(p1 + 2048) = __nv_bfloat162(b0, b1);
    }
}

// ================= host launcher =================
extern "C" void kernel_launch(void* const* d_in, const int* in_sizes, int n_in,
                              void* d_out, int out_size) {
    const float*         q    = (const float*)d_in[0];
    const float*         kv   = (const float*)d_in[1];
    const unsigned char* mask = (const unsigned char*)d_in[2];
    const float*         nqw  = (const float*)d_in[3];
    const float*         nqb  = (const float*)d_in[4];
    const float*         nkw  = (const float*)d_in[5];
    const float*         nkb  = (const float*)d_in[6];
    const float*         Wq   = (const float*)d_in[7];
    const float*         bq   = (const float*)d_in[8];
    const float*         Wkv  = (const float*)d_in[9];
    const float*         bkv  = (const float*)d_in[10];
    const float*         Wo   = (const float*)d_in[11];
    const float*         bo   = (const float*)d_in[12];
    float* out = (float*)d_out;

    __nv_bfloat16 *q3k, *kv3k, *at3k, *wq3k, *wkv3k, *wo3k, *q3, *k3, *v2;
    cudaGetSymbolAddress((void**)&q3k,   g_q3k);
    cudaGetSymbolAddress((void**)&kv3k,  g_kv3k);
    cudaGetSymbolAddress((void**)&at3k,  g_at3k);
    cudaGetSymbolAddress((void**)&wq3k,  g_wq3k);
    cudaGetSymbolAddress((void**)&wkv3k, g_wkv3k);
    cudaGetSymbolAddress((void**)&wo3k,  g_wo3k);
    cudaGetSymbolAddress((void**)&q3,    g_q3);
    cudaGetSymbolAddress((void**)&k3,    g_k3);
    cudaGetSymbolAddress((void**)&v2,    g_v2);

    cudaFuncSetAttribute(flash_attn_mma_kernel,
                         cudaFuncAttributeMaxDynamicSharedMemorySize, FA_SMEM_BYTES);

    compute_lengths_kernel<<<1, 256>>>(mask);
    layernorm_split_kernel<<<B_ * LQ_,  256>>>(q,  nqw, nqb, q3k);
    layernorm_split_kernel<<<B_ * LKV_, 256>>>(kv, nkw, nkb, kv3k);
    weight_split_kernel<<<(D_ * D_) / 1024,     256>>>(Wq,  wq3k);
    weight_split_kernel<<<(2 * D_ * D_) / 1024, 256>>>(Wkv, wkv3k);
    weight_split_kernel<<<(D_ * D_) / 1024,     256>>>(Wo,  wo3k);

    dim3 gq(D_ / 128, (B_ * LQ_) / 128);          // (8, 32)
    gemm_bf16_mma_kernel<<<gq, 256>>>(q3k, wq3k, bq, nullptr, nullptr,
                                      B_ * LQ_, D_, 1);

    dim3 gkv((2 * D_) / 128, (B_ * LKV_) / 128);  // (16, 64)
    gemm_bf16_mma_kernel<<<gkv, 256>>>(kv3k, wkv3k, bkv, nullptr, nullptr,
                                       B_ * LKV_, 2 * D_, 2);

    flash_attn_mma_kernel<<<dim3(LQ_ / AQ, H_, B_), 256, FA_SMEM_BYTES>>>(
        q3, k3, v2, at3k);

    gemm_bf16_mma_kernel<<<gq, 256>>>(at3k, wo3k, bo, q, out,
                                      B_ * LQ_, D_, 0);
}

// round 9
// speedup vs baseline: 2.1354x; 1.5099x over previous
#include <cuda_runtime.h>
#include <cuda_bf16.h>
#include <math.h>
#include <stdint.h>

// Problem dims
#define B_   4
#define LQ_  1024
#define LKV_ 2048
#define D_   1024
#define H_   16
#define HD_  64
#define K3_  3072   // split-K: [hi, lo, hi] x 1024

// ================= warp-MMA helpers (baseline PTX, sm_80+) =================
__device__ __forceinline__ uint32_t smem_to_u32(const void* p) {
    uint32_t a;
    asm("{ .reg .u64 t; cvta.to.shared.u64 t, %1; cvt.u32.u64 %0, t; }"
        : "=r"(a) : "l"(p));
    return a;
}
__device__ __forceinline__ void ldmatrix_x4(uint32_t* r, uint32_t addr) {
    asm volatile("ldmatrix.sync.aligned.m8n8.x4.shared.b16 {%0,%1,%2,%3}, [%4];"
        : "=r"(r[0]), "=r"(r[1]), "=r"(r[2]), "=r"(r[3]) : "r"(addr));
}
__device__ __forceinline__ void ldmatrix_x4_trans(uint32_t* r, uint32_t addr) {
    asm volatile("ldmatrix.sync.aligned.m8n8.x4.trans.shared.b16 {%0,%1,%2,%3}, [%4];"
        : "=r"(r[0]), "=r"(r[1]), "=r"(r[2]), "=r"(r[3]) : "r"(addr));
}
__device__ __forceinline__ void mma_16816(float* d, const uint32_t* a,
                                          uint32_t b0, uint32_t b1) {
    asm volatile("mma.sync.aligned.m16n8k16.row.col.f32.bf16.bf16.f32 "
        "{%0,%1,%2,%3}, {%4,%5,%6,%7}, {%8,%9}, {%0,%1,%2,%3};"
        : "+f"(d[0]), "+f"(d[1]), "+f"(d[2]), "+f"(d[3])
        : "r"(a[0]), "r"(a[1]), "r"(a[2]), "r"(a[3]), "r"(b0), "r"(b1));
}
__device__ __forceinline__ void cp_async16(uint32_t smem_addr, const void* gptr) {
    asm volatile("cp.async.cg.shared.global [%0], [%1], 16;"
        :: "r"(smem_addr), "l"(gptr));
}
#define CP_ASYNC_COMMIT() asm volatile("cp.async.commit_group;" ::: "memory")
#define CP_ASYNC_WAIT(N)  asm volatile("cp.async.wait_group %0;" :: "n"(N) : "memory")

// ================= scratch =================
__device__ __nv_bfloat16 g_q3k   [B_ * LQ_  * K3_];
__device__ __nv_bfloat16 g_kv3k  [B_ * LKV_ * K3_];
__device__ __nv_bfloat16 g_at3k  [B_ * LQ_  * K3_];
__device__ __nv_bfloat16 g_wq3k  [D_ * K3_];
__device__ __nv_bfloat16 g_wkv3k [2 * D_ * K3_];
__device__ __nv_bfloat16 g_wo3k  [D_ * K3_];
__device__ __nv_bfloat16 g_q3 [B_ * H_ * LQ_  * 192];   // Q' per head [hi,lo,hi]
__device__ __nv_bfloat16 g_k3 [B_ * H_ * LKV_ * 192];   // K' per head [hi,hi,lo]
__device__ __nv_bfloat16 g_v2 [B_ * H_ * LKV_ * 128];   // V  per head [hi,lo]
__device__ int g_len[B_];

// ================= mask lengths (dtype-sniffing) =================
__global__ void compute_lengths_kernel(const unsigned char* __restrict__ mask) {
    __shared__ int det[4];
    __shared__ int cnt[4];
    __shared__ int mode;
    int tid = threadIdx.x;
    if (tid < 4) { det[tid] = 0; cnt[tid] = 0; }
    __syncthreads();
    for (int i = tid; i < B_ * LKV_; i += blockDim.x)
        if (mask[i]) atomicOr(&det[i & 3], 1);
    __syncthreads();
    if (tid == 0) {
        if (det[1])                mode = 0;
        else if (det[2] || det[3]) mode = det[0] ? 0 : 2;
        else if (det[0])           mode = 1;
        else                       mode = 0;
    }
    __syncthreads();
    int md = mode;
    for (int b = 0; b < B_; b++) {
        int local = 0;
        for (int k = tid; k < LKV_; k += blockDim.x) {
            int idx = b * LKV_ + k;
            bool t;
            if      (md == 0) t = mask[idx] != 0;
            else if (md == 1) t = ((const int*)  mask)[idx] != 0;
            else              t = ((const float*)mask)[idx] != 0.0f;
            if (!t) local++;
        }
        atomicAdd(&cnt[b], local);
    }
    __syncthreads();
    if (tid < B_) g_len[tid] = cnt[tid];
}

// ================= layernorm + hi/lo split: A' = [hi, lo, hi] =================
__global__ void __launch_bounds__(256) layernorm_split_kernel(
    const float* __restrict__ x, const float* __restrict__ w,
    const float* __restrict__ bb, __nv_bfloat16* __restrict__ y)
{
    int row = blockIdx.x;
    int tid = threadIdx.x;
    const float* xr = x + (size_t)row * D_;
    float4 v = *(const float4*)(xr + tid * 4);
    float s  = v.x + v.y + v.z + v.w;
    float sq = v.x * v.x + v.y * v.y + v.z * v.z + v.w * v.w;
    #pragma unroll
    for (int o = 16; o; o >>= 1) {
        s  += __shfl_xor_sync(0xffffffffu, s,  o);
        sq += __shfl_xor_sync(0xffffffffu, sq, o);
    }
    __shared__ float ss[8], ssq[8];
    int wid = tid >> 5, ln = tid & 31;
    if (ln == 0) { ss[wid] = s; ssq[wid] = sq; }
    __syncthreads();
    if (tid == 0) {
        float S = 0.f, SQ = 0.f;
        #pragma unroll
        for (int i = 0; i < 8; i++) { S += ss[i]; SQ += ssq[i]; }
        float mu  = S * (1.0f / D_);
        float var = SQ * (1.0f / D_) - mu * mu;
        ss[0]  = mu;
        ssq[0] = rsqrtf(fmaxf(var, 0.0f) + 1e-5f);
    }
    __syncthreads();
    float mu = ss[0], inv = ssq[0];
    float4 wv = *(const float4*)(w  + tid * 4);
    float4 bv = *(const float4*)(bb + tid * 4);
    float o[4];
    o[0] = (v.x - mu) * inv * wv.x + bv.x;
    o[1] = (v.y - mu) * inv * wv.y + bv.y;
    o[2] = (v.z - mu) * inv * wv.z + bv.z;
    o[3] = (v.w - mu) * inv * wv.w + bv.w;
    __nv_bfloat16 hi[4], lo[4];
    #pragma unroll
    for (int i = 0; i < 4; i++) {
        hi[i] = __float2bfloat16(o[i]);
        lo[i] = __float2bfloat16(o[i] - __bfloat162float(hi[i]));
    }
    __nv_bfloat16* yr = y + (size_t)row * K3_ + tid * 4;
    *(__nv_bfloat162*)(yr + 0)    = __nv_bfloat162(hi[0], hi[1]);
    *(__nv_bfloat162*)(yr + 2)    = __nv_bfloat162(hi[2], hi[3]);
    *(__nv_bfloat162*)(yr + 1024) = __nv_bfloat162(lo[0], lo[1]);
    *(__nv_bfloat162*)(yr + 1026) = __nv_bfloat162(lo[2], lo[3]);
    *(__nv_bfloat162*)(yr + 2048) = __nv_bfloat162(hi[0], hi[1]);
    *(__nv_bfloat162*)(yr + 2050) = __nv_bfloat162(hi[2], hi[3]);
}

// ================= weight split: B' = [Whi, Whi, Wlo] =================
__global__ void __launch_bounds__(256) weight_split_kernel(
    const float* __restrict__ W, __nv_bfloat16* __restrict__ O)
{
    int idx4 = (blockIdx.x * 256 + threadIdx.x) * 4;
    float4 v = *(const float4*)(W + idx4);
    int n = idx4 >> 10;
    int k = idx4 & 1023;
    float vv[4] = {v.x, v.y, v.z, v.w};
    __nv_bfloat16 hi[4], lo[4];
    #pragma unroll
    for (int i = 0; i < 4; i++) {
        hi[i] = __float2bfloat16(vv[i]);
        lo[i] = __float2bfloat16(vv[i] - __bfloat162float(hi[i]));
    }
    __nv_bfloat16* yr = O + (size_t)n * K3_ + k;
    *(__nv_bfloat162*)(yr + 0)    = __nv_bfloat162(hi[0], hi[1]);
    *(__nv_bfloat162*)(yr + 2)    = __nv_bfloat162(hi[2], hi[3]);
    *(__nv_bfloat162*)(yr + 1024) = __nv_bfloat162(hi[0], hi[1]);
    *(__nv_bfloat162*)(yr + 1026) = __nv_bfloat162(hi[2], hi[3]);
    *(__nv_bfloat162*)(yr + 2048) = __nv_bfloat162(lo[0], lo[1]);
    *(__nv_bfloat162*)(yr + 2050) = __nv_bfloat162(lo[2], lo[3]);
}

// ========== split-write helpers for GEMM epilogues ==========
__device__ __forceinline__ void write_q3_pair(int mrow, int n, float2 v) {
    int b = mrow >> 10, qr = mrow & 1023, h = n >> 6, d = n & 63;
    __nv_bfloat16* dst = g_q3 + ((size_t)((b * H_ + h) * LQ_ + qr)) * 192 + d;
    __nv_bfloat16 h0 = __float2bfloat16(v.x), h1 = __float2bfloat16(v.y);
    __nv_bfloat16 l0 = __float2bfloat16(v.x - __bfloat162float(h0));
    __nv_bfloat16 l1 = __float2bfloat16(v.y - __bfloat162float(h1));
    *(__nv_bfloat162*)(dst)       = __nv_bfloat162(h0, h1);
    *(__nv_bfloat162*)(dst + 64)  = __nv_bfloat162(l0, l1);
    *(__nv_bfloat162*)(dst + 128) = __nv_bfloat162(h0, h1);
}
__device__ __forceinline__ void write_kv_pair(int mrow, int n, float2 v) {
    int b = mrow >> 11, kr = mrow & 2047;
    int h2 = n >> 6, d = n & 63;
    __nv_bfloat16 h0 = __float2bfloat16(v.x), h1 = __float2bfloat16(v.y);
    __nv_bfloat16 l0 = __float2bfloat16(v.x - __bfloat162float(h0));
    __nv_bfloat16 l1 = __float2bfloat16(v.y - __bfloat162float(h1));
    if (h2 < H_) {   // K head: [hi, hi, lo]
        __nv_bfloat16* dst = g_k3 + ((size_t)((b * H_ + h2) * LKV_ + kr)) * 192 + d;
        *(__nv_bfloat162*)(dst)       = __nv_bfloat162(h0, h1);
        *(__nv_bfloat162*)(dst + 64)  = __nv_bfloat162(h0, h1);
        *(__nv_bfloat162*)(dst + 128) = __nv_bfloat162(l0, l1);
    } else {         // V head: [hi, lo]
        __nv_bfloat16* dst = g_v2 + ((size_t)((b * H_ + (h2 - H_)) * LKV_ + kr)) * 128 + d;
        *(__nv_bfloat162*)(dst)      = __nv_bfloat162(h0, h1);
        *(__nv_bfloat162*)(dst + 64) = __nv_bfloat162(l0, l1);
    }
}

// ================= bf16 warp-MMA GEMM (4-stage cp.async pipeline) =================
// C = A'[M,3072] @ B'[N,3072]^T, 128x128 CTA tile, 8 warps 32x64, BK=32.
// mode 0: fp32 C + bias + residual; mode 1: Q split; mode 2: KV split.
#define SSTRIDE 40                      // bf16 per smem row (80B)
#define GSTAGE_BYTES (128 * SSTRIDE * 2)   // 10240 B per operand stage
#define GSTAGES 4
#define GEMM_SMEM (2 * GSTAGES * GSTAGE_BYTES)  // 81920 B

__global__ void __launch_bounds__(256) gemm_bf16_mma_kernel(
    const __nv_bfloat16* __restrict__ A, const __nv_bfloat16* __restrict__ W,
    const float* __restrict__ bias, const float* __restrict__ R,
    float* __restrict__ C, int M, int N, int mode)
{
    extern __shared__ char gsm[];
    const uint32_t smem_u = smem_to_u32(gsm);
    const uint32_t sa_u = smem_u;                                // stages 0..3
    const uint32_t sb_u = smem_u + GSTAGES * GSTAGE_BYTES;       // stages 0..3

    const int tid  = threadIdx.x;
    const int lane = tid & 31;
    const int wid  = tid >> 5;
    const int warp_m = wid & 3;
    const int warp_n = wid >> 2;
    const int m0 = blockIdx.y * 128, n0 = blockIdx.x * 128;

    const int lr = tid >> 2;            // 0..63
    const int lu = tid & 3;             // 16B unit
    const __nv_bfloat16* ag = A + (size_t)(m0 + lr) * K3_ + lu * 8;
    const __nv_bfloat16* bg = W + (size_t)(n0 + lr) * K3_ + lu * 8;
    const uint32_t row_b  = (uint32_t)(lr * SSTRIDE * 2 + lu * 16);
    const uint32_t row_b2 = row_b + (uint32_t)(64 * SSTRIDE * 2);

    float acc[2][8][4];
    #pragma unroll
    for (int i = 0; i < 2; i++)
        #pragma unroll
        for (int j = 0; j < 8; j++)
            #pragma unroll
            for (int t = 0; t < 4; t++) acc[i][j][t] = 0.0f;

    const uint32_t a_off = (uint32_t)((warp_m * 32 + (lane & 15)) * SSTRIDE * 2
                                      + (lane >> 4) * 16);
    const uint32_t b_off = (uint32_t)((warp_n * 64 + ((lane >> 4) & 1) * 8 + (lane & 7)) * SSTRIDE * 2
                                      + ((lane >> 3) & 1) * 16);

    const int NK = K3_ / 32;   // 96

    // prologue: issue stages 0..2
    #pragma unroll
    for (int s = 0; s < 3; s++) {
        const size_t koff = (size_t)s * 32;
        const uint32_t sa_s = sa_u + (uint32_t)(s * GSTAGE_BYTES);
        const uint32_t sb_s = sb_u + (uint32_t)(s * GSTAGE_BYTES);
        cp_async16(sa_s + row_b,  ag + koff);
        cp_async16(sa_s + row_b2, ag + (size_t)64 * K3_ + koff);
        cp_async16(sb_s + row_b,  bg + koff);
        cp_async16(sb_s + row_b2, bg + (size_t)64 * K3_ + koff);
        CP_ASYNC_COMMIT();
    }

    for (int kt = 0; kt < NK; kt++) {
        CP_ASYNC_WAIT(2);
        __syncthreads();
        // issue stage kt+3 (safe: all threads finished computing on this buffer)
        if (kt + 3 < NK) {
            const int s = (kt + 3) & 3;
            const size_t koff = (size_t)(kt + 3) * 32;
            const uint32_t sa_s = sa_u + (uint32_t)(s * GSTAGE_BYTES);
            const uint32_t sb_s = sb_u + (uint32_t)(s * GSTAGE_BYTES);
            cp_async16(sa_s + row_b,  ag + koff);
            cp_async16(sa_s + row_b2, ag + (size_t)64 * K3_ + koff);
            cp_async16(sb_s + row_b,  bg + koff);
            cp_async16(sb_s + row_b2, bg + (size_t)64 * K3_ + koff);
        }
        CP_ASYNC_COMMIT();

        const int cur = kt & 3;
        const uint32_t sa_cur = sa_u + (uint32_t)(cur * GSTAGE_BYTES);
        const uint32_t sb_cur = sb_u + (uint32_t)(cur * GSTAGE_BYTES);
        #pragma unroll
        for (int ks = 0; ks < 2; ks++) {
            uint32_t a_frag[2][4];
            #pragma unroll
            for (int im = 0; im < 2; im++)
                ldmatrix_x4(a_frag[im], sa_cur + a_off
                            + (uint32_t)(im * 16 * SSTRIDE * 2 + ks * 32));
            uint32_t b_frag[4][4];
            #pragma unroll
            for (int iu = 0; iu < 4; iu++)
                ldmatrix_x4(b_frag[iu], sb_cur + b_off
                            + (uint32_t)(iu * 16 * SSTRIDE * 2 + ks * 32));
            #pragma unroll
            for (int im = 0; im < 2; im++)
                #pragma unroll
                for (int iu = 0; iu < 4; iu++) {
                    mma_16816(acc[im][iu * 2 + 0], a_frag[im], b_frag[iu][0], b_frag[iu][1]);
                    mma_16816(acc[im][iu * 2 + 1], a_frag[im], b_frag[iu][2], b_frag[iu][3]);
                }
        }
    }

    const int gr = lane >> 2;
    const int gc = (lane & 3) * 2;
    #pragma unroll
    for (int im = 0; im < 2; im++) {
        const int mrow = m0 + warp_m * 32 + im * 16 + gr;
        #pragma unroll
        for (int in = 0; in < 8; in++) {
            const int n = n0 + warp_n * 64 + in * 8 + gc;
            float b0 = bias[n], b1 = bias[n + 1];
            float2 v0 = make_float2(acc[im][in][0] + b0, acc[im][in][1] + b1);
            float2 v1 = make_float2(acc[im][in][2] + b0, acc[im][in][3] + b1);
            if (mode == 0) {
                if (R) {
                    float2 r0 = *(const float2*)(R + (size_t)mrow * N + n);
                    float2 r1 = *(const float2*)(R + (size_t)(mrow + 8) * N + n);
                    v0.x += r0.x; v0.y += r0.y;
                    v1.x += r1.x; v1.y += r1.y;
                }
                *(float2*)(C + (size_t)mrow * N + n)       = v0;
                *(float2*)(C + (size_t)(mrow + 8) * N + n) = v1;
            } else if (mode == 1) {
                write_q3_pair(mrow,     n, v0);
                write_q3_pair(mrow + 8, n, v1);
            } else {
                write_kv_pair(mrow,     n, v0);
                write_kv_pair(mrow + 8, n, v1);
            }
        }
    }
}

// ================= HMMA flash attention (double-buffered cp.async K/V) =================
#define AQ   128
#define SQ3  200   // Q/K smem row stride (bf16)
#define SV   72    // V/P smem row stride (bf16)
// smem (bf16 elem offsets):
//   K3s[2]: 0, 12800   Vhi[2]: 25600, 30208   Vlo[2]: 34816, 39424
//   Phi: 44032   Plo: 53248   Q3s: 62464..88064
#define FA_SMEM_BYTES (88064 * 2)

__global__ void __launch_bounds__(256) flash_attn_mma_kernel(
    const __nv_bfloat16* __restrict__ q3, const __nv_bfloat16* __restrict__ k3,
    const __nv_bfloat16* __restrict__ v2, __nv_bfloat16* __restrict__ out3k)
{
    extern __shared__ __nv_bfloat16 smem_bf[];
    __nv_bfloat16* Phi = smem_bf + 44032;
    __nv_bfloat16* Plo = smem_bf + 53248;
    __nv_bfloat16* Q3s = smem_bf + 62464;

    const int b = blockIdx.z, h = blockIdx.y, qt = blockIdx.x;
    const int tid = threadIdx.x, lane = tid & 31, wid = tid >> 5;
    const int gr = lane >> 2, gc = (lane & 3) * 2;

    const uint32_t smem_u = smem_to_u32(smem_bf);
    const uint32_t k3s_u = smem_u;
    const uint32_t vhi_u = smem_u + 25600 * 2;
    const uint32_t vlo_u = smem_u + 34816 * 2;
    const uint32_t phi_u = smem_u + 44032 * 2;
    const uint32_t plo_u = smem_u + 53248 * 2;
    const uint32_t q3s_u = smem_u + 62464 * 2;

    // ---- load Q tile [128][192] ----
    const __nv_bfloat16* qg = q3 + ((size_t)((b * H_ + h) * LQ_ + qt * AQ)) * 192;
    for (int idx = tid; idx < AQ * 24; idx += 256) {
        int r = idx / 24, u = idx % 24;
        *(uint4*)&Q3s[r * SQ3 + u * 8] = *(const uint4*)(qg + (size_t)r * 192 + u * 8);
    }
    __syncthreads();

    // ---- preload Q a-frags (12 k16-steps) ----
    uint32_t qfrag[12][4];
    const uint32_t a_base = q3s_u + (uint32_t)((wid * 16 + (lane & 15)) * SQ3 * 2
                                               + (lane >> 4) * 16);
    #pragma unroll
    for (int ks = 0; ks < 12; ks++)
        ldmatrix_x4(qfrag[ks], a_base + (uint32_t)(ks * 32));

    const uint32_t kb_off = (uint32_t)((((lane >> 4) & 1) * 8 + (lane & 7)) * SQ3 * 2
                                       + ((lane >> 3) & 1) * 16);
    const uint32_t vb_off = (uint32_t)(((lane & 7) + ((lane >> 3) & 1) * 8) * SV * 2
                                       + (lane >> 4) * 16);
    const uint32_t pa_off = (uint32_t)((wid * 16 + (lane & 15)) * SV * 2
                                       + (lane >> 4) * 16);

    const int len   = g_len[b];
    const int ntile = (len + 63) >> 6;

    const __nv_bfloat16* kbase = k3 + ((size_t)((b * H_ + h) * LKV_)) * 192;
    const __nv_bfloat16* vbase = v2 + ((size_t)((b * H_ + h) * LKV_)) * 128;

    // K/V tile async-copy issuer
    auto issue_tile = [&](int kt, int buf) {
        const __nv_bfloat16* kg = kbase + (size_t)(kt * 64) * 192;
        const uint32_t kdst = k3s_u + (uint32_t)(buf * 12800 * 2);
        #pragma unroll
        for (int rep = 0; rep < 6; rep++) {
            int idx = rep * 256 + tid;
            int r = idx / 24, u = idx % 24;
            cp_async16(kdst + (uint32_t)((r * SQ3 + u * 8) * 2),
                       kg + (size_t)r * 192 + u * 8);
        }
        const __nv_bfloat16* vg = vbase + (size_t)(kt * 64) * 128;
        #pragma unroll
        for (int rep = 0; rep < 4; rep++) {
            int idx = rep * 256 + tid;
            int r = idx / 16, u = idx % 16;
            uint32_t dst = (u < 8)
                ? vhi_u + (uint32_t)(buf * 4608 * 2) + (uint32_t)((r * SV + u * 8) * 2)
                : vlo_u + (uint32_t)(buf * 4608 * 2) + (uint32_t)((r * SV + (u - 8) * 8) * 2);
            cp_async16(dst, vg + (size_t)r * 128 + u * 8);
        }
    };

    float m_r[2] = {-1e30f, -1e30f};
    float l_r[2] = {0.0f, 0.0f};
    float acc_o[8][4];
    #pragma unroll
    for (int i = 0; i < 8; i++)
        #pragma unroll
        for (int j = 0; j < 4; j++) acc_o[i][j] = 0.0f;

    // prologue: tile 0 -> buf 0
    issue_tile(0, 0);
    CP_ASYNC_COMMIT();

    for (int kt = 0; kt < ntile; kt++) {
        const int buf = kt & 1;
        if (kt + 1 < ntile) issue_tile(kt + 1, buf ^ 1);
        CP_ASYNC_COMMIT();
        CP_ASYNC_WAIT(1);
        __syncthreads();

        const uint32_t kcur  = k3s_u + (uint32_t)(buf * 12800 * 2);
        const uint32_t vhcur = vhi_u + (uint32_t)(buf * 4608 * 2);
        const uint32_t vlcur = vlo_u + (uint32_t)(buf * 4608 * 2);

        // ---- S = Q' @ K'^T (12 k16-steps) ----
        float acc_s[8][4];
        #pragma unroll
        for (int i = 0; i < 8; i++)
            #pragma unroll
            for (int j = 0; j < 4; j++) acc_s[i][j] = 0.0f;

        #pragma unroll
        for (int ks = 0; ks < 12; ks++) {
            uint32_t bf[4][4];
            #pragma unroll
            for (int nt4 = 0; nt4 < 4; nt4++)
                ldmatrix_x4(bf[nt4], kcur + kb_off
                            + (uint32_t)(nt4 * 16 * SQ3 * 2 + ks * 32));
            #pragma unroll
            for (int nt4 = 0; nt4 < 4; nt4++) {
                mma_16816(acc_s[nt4 * 2 + 0], qfrag[ks], bf[nt4][0], bf[nt4][1]);
                mma_16816(acc_s[nt4 * 2 + 1], qfrag[ks], bf[nt4][2], bf[nt4][3]);
            }
        }

        // ---- scale + mask ----
        const int rem = len - kt * 64;
        #pragma unroll
        for (int nt = 0; nt < 8; nt++) {
            int c0 = nt * 8 + gc;
            bool k0 = (c0 >= rem), k1 = (c0 + 1 >= rem);
            acc_s[nt][0] = k0 ? -1e9f : acc_s[nt][0] * 0.125f;
            acc_s[nt][1] = k1 ? -1e9f : acc_s[nt][1] * 0.125f;
            acc_s[nt][2] = k0 ? -1e9f : acc_s[nt][2] * 0.125f;
            acc_s[nt][3] = k1 ? -1e9f : acc_s[nt][3] * 0.125f;
        }

        // ---- online softmax ----
        float tmax0 = -1e30f, tmax1 = -1e30f;
        #pragma unroll
        for (int nt = 0; nt < 8; nt++) {
            tmax0 = fmaxf(tmax0, fmaxf(acc_s[nt][0], acc_s[nt][1]));
            tmax1 = fmaxf(tmax1, fmaxf(acc_s[nt][2], acc_s[nt][3]));
        }
        #pragma unroll
        for (int o = 1; o < 4; o <<= 1) {
            tmax0 = fmaxf(tmax0, __shfl_xor_sync(0xffffffffu, tmax0, o));
            tmax1 = fmaxf(tmax1, __shfl_xor_sync(0xffffffffu, tmax1, o));
        }
        float mn0 = fmaxf(m_r[0], tmax0), mn1 = fmaxf(m_r[1], tmax1);
        float al0 = __expf(m_r[0] - mn0), al1 = __expf(m_r[1] - mn1);
        float rs0 = 0.0f, rs1 = 0.0f;
        #pragma unroll
        for (int nt = 0; nt < 8; nt++) {
            acc_s[nt][0] = __expf(acc_s[nt][0] - mn0);
            acc_s[nt][1] = __expf(acc_s[nt][1] - mn0);
            acc_s[nt][2] = __expf(acc_s[nt][2] - mn1);
            acc_s[nt][3] = __expf(acc_s[nt][3] - mn1);
            rs0 += acc_s[nt][0] + acc_s[nt][1];
            rs1 += acc_s[nt][2] + acc_s[nt][3];
        }
        #pragma unroll
        for (int o = 1; o < 4; o <<= 1) {
            rs0 += __shfl_xor_sync(0xffffffffu, rs0, o);
            rs1 += __shfl_xor_sync(0xffffffffu, rs1, o);
        }
        l_r[0] = l_r[0] * al0 + rs0;  m_r[0] = mn0;
        l_r[1] = l_r[1] * al1 + rs1;  m_r[1] = mn1;
        #pragma unroll
        for (int nt = 0; nt < 8; nt++) {
            acc_o[nt][0] *= al0; acc_o[nt][1] *= al0;
            acc_o[nt][2] *= al1; acc_o[nt][3] *= al1;
        }

        // ---- P -> smem split (warp-private rows) ----
        const int pr0 = wid * 16 + gr, pr1 = pr0 + 8;
        #pragma unroll
        for (int nt = 0; nt < 8; nt++) {
            int c0 = nt * 8 + gc;
            __nv_bfloat16 h0 = __float2bfloat16(acc_s[nt][0]);
            __nv_bfloat16 h1 = __float2bfloat16(acc_s[nt][1]);
            __nv_bfloat16 h2 = __float2bfloat16(acc_s[nt][2]);
            __nv_bfloat16 h3 = __float2bfloat16(acc_s[nt][3]);
            *(__nv_bfloat162*)&Phi[pr0 * SV + c0] = __nv_bfloat162(h0, h1);
            *(__nv_bfloat162*)&Phi[pr1 * SV + c0] = __nv_bfloat162(h2, h3);
            __nv_bfloat16 l0 = __float2bfloat16(acc_s[nt][0] - __bfloat162float(h0));
            __nv_bfloat16 l1 = __float2bfloat16(acc_s[nt][1] - __bfloat162float(h1));
            __nv_bfloat16 l2 = __float2bfloat16(acc_s[nt][2] - __bfloat162float(h2));
            __nv_bfloat16 l3 = __float2bfloat16(acc_s[nt][3] - __bfloat162float(h3));
            *(__nv_bfloat162*)&Plo[pr0 * SV + c0] = __nv_bfloat162(l0, l1);
            *(__nv_bfloat162*)&Plo[pr1 * SV + c0] = __nv_bfloat162(l2, l3);
        }
        __syncwarp();

        // ---- O += P @ V  (3 split terms x 4 k16-steps) ----
        #pragma unroll
        for (int t = 0; t < 3; t++) {
            const uint32_t pa_u = ((t == 1) ? plo_u : phi_u) + pa_off;
            const uint32_t vb_u = ((t == 2) ? vlcur : vhcur) + vb_off;
            #pragma unroll
            for (int ks4 = 0; ks4 < 4; ks4++) {
                uint32_t af[4];
                ldmatrix_x4(af, pa_u + (uint32_t)(ks4 * 32));
                uint32_t bf[4][4];
                #pragma unroll
                for (int g = 0; g < 4; g++)
                    ldmatrix_x4_trans(bf[g], vb_u
                                      + (uint32_t)(ks4 * 16 * SV * 2 + g * 32));
                #pragma unroll
                for (int g = 0; g < 4; g++) {
                    mma_16816(acc_o[g * 2 + 0], af, bf[g][0], bf[g][1]);
                    mma_16816(acc_o[g * 2 + 1], af, bf[g][2], bf[g][3]);
                }
            }
        }
        __syncthreads();   // WAR: protect buf before next iteration's issue
    }

    // ---- epilogue: normalize + write split [hi,lo,hi] rows to at3k ----
    float inv0 = 1.0f / l_r[0], inv1 = 1.0f / l_r[1];
    const int qrow0 = qt * AQ + wid * 16 + gr;
    const size_t row0 = ((size_t)(b * LQ_ + qrow0)) * K3_;
    const size_t row1 = row0 + (size_t)8 * K3_;
    #pragma unroll
    for (int nt = 0; nt < 8; nt++) {
        int col = h * HD_ + nt * 8 + gc;
        float v00 = acc_o[nt][0] * inv0, v01 = acc_o[nt][1] * inv0;
        float v10 = acc_o[nt][2] * inv1, v11 = acc_o[nt][3] * inv1;
        __nv_bfloat16 a0 = __float2bfloat16(v00), a1 = __float2bfloat16(v01);
        __nv_bfloat16 b0 = __float2bfloat16(v10), b1 = __float2bfloat16(v11);
        __nv_bfloat16 c0 = __float2bfloat16(v00 - __bfloat162float(a0));
        __nv_bfloat16 c1 = __float2bfloat16(v01 - __bfloat162float(a1));
        __nv_bfloat16 d0 = __float2bfloat16(v10 - __bfloat162float(b0));
        __nv_bfloat16 d1 = __float2bfloat16(v11 - __bfloat162float(b1));
        __nv_bfloat16* p0 = out3k + row0 + col;
        __nv_bfloat16* p1 = out3k + row1 + col;
        *(__nv_bfloat162*)(p0)        = __nv_bfloat162(a0, a1);
        *(__nv_bfloat162*)(p0 + 1024) = __nv_bfloat162(c0, c1);
        *(__nv_bfloat162*)(p0 + 2048) = __nv_bfloat162(a0, a1);
        *(__nv_bfloat162*)(p1)        = __nv_bfloat162(b0, b1);
        *(__nv_bfloat162*)(p1 + 1024) = __nv_bfloat162(d0, d1);
        *(__nv_bfloat162*)(p1 + 2048) = __nv_bfloat162(b0, b1);
    }
}

// ================= host launcher =================
extern "C" void kernel_launch(void* const* d_in, const int* in_sizes, int n_in,
                              void* d_out, int out_size) {
    const float*         q    = (const float*)d_in[0];
    const float*         kv   = (const float*)d_in[1];
    const unsigned char* mask = (const unsigned char*)d_in[2];
    const float*         nqw  = (const float*)d_in[3];
    const float*         nqb  = (const float*)d_in[4];
    const float*         nkw  = (const float*)d_in[5];
    const float*         nkb  = (const float*)d_in[6];
    const float*         Wq   = (const float*)d_in[7];
    const float*         bq   = (const float*)d_in[8];
    const float*         Wkv  = (const float*)d_in[9];
    const float*         bkv  = (const float*)d_in[10];
    const float*         Wo   = (const float*)d_in[11];
    const float*         bo   = (const float*)d_in[12];
    float* out = (float*)d_out;

    __nv_bfloat16 *q3k, *kv3k, *at3k, *wq3k, *wkv3k, *wo3k, *q3, *k3, *v2;
    cudaGetSymbolAddress((void**)&q3k,   g_q3k);
    cudaGetSymbolAddress((void**)&kv3k,  g_kv3k);
    cudaGetSymbolAddress((void**)&at3k,  g_at3k);
    cudaGetSymbolAddress((void**)&wq3k,  g_wq3k);
    cudaGetSymbolAddress((void**)&wkv3k, g_wkv3k);
    cudaGetSymbolAddress((void**)&wo3k,  g_wo3k);
    cudaGetSymbolAddress((void**)&q3,    g_q3);
    cudaGetSymbolAddress((void**)&k3,    g_k3);
    cudaGetSymbolAddress((void**)&v2,    g_v2);

    cudaFuncSetAttribute(flash_attn_mma_kernel,
                         cudaFuncAttributeMaxDynamicSharedMemorySize, FA_SMEM_BYTES);
    cudaFuncSetAttribute(gemm_bf16_mma_kernel,
                         cudaFuncAttributeMaxDynamicSharedMemorySize, GEMM_SMEM);

    // Launch order chosen so ncu (-s 5) captures the KV GEMM.
    compute_lengths_kernel<<<1, 256>>>(mask);                              // 0
    weight_split_kernel<<<(D_ * D_) / 1024,     256>>>(Wq,  wq3k);         // 1
    weight_split_kernel<<<(2 * D_ * D_) / 1024, 256>>>(Wkv, wkv3k);        // 2
    weight_split_kernel<<<(D_ * D_) / 1024,     256>>>(Wo,  wo3k);         // 3
    layernorm_split_kernel<<<B_ * LKV_, 256>>>(kv, nkw, nkb, kv3k);        // 4

    dim3 gkv((2 * D_) / 128, (B_ * LKV_) / 128);  // (16, 64)
    gemm_bf16_mma_kernel<<<gkv, 256, GEMM_SMEM>>>(kv3k, wkv3k, bkv, nullptr,
                                                  nullptr, B_ * LKV_, 2 * D_, 2); // 5

    layernorm_split_kernel<<<B_ * LQ_,  256>>>(q,  nqw, nqb, q3k);         // 6

    dim3 gq(D_ / 128, (B_ * LQ_) / 128);          // (8, 32)
    gemm_bf16_mma_kernel<<<gq, 256, GEMM_SMEM>>>(q3k, wq3k, bq, nullptr,
                                                 nullptr, B_ * LQ_, D_, 1);   // 7

    flash_attn_mma_kernel<<<dim3(LQ_ / AQ, H_, B_), 256, FA_SMEM_BYTES>>>(
        q3, k3, v2, at3k);                                                  // 8

    gemm_bf16_mma_kernel<<<gq, 256, GEMM_SMEM>>>(at3k, wo3k, bo, q, out,
                                                 B_ * LQ_, D_, 0);          // 9
}

// round 10
// speedup vs baseline: 5.3834x; 2.5211x over previous
#include <cuda_runtime.h>
#include <cuda_fp16.h>
#include <math.h>
#include <stdint.h>

// Problem dims
#define B_   4
#define LQ_  1024
#define LKV_ 2048
#define D_   1024
#define H_   16
#define HD_  64

// ================= warp-MMA helpers (baseline PTX, sm_80+) =================
__device__ __forceinline__ uint32_t smem_to_u32(const void* p) {
    uint32_t a;
    asm("{ .reg .u64 t; cvta.to.shared.u64 t, %1; cvt.u32.u64 %0, t; }"
        : "=r"(a) : "l"(p));
    return a;
}
__device__ __forceinline__ void ldmatrix_x4(uint32_t* r, uint32_t addr) {
    asm volatile("ldmatrix.sync.aligned.m8n8.x4.shared.b16 {%0,%1,%2,%3}, [%4];"
        : "=r"(r[0]), "=r"(r[1]), "=r"(r[2]), "=r"(r[3]) : "r"(addr));
}
__device__ __forceinline__ void ldmatrix_x4_trans(uint32_t* r, uint32_t addr) {
    asm volatile("ldmatrix.sync.aligned.m8n8.x4.trans.shared.b16 {%0,%1,%2,%3}, [%4];"
        : "=r"(r[0]), "=r"(r[1]), "=r"(r[2]), "=r"(r[3]) : "r"(addr));
}
__device__ __forceinline__ void mma_16816(float* d, const uint32_t* a,
                                          uint32_t b0, uint32_t b1) {
    asm volatile("mma.sync.aligned.m16n8k16.row.col.f32.f16.f16.f32 "
        "{%0,%1,%2,%3}, {%4,%5,%6,%7}, {%8,%9}, {%0,%1,%2,%3};"
        : "+f"(d[0]), "+f"(d[1]), "+f"(d[2]), "+f"(d[3])
        : "r"(a[0]), "r"(a[1]), "r"(a[2]), "r"(a[3]), "r"(b0), "r"(b1));
}
__device__ __forceinline__ void cp_async16(uint32_t smem_addr, const void* gptr) {
    asm volatile("cp.async.cg.shared.global [%0], [%1], 16;"
        :: "r"(smem_addr), "l"(gptr));
}
#define CP_ASYNC_COMMIT() asm volatile("cp.async.commit_group;" ::: "memory")
#define CP_ASYNC_WAIT(N)  asm volatile("cp.async.wait_group %0;" :: "n"(N) : "memory")

// ================= scratch =================
__device__ __half g_qk  [B_ * LQ_  * D_];        // LN(q)  fp16 (GEMM A)
__device__ __half g_kvk [B_ * LKV_ * D_];        // LN(kv) fp16 (GEMM A)
__device__ __half g_ak  [B_ * LQ_  * D_];        // attn out fp16 (GEMM A)
__device__ __half g_wq  [D_ * D_];
__device__ __half g_wkv [2 * D_ * D_];
__device__ __half g_wo  [D_ * D_];
__device__ __half g_q1 [B_ * H_ * LQ_  * HD_];   // Q per head
__device__ __half g_k1 [B_ * H_ * LKV_ * HD_];   // K per head
__device__ __half g_v1 [B_ * H_ * LKV_ * HD_];   // V per head
__device__ int g_len[B_];

// ================= mask lengths (dtype-sniffing) =================
__global__ void compute_lengths_kernel(const unsigned char* __restrict__ mask) {
    __shared__ int det[4];
    __shared__ int cnt[4];
    __shared__ int mode;
    int tid = threadIdx.x;
    if (tid < 4) { det[tid] = 0; cnt[tid] = 0; }
    __syncthreads();
    for (int i = tid; i < B_ * LKV_; i += blockDim.x)
        if (mask[i]) atomicOr(&det[i & 3], 1);
    __syncthreads();
    if (tid == 0) {
        if (det[1])                mode = 0;
        else if (det[2] || det[3]) mode = det[0] ? 0 : 2;
        else if (det[0])           mode = 1;
        else                       mode = 0;
    }
    __syncthreads();
    int md = mode;
    for (int b = 0; b < B_; b++) {
        int local = 0;
        for (int k = tid; k < LKV_; k += blockDim.x) {
            int idx = b * LKV_ + k;
            bool t;
            if      (md == 0) t = mask[idx] != 0;
            else if (md == 1) t = ((const int*)  mask)[idx] != 0;
            else              t = ((const float*)mask)[idx] != 0.0f;
            if (!t) local++;
        }
        atomicAdd(&cnt[b], local);
    }
    __syncthreads();
    if (tid < B_) g_len[tid] = cnt[tid];
}

// ================= layernorm -> fp16 =================
__global__ void __launch_bounds__(256) layernorm_fp16_kernel(
    const float* __restrict__ x, const float* __restrict__ w,
    const float* __restrict__ bb, __half* __restrict__ y)
{
    int row = blockIdx.x;
    int tid = threadIdx.x;
    const float* xr = x + (size_t)row * D_;
    float4 v = *(const float4*)(xr + tid * 4);
    float s  = v.x + v.y + v.z + v.w;
    float sq = v.x * v.x + v.y * v.y + v.z * v.z + v.w * v.w;
    #pragma unroll
    for (int o = 16; o; o >>= 1) {
        s  += __shfl_xor_sync(0xffffffffu, s,  o);
        sq += __shfl_xor_sync(0xffffffffu, sq, o);
    }
    __shared__ float ss[8], ssq[8];
    int wid = tid >> 5, ln = tid & 31;
    if (ln == 0) { ss[wid] = s; ssq[wid] = sq; }
    __syncthreads();
    if (tid == 0) {
        float S = 0.f, SQ = 0.f;
        #pragma unroll
        for (int i = 0; i < 8; i++) { S += ss[i]; SQ += ssq[i]; }
        float mu  = S * (1.0f / D_);
        float var = SQ * (1.0f / D_) - mu * mu;
        ss[0]  = mu;
        ssq[0] = rsqrtf(fmaxf(var, 0.0f) + 1e-5f);
    }
    __syncthreads();
    float mu = ss[0], inv = ssq[0];
    float4 wv = *(const float4*)(w  + tid * 4);
    float4 bv = *(const float4*)(bb + tid * 4);
    __half* yr = y + (size_t)row * D_ + tid * 4;
    *(__half2*)(yr)     = __floats2half2_rn((v.x - mu) * inv * wv.x + bv.x,
                                            (v.y - mu) * inv * wv.y + bv.y);
    *(__half2*)(yr + 2) = __floats2half2_rn((v.z - mu) * inv * wv.z + bv.z,
                                            (v.w - mu) * inv * wv.w + bv.w);
}

// ================= weight convert fp32 -> fp16 =================
__global__ void __launch_bounds__(256) weight_fp16_kernel(
    const float* __restrict__ W, __half* __restrict__ O)
{
    int idx4 = (blockIdx.x * 256 + threadIdx.x) * 4;
    float4 v = *(const float4*)(W + idx4);
    *(__half2*)(O + idx4)     = __floats2half2_rn(v.x, v.y);
    *(__half2*)(O + idx4 + 2) = __floats2half2_rn(v.z, v.w);
}

// ========== per-head write helpers for GEMM epilogues ==========
__device__ __forceinline__ void write_q_pair(int mrow, int n, float2 v) {
    int b = mrow >> 10, qr = mrow & 1023, h = n >> 6, d = n & 63;
    __half* dst = g_q1 + ((size_t)((b * H_ + h) * LQ_ + qr)) * HD_ + d;
    *(__half2*)dst = __floats2half2_rn(v.x, v.y);
}
__device__ __forceinline__ void write_kv_pair(int mrow, int n, float2 v) {
    int b = mrow >> 11, kr = mrow & 2047;
    int h2 = n >> 6, d = n & 63;
    __half* dst = (h2 < H_)
        ? g_k1 + ((size_t)((b * H_ + h2) * LKV_ + kr)) * HD_ + d
        : g_v1 + ((size_t)((b * H_ + (h2 - H_)) * LKV_ + kr)) * HD_ + d;
    *(__half2*)dst = __floats2half2_rn(v.x, v.y);
}

// ================= fp16 warp-MMA GEMM (4-stage cp.async pipeline) =================
// C = A[M,1024] @ W[N,1024]^T, 128x128 CTA tile, 8 warps 32x64, BK=32, NK=32.
// mode 0: fp32 C + bias + residual; mode 1: Q per-head; mode 2: KV per-head.
#define SSTRIDE 40                      // fp16 per smem row (80B)
#define GSTAGE_BYTES (128 * SSTRIDE * 2)
#define GSTAGES 4
#define GEMM_SMEM (2 * GSTAGES * GSTAGE_BYTES)  // 81920 B
#define NKG (D_ / 32)   // 32

__global__ void __launch_bounds__(256) gemm_fp16_mma_kernel(
    const __half* __restrict__ A, const __half* __restrict__ W,
    const float* __restrict__ bias, const float* __restrict__ R,
    float* __restrict__ C, int M, int N, int mode)
{
    extern __shared__ char gsm[];
    const uint32_t smem_u = smem_to_u32(gsm);
    const uint32_t sa_u = smem_u;
    const uint32_t sb_u = smem_u + GSTAGES * GSTAGE_BYTES;

    const int tid  = threadIdx.x;
    const int lane = tid & 31;
    const int wid  = tid >> 5;
    const int warp_m = wid & 3;
    const int warp_n = wid >> 2;
    const int m0 = blockIdx.y * 128, n0 = blockIdx.x * 128;

    const int lr = tid >> 2;            // 0..63
    const int lu = tid & 3;             // 16B unit
    const __half* ag = A + (size_t)(m0 + lr) * D_ + lu * 8;
    const __half* bg = W + (size_t)(n0 + lr) * D_ + lu * 8;
    const uint32_t row_b  = (uint32_t)(lr * SSTRIDE * 2 + lu * 16);
    const uint32_t row_b2 = row_b + (uint32_t)(64 * SSTRIDE * 2);

    float acc[2][8][4];
    #pragma unroll
    for (int i = 0; i < 2; i++)
        #pragma unroll
        for (int j = 0; j < 8; j++)
            #pragma unroll
            for (int t = 0; t < 4; t++) acc[i][j][t] = 0.0f;

    const uint32_t a_off = (uint32_t)((warp_m * 32 + (lane & 15)) * SSTRIDE * 2
                                      + (lane >> 4) * 16);
    const uint32_t b_off = (uint32_t)((warp_n * 64 + ((lane >> 4) & 1) * 8 + (lane & 7)) * SSTRIDE * 2
                                      + ((lane >> 3) & 1) * 16);

    // prologue: stages 0..2
    #pragma unroll
    for (int s = 0; s < 3; s++) {
        const size_t koff = (size_t)s * 32;
        const uint32_t sa_s = sa_u + (uint32_t)(s * GSTAGE_BYTES);
        const uint32_t sb_s = sb_u + (uint32_t)(s * GSTAGE_BYTES);
        cp_async16(sa_s + row_b,  ag + koff);
        cp_async16(sa_s + row_b2, ag + (size_t)64 * D_ + koff);
        cp_async16(sb_s + row_b,  bg + koff);
        cp_async16(sb_s + row_b2, bg + (size_t)64 * D_ + koff);
        CP_ASYNC_COMMIT();
    }

    for (int kt = 0; kt < NKG; kt++) {
        CP_ASYNC_WAIT(2);
        __syncthreads();
        if (kt + 3 < NKG) {
            const int s = (kt + 3) & 3;
            const size_t koff = (size_t)(kt + 3) * 32;
            const uint32_t sa_s = sa_u + (uint32_t)(s * GSTAGE_BYTES);
            const uint32_t sb_s = sb_u + (uint32_t)(s * GSTAGE_BYTES);
            cp_async16(sa_s + row_b,  ag + koff);
            cp_async16(sa_s + row_b2, ag + (size_t)64 * D_ + koff);
            cp_async16(sb_s + row_b,  bg + koff);
            cp_async16(sb_s + row_b2, bg + (size_t)64 * D_ + koff);
        }
        CP_ASYNC_COMMIT();

        const int cur = kt & 3;
        const uint32_t sa_cur = sa_u + (uint32_t)(cur * GSTAGE_BYTES);
        const uint32_t sb_cur = sb_u + (uint32_t)(cur * GSTAGE_BYTES);
        #pragma unroll
        for (int ks = 0; ks < 2; ks++) {
            uint32_t a_frag[2][4];
            #pragma unroll
            for (int im = 0; im < 2; im++)
                ldmatrix_x4(a_frag[im], sa_cur + a_off
                            + (uint32_t)(im * 16 * SSTRIDE * 2 + ks * 32));
            uint32_t b_frag[4][4];
            #pragma unroll
            for (int iu = 0; iu < 4; iu++)
                ldmatrix_x4(b_frag[iu], sb_cur + b_off
                            + (uint32_t)(iu * 16 * SSTRIDE * 2 + ks * 32));
            #pragma unroll
            for (int im = 0; im < 2; im++)
                #pragma unroll
                for (int iu = 0; iu < 4; iu++) {
                    mma_16816(acc[im][iu * 2 + 0], a_frag[im], b_frag[iu][0], b_frag[iu][1]);
                    mma_16816(acc[im][iu * 2 + 1], a_frag[im], b_frag[iu][2], b_frag[iu][3]);
                }
        }
    }

    const int gr = lane >> 2;
    const int gc = (lane & 3) * 2;
    #pragma unroll
    for (int im = 0; im < 2; im++) {
        const int mrow = m0 + warp_m * 32 + im * 16 + gr;
        #pragma unroll
        for (int in = 0; in < 8; in++) {
            const int n = n0 + warp_n * 64 + in * 8 + gc;
            float b0 = bias[n], b1 = bias[n + 1];
            float2 v0 = make_float2(acc[im][in][0] + b0, acc[im][in][1] + b1);
            float2 v1 = make_float2(acc[im][in][2] + b0, acc[im][in][3] + b1);
            if (mode == 0) {
                if (R) {
                    float2 r0 = *(const float2*)(R + (size_t)mrow * N + n);
                    float2 r1 = *(const float2*)(R + (size_t)(mrow + 8) * N + n);
                    v0.x += r0.x; v0.y += r0.y;
                    v1.x += r1.x; v1.y += r1.y;
                }
                *(float2*)(C + (size_t)mrow * N + n)       = v0;
                *(float2*)(C + (size_t)(mrow + 8) * N + n) = v1;
            } else if (mode == 1) {
                write_q_pair(mrow,     n, v0);
                write_q_pair(mrow + 8, n, v1);
            } else {
                write_kv_pair(mrow,     n, v0);
                write_kv_pair(mrow + 8, n, v1);
            }
        }
    }
}

// ================= fp16 HMMA flash attention (double-buffered cp.async K/V) =================
#define AQ  128
#define SQ  72     // smem row stride in fp16 (144B)
// smem layout (fp16 elem offsets):
//   Ks[2]: 0, 4608   Vs[2]: 9216, 13824   Ps: 18432   Qs: 27648..36864
#define KTILE 4608             // 64 * SQ
#define FA_SMEM_BYTES (36864 * 2)

__global__ void __launch_bounds__(256) flash_attn_mma_kernel(
    const __half* __restrict__ q1, const __half* __restrict__ k1,
    const __half* __restrict__ v1, __half* __restrict__ outk)
{
    extern __shared__ __half smem_h[];
    __half* Ps = smem_h + 18432;
    __half* Qs = smem_h + 27648;

    const int b = blockIdx.z, h = blockIdx.y, qt = blockIdx.x;
    const int tid = threadIdx.x, lane = tid & 31, wid = tid >> 5;
    const int gr = lane >> 2, gc = (lane & 3) * 2;

    const uint32_t smem_u = smem_to_u32(smem_h);
    const uint32_t ks_u = smem_u;
    const uint32_t vs_u = smem_u + 9216 * 2;
    const uint32_t ps_u = smem_u + 18432 * 2;
    const uint32_t qs_u = smem_u + 27648 * 2;

    // ---- load Q tile [128][64] ----
    const __half* qg = q1 + ((size_t)((b * H_ + h) * LQ_ + qt * AQ)) * HD_;
    #pragma unroll
    for (int rep = 0; rep < 4; rep++) {
        int idx = rep * 256 + tid;
        int r = idx >> 3, u = idx & 7;
        *(uint4*)&Qs[r * SQ + u * 8] = *(const uint4*)(qg + (size_t)r * HD_ + u * 8);
    }
    __syncthreads();

    // ---- preload Q a-frags (4 k16-steps) ----
    uint32_t qfrag[4][4];
    const uint32_t a_base = qs_u + (uint32_t)((wid * 16 + (lane & 15)) * SQ * 2
                                              + (lane >> 4) * 16);
    #pragma unroll
    for (int ks = 0; ks < 4; ks++)
        ldmatrix_x4(qfrag[ks], a_base + (uint32_t)(ks * 32));

    const uint32_t kb_off = (uint32_t)((((lane >> 4) & 1) * 8 + (lane & 7)) * SQ * 2
                                       + ((lane >> 3) & 1) * 16);
    const uint32_t vb_off = (uint32_t)(((lane & 7) + ((lane >> 3) & 1) * 8) * SQ * 2
                                       + (lane >> 4) * 16);
    const uint32_t pa_off = (uint32_t)((wid * 16 + (lane & 15)) * SQ * 2
                                       + (lane >> 4) * 16);

    const int len   = g_len[b];
    const int ntile = (len + 63) >> 6;

    const __half* kbase = k1 + ((size_t)((b * H_ + h) * LKV_)) * HD_;
    const __half* vbase = v1 + ((size_t)((b * H_ + h) * LKV_)) * HD_;

    auto issue_tile = [&](int kt, int buf) {
        const __half* kg = kbase + (size_t)(kt * 64) * HD_;
        const __half* vg = vbase + (size_t)(kt * 64) * HD_;
        const uint32_t kdst = ks_u + (uint32_t)(buf * KTILE * 2);
        const uint32_t vdst = vs_u + (uint32_t)(buf * KTILE * 2);
        #pragma unroll
        for (int rep = 0; rep < 2; rep++) {
            int idx = rep * 256 + tid;
            int r = idx >> 3, u = idx & 7;
            uint32_t off = (uint32_t)((r * SQ + u * 8) * 2);
            cp_async16(kdst + off, kg + (size_t)r * HD_ + u * 8);
            cp_async16(vdst + off, vg + (size_t)r * HD_ + u * 8);
        }
    };

    float m_r[2] = {-1e30f, -1e30f};
    float l_r[2] = {0.0f, 0.0f};
    float acc_o[8][4];
    #pragma unroll
    for (int i = 0; i < 8; i++)
        #pragma unroll
        for (int j = 0; j < 4; j++) acc_o[i][j] = 0.0f;

    issue_tile(0, 0);
    CP_ASYNC_COMMIT();

    for (int kt = 0; kt < ntile; kt++) {
        const int buf = kt & 1;
        if (kt + 1 < ntile) issue_tile(kt + 1, buf ^ 1);
        CP_ASYNC_COMMIT();
        CP_ASYNC_WAIT(1);
        __syncthreads();

        const uint32_t kcur = ks_u + (uint32_t)(buf * KTILE * 2);
        const uint32_t vcur = vs_u + (uint32_t)(buf * KTILE * 2);

        // ---- S = Q @ K^T (4 k16-steps) ----
        float acc_s[8][4];
        #pragma unroll
        for (int i = 0; i < 8; i++)
            #pragma unroll
            for (int j = 0; j < 4; j++) acc_s[i][j] = 0.0f;

        #pragma unroll
        for (int ks = 0; ks < 4; ks++) {
            uint32_t bf[4][4];
            #pragma unroll
            for (int nt4 = 0; nt4 < 4; nt4++)
                ldmatrix_x4(bf[nt4], kcur + kb_off
                            + (uint32_t)(nt4 * 16 * SQ * 2 + ks * 32));
            #pragma unroll
            for (int nt4 = 0; nt4 < 4; nt4++) {
                mma_16816(acc_s[nt4 * 2 + 0], qfrag[ks], bf[nt4][0], bf[nt4][1]);
                mma_16816(acc_s[nt4 * 2 + 1], qfrag[ks], bf[nt4][2], bf[nt4][3]);
            }
        }

        // ---- scale + mask ----
        const int rem = len - kt * 64;
        #pragma unroll
        for (int nt = 0; nt < 8; nt++) {
            int c0 = nt * 8 + gc;
            bool k0 = (c0 >= rem), k1m = (c0 + 1 >= rem);
            acc_s[nt][0] = k0  ? -1e9f : acc_s[nt][0] * 0.125f;
            acc_s[nt][1] = k1m ? -1e9f : acc_s[nt][1] * 0.125f;
            acc_s[nt][2] = k0  ? -1e9f : acc_s[nt][2] * 0.125f;
            acc_s[nt][3] = k1m ? -1e9f : acc_s[nt][3] * 0.125f;
        }

        // ---- online softmax ----
        float tmax0 = -1e30f, tmax1 = -1e30f;
        #pragma unroll
        for (int nt = 0; nt < 8; nt++) {
            tmax0 = fmaxf(tmax0, fmaxf(acc_s[nt][0], acc_s[nt][1]));
            tmax1 = fmaxf(tmax1, fmaxf(acc_s[nt][2], acc_s[nt][3]));
        }
        #pragma unroll
        for (int o = 1; o < 4; o <<= 1) {
            tmax0 = fmaxf(tmax0, __shfl_xor_sync(0xffffffffu, tmax0, o));
            tmax1 = fmaxf(tmax1, __shfl_xor_sync(0xffffffffu, tmax1, o));
        }
        float mn0 = fmaxf(m_r[0], tmax0), mn1 = fmaxf(m_r[1], tmax1);
        float al0 = __expf(m_r[0] - mn0), al1 = __expf(m_r[1] - mn1);
        float rs0 = 0.0f, rs1 = 0.0f;
        #pragma unroll
        for (int nt = 0; nt < 8; nt++) {
            acc_s[nt][0] = __expf(acc_s[nt][0] - mn0);
            acc_s[nt][1] = __expf(acc_s[nt][1] - mn0);
            acc_s[nt][2] = __expf(acc_s[nt][2] - mn1);
            acc_s[nt][3] = __expf(acc_s[nt][3] - mn1);
            rs0 += acc_s[nt][0] + acc_s[nt][1];
            rs1 += acc_s[nt][2] + acc_s[nt][3];
        }
        #pragma unroll
        for (int o = 1; o < 4; o <<= 1) {
            rs0 += __shfl_xor_sync(0xffffffffu, rs0, o);
            rs1 += __shfl_xor_sync(0xffffffffu, rs1, o);
        }
        l_r[0] = l_r[0] * al0 + rs0;  m_r[0] = mn0;
        l_r[1] = l_r[1] * al1 + rs1;  m_r[1] = mn1;
        #pragma unroll
        for (int nt = 0; nt < 8; nt++) {
            acc_o[nt][0] *= al0; acc_o[nt][1] *= al0;
            acc_o[nt][2] *= al1; acc_o[nt][3] *= al1;
        }

        // ---- P -> smem fp16 (warp-private rows) ----
        const int pr0 = wid * 16 + gr, pr1 = pr0 + 8;
        #pragma unroll
        for (int nt = 0; nt < 8; nt++) {
            int c0 = nt * 8 + gc;
            *(__half2*)&Ps[pr0 * SQ + c0] = __floats2half2_rn(acc_s[nt][0], acc_s[nt][1]);
            *(__half2*)&Ps[pr1 * SQ + c0] = __floats2half2_rn(acc_s[nt][2], acc_s[nt][3]);
        }
        __syncwarp();

        // ---- O += P @ V (4 k16-steps) ----
        #pragma unroll
        for (int ks4 = 0; ks4 < 4; ks4++) {
            uint32_t af[4];
            ldmatrix_x4(af, ps_u + pa_off + (uint32_t)(ks4 * 32));
            uint32_t bf[4][4];
            #pragma unroll
            for (int g = 0; g < 4; g++)
                ldmatrix_x4_trans(bf[g], vcur + vb_off
                                  + (uint32_t)(ks4 * 16 * SQ * 2 + g * 32));
            #pragma unroll
            for (int g = 0; g < 4; g++) {
                mma_16816(acc_o[g * 2 + 0], af, bf[g][0], bf[g][1]);
                mma_16816(acc_o[g * 2 + 1], af, bf[g][2], bf[g][3]);
            }
        }
        __syncthreads();   // WAR: protect buf before next iteration's issue
    }

    // ---- epilogue: normalize + write fp16 rows [M, 1024] ----
    float inv0 = 1.0f / l_r[0], inv1 = 1.0f / l_r[1];
    const int qrow0 = qt * AQ + wid * 16 + gr;
    __half* p0 = outk + ((size_t)(b * LQ_ + qrow0)) * D_ + h * HD_;
    __half* p1 = p0 + (size_t)8 * D_;
    #pragma unroll
    for (int nt = 0; nt < 8; nt++) {
        int col = nt * 8 + gc;
        *(__half2*)(p0 + col) = __floats2half2_rn(acc_o[nt][0] * inv0,
                                                  acc_o[nt][1] * inv0);
        *(__half2*)(p1 + col) = __floats2half2_rn(acc_o[nt][2] * inv1,
                                                  acc_o[nt][3] * inv1);
    }
}

// ================= host launcher =================
extern "C" void kernel_launch(void* const* d_in, const int* in_sizes, int n_in,
                              void* d_out, int out_size) {
    const float*         q    = (const float*)d_in[0];
    const float*         kv   = (const float*)d_in[1];
    const unsigned char* mask = (const unsigned char*)d_in[2];
    const float*         nqw  = (const float*)d_in[3];
    const float*         nqb  = (const float*)d_in[4];
    const float*         nkw  = (const float*)d_in[5];
    const float*         nkb  = (const float*)d_in[6];
    const float*         Wq   = (const float*)d_in[7];
    const float*         bq   = (const float*)d_in[8];
    const float*         Wkv  = (const float*)d_in[9];
    const float*         bkv  = (const float*)d_in[10];
    const float*         Wo   = (const float*)d_in[11];
    const float*         bo   = (const float*)d_in[12];
    float* out = (float*)d_out;

    __half *qk, *kvk, *ak, *wq, *wkv, *wo, *q1, *k1, *v1;
    cudaGetSymbolAddress((void**)&qk,  g_qk);
    cudaGetSymbolAddress((void**)&kvk, g_kvk);
    cudaGetSymbolAddress((void**)&ak,  g_ak);
    cudaGetSymbolAddress((void**)&wq,  g_wq);
    cudaGetSymbolAddress((void**)&wkv, g_wkv);
    cudaGetSymbolAddress((void**)&wo,  g_wo);
    cudaGetSymbolAddress((void**)&q1,  g_q1);
    cudaGetSymbolAddress((void**)&k1,  g_k1);
    cudaGetSymbolAddress((void**)&v1,  g_v1);

    cudaFuncSetAttribute(flash_attn_mma_kernel,
                         cudaFuncAttributeMaxDynamicSharedMemorySize, FA_SMEM_BYTES);
    cudaFuncSetAttribute(gemm_fp16_mma_kernel,
                         cudaFuncAttributeMaxDynamicSharedMemorySize, GEMM_SMEM);

    // Launch order chosen so ncu (-s 5) captures the KV GEMM.
    compute_lengths_kernel<<<1, 256>>>(mask);                              // 0
    weight_fp16_kernel<<<(D_ * D_) / 1024,     256>>>(Wq,  wq);            // 1
    weight_fp16_kernel<<<(2 * D_ * D_) / 1024, 256>>>(Wkv, wkv);           // 2
    weight_fp16_kernel<<<(D_ * D_) / 1024,     256>>>(Wo,  wo);            // 3
    layernorm_fp16_kernel<<<B_ * LKV_, 256>>>(kv, nkw, nkb, kvk);          // 4

    dim3 gkv((2 * D_) / 128, (B_ * LKV_) / 128);  // (16, 64)
    gemm_fp16_mma_kernel<<<gkv, 256, GEMM_SMEM>>>(kvk, wkv, bkv, nullptr,
                                                  nullptr, B_ * LKV_, 2 * D_, 2); // 5

    layernorm_fp16_kernel<<<B_ * LQ_,  256>>>(q,  nqw, nqb, qk);           // 6

    dim3 gq(D_ / 128, (B_ * LQ_) / 128);          // (8, 32)
    gemm_fp16_mma_kernel<<<gq, 256, GEMM_SMEM>>>(qk, wq, bq, nullptr,
                                                 nullptr, B_ * LQ_, D_, 1);   // 7

    flash_attn_mma_kernel<<<dim3(LQ_ / AQ, H_, B_), 256, FA_SMEM_BYTES>>>(
        q1, k1, v1, ak);                                                    // 8

    gemm_fp16_mma_kernel<<<gq, 256, GEMM_SMEM>>>(ak, wo, bo, q, out,
                                                 B_ * LQ_, D_, 0);          // 9
}

// round 11
// speedup vs baseline: 6.1618x; 1.1446x over previous
#include <cuda_runtime.h>
#include <cuda_fp16.h>
#include <math.h>
#include <stdint.h>

// Problem dims
#define B_   4
#define LQ_  1024
#define LKV_ 2048
#define D_   1024
#define H_   16
#define HD_  64

// ================= warp-MMA helpers (baseline PTX, sm_80+) =================
__device__ __forceinline__ uint32_t smem_to_u32(const void* p) {
    uint32_t a;
    asm("{ .reg .u64 t; cvta.to.shared.u64 t, %1; cvt.u32.u64 %0, t; }"
        : "=r"(a) : "l"(p));
    return a;
}
__device__ __forceinline__ void ldmatrix_x4(uint32_t* r, uint32_t addr) {
    asm volatile("ldmatrix.sync.aligned.m8n8.x4.shared.b16 {%0,%1,%2,%3}, [%4];"
        : "=r"(r[0]), "=r"(r[1]), "=r"(r[2]), "=r"(r[3]) : "r"(addr));
}
__device__ __forceinline__ void ldmatrix_x4_trans(uint32_t* r, uint32_t addr) {
    asm volatile("ldmatrix.sync.aligned.m8n8.x4.trans.shared.b16 {%0,%1,%2,%3}, [%4];"
        : "=r"(r[0]), "=r"(r[1]), "=r"(r[2]), "=r"(r[3]) : "r"(addr));
}
__device__ __forceinline__ void mma_16816(float* d, const uint32_t* a,
                                          uint32_t b0, uint32_t b1) {
    asm volatile("mma.sync.aligned.m16n8k16.row.col.f32.f16.f16.f32 "
        "{%0,%1,%2,%3}, {%4,%5,%6,%7}, {%8,%9}, {%0,%1,%2,%3};"
        : "+f"(d[0]), "+f"(d[1]), "+f"(d[2]), "+f"(d[3])
        : "r"(a[0]), "r"(a[1]), "r"(a[2]), "r"(a[3]), "r"(b0), "r"(b1));
}
__device__ __forceinline__ void cp_async16(uint32_t smem_addr, const void* gptr) {
    asm volatile("cp.async.cg.shared.global [%0], [%1], 16;"
        :: "r"(smem_addr), "l"(gptr));
}
#define CP_ASYNC_COMMIT() asm volatile("cp.async.commit_group;" ::: "memory")
#define CP_ASYNC_WAIT(N)  asm volatile("cp.async.wait_group %0;" :: "n"(N) : "memory")

// ================= scratch =================
__device__ __half g_qk  [B_ * LQ_  * D_];        // LN(q)  fp16 (GEMM A)
__device__ __half g_kvk [B_ * LKV_ * D_];        // LN(kv) fp16 (GEMM A)
__device__ __half g_ak  [B_ * LQ_  * D_];        // attn out fp16 (GEMM A)
__device__ __half g_wq  [D_ * D_];
__device__ __half g_wkv [2 * D_ * D_];
__device__ __half g_wo  [D_ * D_];
__device__ __half g_q1 [B_ * H_ * LQ_  * HD_];   // Q per head
__device__ __half g_k1 [B_ * H_ * LKV_ * HD_];   // K per head
__device__ __half g_v1 [B_ * H_ * LKV_ * HD_];   // V per head
__device__ int g_len[B_];

// ================= mask lengths (dtype-sniffing) =================
__global__ void compute_lengths_kernel(const unsigned char* __restrict__ mask) {
    __shared__ int det[4];
    __shared__ int cnt[4];
    __shared__ int mode;
    int tid = threadIdx.x;
    if (tid < 4) { det[tid] = 0; cnt[tid] = 0; }
    __syncthreads();
    for (int i = tid; i < B_ * LKV_; i += blockDim.x)
        if (mask[i]) atomicOr(&det[i & 3], 1);
    __syncthreads();
    if (tid == 0) {
        if (det[1])                mode = 0;
        else if (det[2] || det[3]) mode = det[0] ? 0 : 2;
        else if (det[0])           mode = 1;
        else                       mode = 0;
    }
    __syncthreads();
    int md = mode;
    for (int b = 0; b < B_; b++) {
        int local = 0;
        for (int k = tid; k < LKV_; k += blockDim.x) {
            int idx = b * LKV_ + k;
            bool t;
            if      (md == 0) t = mask[idx] != 0;
            else if (md == 1) t = ((const int*)  mask)[idx] != 0;
            else              t = ((const float*)mask)[idx] != 0.0f;
            if (!t) local++;
        }
        atomicAdd(&cnt[b], local);
    }
    __syncthreads();
    if (tid < B_) g_len[tid] = cnt[tid];
}

// ================= fused layernorm (q rows then kv rows) -> fp16 =================
__global__ void __launch_bounds__(256) layernorm_all_kernel(
    const float* __restrict__ xq, const float* __restrict__ xkv,
    const float* __restrict__ nqw, const float* __restrict__ nqb,
    const float* __restrict__ nkw, const float* __restrict__ nkb,
    __half* __restrict__ yq, __half* __restrict__ ykv)
{
    const bool is_q = (blockIdx.x < B_ * LQ_);
    const int  row  = is_q ? blockIdx.x : blockIdx.x - B_ * LQ_;
    const float* x  = is_q ? xq  : xkv;
    const float* w  = is_q ? nqw : nkw;
    const float* bb = is_q ? nqb : nkb;
    __half* y       = is_q ? yq  : ykv;

    int tid = threadIdx.x;
    const float* xr = x + (size_t)row * D_;
    float4 v = *(const float4*)(xr + tid * 4);
    float s  = v.x + v.y + v.z + v.w;
    float sq = v.x * v.x + v.y * v.y + v.z * v.z + v.w * v.w;
    #pragma unroll
    for (int o = 16; o; o >>= 1) {
        s  += __shfl_xor_sync(0xffffffffu, s,  o);
        sq += __shfl_xor_sync(0xffffffffu, sq, o);
    }
    __shared__ float ss[8], ssq[8];
    int wid = tid >> 5, ln = tid & 31;
    if (ln == 0) { ss[wid] = s; ssq[wid] = sq; }
    __syncthreads();
    if (tid == 0) {
        float S = 0.f, SQ = 0.f;
        #pragma unroll
        for (int i = 0; i < 8; i++) { S += ss[i]; SQ += ssq[i]; }
        float mu  = S * (1.0f / D_);
        float var = SQ * (1.0f / D_) - mu * mu;
        ss[0]  = mu;
        ssq[0] = rsqrtf(fmaxf(var, 0.0f) + 1e-5f);
    }
    __syncthreads();
    float mu = ss[0], inv = ssq[0];
    float4 wv = *(const float4*)(w  + tid * 4);
    float4 bv = *(const float4*)(bb + tid * 4);
    __half* yr = y + (size_t)row * D_ + tid * 4;
    *(__half2*)(yr)     = __floats2half2_rn((v.x - mu) * inv * wv.x + bv.x,
                                            (v.y - mu) * inv * wv.y + bv.y);
    *(__half2*)(yr + 2) = __floats2half2_rn((v.z - mu) * inv * wv.z + bv.z,
                                            (v.w - mu) * inv * wv.w + bv.w);
}

// ================= fused weight convert fp32 -> fp16 (Wq | Wkv | Wo) =================
__global__ void __launch_bounds__(256) weight_fp16_all_kernel(
    const float* __restrict__ Wq, const float* __restrict__ Wkv,
    const float* __restrict__ Wo,
    __half* __restrict__ wq, __half* __restrict__ wkv, __half* __restrict__ wo)
{
    int idx4 = (blockIdx.x * 256 + threadIdx.x) * 4;
    const float* src;
    __half* dst;
    if (idx4 < D_ * D_)              { src = Wq;  dst = wq;  }
    else if (idx4 < 3 * D_ * D_)     { src = Wkv; dst = wkv; idx4 -= D_ * D_; }
    else                             { src = Wo;  dst = wo;  idx4 -= 3 * D_ * D_; }
    float4 v = *(const float4*)(src + idx4);
    *(__half2*)(dst + idx4)     = __floats2half2_rn(v.x, v.y);
    *(__half2*)(dst + idx4 + 2) = __floats2half2_rn(v.z, v.w);
}

// ========== per-head write helpers for GEMM epilogues ==========
__device__ __forceinline__ void write_q_pair(int mrow, int n, float2 v) {
    int b = mrow >> 10, qr = mrow & 1023, h = n >> 6, d = n & 63;
    __half* dst = g_q1 + ((size_t)((b * H_ + h) * LQ_ + qr)) * HD_ + d;
    *(__half2*)dst = __floats2half2_rn(v.x, v.y);
}
__device__ __forceinline__ void write_kv_pair(int mrow, int n, float2 v) {
    int b = mrow >> 11, kr = mrow & 2047;
    int h2 = n >> 6, d = n & 63;
    __half* dst = (h2 < H_)
        ? g_k1 + ((size_t)((b * H_ + h2) * LKV_ + kr)) * HD_ + d
        : g_v1 + ((size_t)((b * H_ + (h2 - H_)) * LKV_ + kr)) * HD_ + d;
    *(__half2*)dst = __floats2half2_rn(v.x, v.y);
}

// ================= fp16 warp-MMA GEMM (3-stage cp.async, 2 CTAs/SM) =================
// C = A[M,1024] @ W[N,1024]^T, 128x128 CTA tile, 8 warps 32x64, BK=32, NK=32.
// mode 0: fp32 C + bias + residual; mode 1: Q per-head; mode 2: KV per-head
//          (mode 2 skips m-tiles fully past len[b]).
#define SSTRIDE 40                      // fp16 per smem row (80B)
#define GSTAGE_BYTES (128 * SSTRIDE * 2)
#define GSTAGES 3
#define GEMM_SMEM (2 * GSTAGES * GSTAGE_BYTES)  // 61440 B
#define NKG (D_ / 32)   // 32

__global__ void __launch_bounds__(256, 2) gemm_fp16_mma_kernel(
    const __half* __restrict__ A, const __half* __restrict__ W,
    const float* __restrict__ bias, const float* __restrict__ R,
    float* __restrict__ C, int M, int N, int mode)
{
    const int m0 = blockIdx.y * 128, n0 = blockIdx.x * 128;
    if (mode == 2) {
        // kv rows beyond this batch's length are never read by attention
        int b = m0 >> 11, kr0 = m0 & 2047;
        if (kr0 >= g_len[b]) return;
    }

    extern __shared__ char gsm[];
    const uint32_t smem_u = smem_to_u32(gsm);
    const uint32_t sa_u = smem_u;
    const uint32_t sb_u = smem_u + GSTAGES * GSTAGE_BYTES;

    const int tid  = threadIdx.x;
    const int lane = tid & 31;
    const int wid  = tid >> 5;
    const int warp_m = wid & 3;
    const int warp_n = wid >> 2;

    const int lr = tid >> 2;            // 0..63
    const int lu = tid & 3;             // 16B unit
    const __half* ag = A + (size_t)(m0 + lr) * D_ + lu * 8;
    const __half* bg = W + (size_t)(n0 + lr) * D_ + lu * 8;
    const uint32_t row_b  = (uint32_t)(lr * SSTRIDE * 2 + lu * 16);
    const uint32_t row_b2 = row_b + (uint32_t)(64 * SSTRIDE * 2);

    float acc[2][8][4];
    #pragma unroll
    for (int i = 0; i < 2; i++)
        #pragma unroll
        for (int j = 0; j < 8; j++)
            #pragma unroll
            for (int t = 0; t < 4; t++) acc[i][j][t] = 0.0f;

    const uint32_t a_off = (uint32_t)((warp_m * 32 + (lane & 15)) * SSTRIDE * 2
                                      + (lane >> 4) * 16);
    const uint32_t b_off = (uint32_t)((warp_n * 64 + ((lane >> 4) & 1) * 8 + (lane & 7)) * SSTRIDE * 2
                                      + ((lane >> 3) & 1) * 16);

    // prologue: stages 0..1
    #pragma unroll
    for (int s = 0; s < 2; s++) {
        const size_t koff = (size_t)s * 32;
        const uint32_t sa_s = sa_u + (uint32_t)(s * GSTAGE_BYTES);
        const uint32_t sb_s = sb_u + (uint32_t)(s * GSTAGE_BYTES);
        cp_async16(sa_s + row_b,  ag + koff);
        cp_async16(sa_s + row_b2, ag + (size_t)64 * D_ + koff);
        cp_async16(sb_s + row_b,  bg + koff);
        cp_async16(sb_s + row_b2, bg + (size_t)64 * D_ + koff);
        CP_ASYNC_COMMIT();
    }

    int sidx = 2;   // next stage slot to fill (mod 3)
    for (int kt = 0; kt < NKG; kt++) {
        CP_ASYNC_WAIT(1);
        __syncthreads();
        if (kt + 2 < NKG) {
            const size_t koff = (size_t)(kt + 2) * 32;
            const uint32_t sa_s = sa_u + (uint32_t)(sidx * GSTAGE_BYTES);
            const uint32_t sb_s = sb_u + (uint32_t)(sidx * GSTAGE_BYTES);
            cp_async16(sa_s + row_b,  ag + koff);
            cp_async16(sa_s + row_b2, ag + (size_t)64 * D_ + koff);
            cp_async16(sb_s + row_b,  bg + koff);
            cp_async16(sb_s + row_b2, bg + (size_t)64 * D_ + koff);
            if (++sidx == 3) sidx = 0;
        }
        CP_ASYNC_COMMIT();

        const int cur = kt % 3;
        const uint32_t sa_cur = sa_u + (uint32_t)(cur * GSTAGE_BYTES);
        const uint32_t sb_cur = sb_u + (uint32_t)(cur * GSTAGE_BYTES);
        #pragma unroll
        for (int ks = 0; ks < 2; ks++) {
            uint32_t a_frag[2][4];
            #pragma unroll
            for (int im = 0; im < 2; im++)
                ldmatrix_x4(a_frag[im], sa_cur + a_off
                            + (uint32_t)(im * 16 * SSTRIDE * 2 + ks * 32));
            uint32_t b_frag[4][4];
            #pragma unroll
            for (int iu = 0; iu < 4; iu++)
                ldmatrix_x4(b_frag[iu], sb_cur + b_off
                            + (uint32_t)(iu * 16 * SSTRIDE * 2 + ks * 32));
            #pragma unroll
            for (int im = 0; im < 2; im++)
                #pragma unroll
                for (int iu = 0; iu < 4; iu++) {
                    mma_16816(acc[im][iu * 2 + 0], a_frag[im], b_frag[iu][0], b_frag[iu][1]);
                    mma_16816(acc[im][iu * 2 + 1], a_frag[im], b_frag[iu][2], b_frag[iu][3]);
                }
        }
    }

    const int gr = lane >> 2;
    const int gc = (lane & 3) * 2;
    #pragma unroll
    for (int im = 0; im < 2; im++) {
        const int mrow = m0 + warp_m * 32 + im * 16 + gr;
        #pragma unroll
        for (int in = 0; in < 8; in++) {
            const int n = n0 + warp_n * 64 + in * 8 + gc;
            float b0 = bias[n], b1 = bias[n + 1];
            float2 v0 = make_float2(acc[im][in][0] + b0, acc[im][in][1] + b1);
            float2 v1 = make_float2(acc[im][in][2] + b0, acc[im][in][3] + b1);
            if (mode == 0) {
                if (R) {
                    float2 r0 = *(const float2*)(R + (size_t)mrow * N + n);
                    float2 r1 = *(const float2*)(R + (size_t)(mrow + 8) * N + n);
                    v0.x += r0.x; v0.y += r0.y;
                    v1.x += r1.x; v1.y += r1.y;
                }
                *(float2*)(C + (size_t)mrow * N + n)       = v0;
                *(float2*)(C + (size_t)(mrow + 8) * N + n) = v1;
            } else if (mode == 1) {
                write_q_pair(mrow,     n, v0);
                write_q_pair(mrow + 8, n, v1);
            } else {
                write_kv_pair(mrow,     n, v0);
                write_kv_pair(mrow + 8, n, v1);
            }
        }
    }
}

// ================= fp16 HMMA flash attention (double-buffered cp.async K/V) =================
#define AQ  128
#define SQ  72     // smem row stride in fp16 (144B)
// smem layout (fp16 elem offsets):
//   Ks[2]: 0, 4608   Vs[2]: 9216, 13824   Ps: 18432   Qs: 27648..36864
#define KTILE 4608             // 64 * SQ
#define FA_SMEM_BYTES (36864 * 2)

__global__ void __launch_bounds__(256, 2) flash_attn_mma_kernel(
    const __half* __restrict__ q1, const __half* __restrict__ k1,
    const __half* __restrict__ v1, __half* __restrict__ outk)
{
    extern __shared__ __half smem_h[];
    __half* Ps = smem_h + 18432;
    __half* Qs = smem_h + 27648;

    const int b = blockIdx.z, h = blockIdx.y, qt = blockIdx.x;
    const int tid = threadIdx.x, lane = tid & 31, wid = tid >> 5;
    const int gr = lane >> 2, gc = (lane & 3) * 2;

    const uint32_t smem_u = smem_to_u32(smem_h);
    const uint32_t ks_u = smem_u;
    const uint32_t vs_u = smem_u + 9216 * 2;
    const uint32_t ps_u = smem_u + 18432 * 2;
    const uint32_t qs_u = smem_u + 27648 * 2;

    // ---- load Q tile [128][64] ----
    const __half* qg = q1 + ((size_t)((b * H_ + h) * LQ_ + qt * AQ)) * HD_;
    #pragma unroll
    for (int rep = 0; rep < 4; rep++) {
        int idx = rep * 256 + tid;
        int r = idx >> 3, u = idx & 7;
        *(uint4*)&Qs[r * SQ + u * 8] = *(const uint4*)(qg + (size_t)r * HD_ + u * 8);
    }
    __syncthreads();

    // ---- preload Q a-frags (4 k16-steps) ----
    uint32_t qfrag[4][4];
    const uint32_t a_base = qs_u + (uint32_t)((wid * 16 + (lane & 15)) * SQ * 2
                                              + (lane >> 4) * 16);
    #pragma unroll
    for (int ks = 0; ks < 4; ks++)
        ldmatrix_x4(qfrag[ks], a_base + (uint32_t)(ks * 32));

    const uint32_t kb_off = (uint32_t)((((lane >> 4) & 1) * 8 + (lane & 7)) * SQ * 2
                                       + ((lane >> 3) & 1) * 16);
    const uint32_t vb_off = (uint32_t)(((lane & 7) + ((lane >> 3) & 1) * 8) * SQ * 2
                                       + (lane >> 4) * 16);
    const uint32_t pa_off = (uint32_t)((wid * 16 + (lane & 15)) * SQ * 2
                                       + (lane >> 4) * 16);

    const int len   = g_len[b];
    const int ntile = (len + 63) >> 6;

    const __half* kbase = k1 + ((size_t)((b * H_ + h) * LKV_)) * HD_;
    const __half* vbase = v1 + ((size_t)((b * H_ + h) * LKV_)) * HD_;

    auto issue_tile = [&](int kt, int buf) {
        const __half* kg = kbase + (size_t)(kt * 64) * HD_;
        const __half* vg = vbase + (size_t)(kt * 64) * HD_;
        const uint32_t kdst = ks_u + (uint32_t)(buf * KTILE * 2);
        const uint32_t vdst = vs_u + (uint32_t)(buf * KTILE * 2);
        #pragma unroll
        for (int rep = 0; rep < 2; rep++) {
            int idx = rep * 256 + tid;
            int r = idx >> 3, u = idx & 7;
            uint32_t off = (uint32_t)((r * SQ + u * 8) * 2);
            cp_async16(kdst + off, kg + (size_t)r * HD_ + u * 8);
            cp_async16(vdst + off, vg + (size_t)r * HD_ + u * 8);
        }
    };

    float m_r[2] = {-1e30f, -1e30f};
    float l_r[2] = {0.0f, 0.0f};
    float acc_o[8][4];
    #pragma unroll
    for (int i = 0; i < 8; i++)
        #pragma unroll
        for (int j = 0; j < 4; j++) acc_o[i][j] = 0.0f;

    issue_tile(0, 0);
    CP_ASYNC_COMMIT();

    for (int kt = 0; kt < ntile; kt++) {
        const int buf = kt & 1;
        if (kt + 1 < ntile) issue_tile(kt + 1, buf ^ 1);
        CP_ASYNC_COMMIT();
        CP_ASYNC_WAIT(1);
        __syncthreads();

        const uint32_t kcur = ks_u + (uint32_t)(buf * KTILE * 2);
        const uint32_t vcur = vs_u + (uint32_t)(buf * KTILE * 2);

        // ---- S = Q @ K^T (4 k16-steps) ----
        float acc_s[8][4];
        #pragma unroll
        for (int i = 0; i < 8; i++)
            #pragma unroll
            for (int j = 0; j < 4; j++) acc_s[i][j] = 0.0f;

        #pragma unroll
        for (int ks = 0; ks < 4; ks++) {
            uint32_t bf[4][4];
            #pragma unroll
            for (int nt4 = 0; nt4 < 4; nt4++)
                ldmatrix_x4(bf[nt4], kcur + kb_off
                            + (uint32_t)(nt4 * 16 * SQ * 2 + ks * 32));
            #pragma unroll
            for (int nt4 = 0; nt4 < 4; nt4++) {
                mma_16816(acc_s[nt4 * 2 + 0], qfrag[ks], bf[nt4][0], bf[nt4][1]);
                mma_16816(acc_s[nt4 * 2 + 1], qfrag[ks], bf[nt4][2], bf[nt4][3]);
            }
        }

        // ---- scale + mask ----
        const int rem = len - kt * 64;
        #pragma unroll
        for (int nt = 0; nt < 8; nt++) {
            int c0 = nt * 8 + gc;
            bool k0 = (c0 >= rem), k1m = (c0 + 1 >= rem);
            acc_s[nt][0] = k0  ? -1e9f : acc_s[nt][0] * 0.125f;
            acc_s[nt][1] = k1m ? -1e9f : acc_s[nt][1] * 0.125f;
            acc_s[nt][2] = k0  ? -1e9f : acc_s[nt][2] * 0.125f;
            acc_s[nt][3] = k1m ? -1e9f : acc_s[nt][3] * 0.125f;
        }

        // ---- online softmax ----
        float tmax0 = -1e30f, tmax1 = -1e30f;
        #pragma unroll
        for (int nt = 0; nt < 8; nt++) {
            tmax0 = fmaxf(tmax0, fmaxf(acc_s[nt][0], acc_s[nt][1]));
            tmax1 = fmaxf(tmax1, fmaxf(acc_s[nt][2], acc_s[nt][3]));
        }
        #pragma unroll
        for (int o = 1; o < 4; o <<= 1) {
            tmax0 = fmaxf(tmax0, __shfl_xor_sync(0xffffffffu, tmax0, o));
            tmax1 = fmaxf(tmax1, __shfl_xor_sync(0xffffffffu, tmax1, o));
        }
        float mn0 = fmaxf(m_r[0], tmax0), mn1 = fmaxf(m_r[1], tmax1);
        float al0 = __expf(m_r[0] - mn0), al1 = __expf(m_r[1] - mn1);
        float rs0 = 0.0f, rs1 = 0.0f;
        #pragma unroll
        for (int nt = 0; nt < 8; nt++) {
            acc_s[nt][0] = __expf(acc_s[nt][0] - mn0);
            acc_s[nt][1] = __expf(acc_s[nt][1] - mn0);
            acc_s[nt][2] = __expf(acc_s[nt][2] - mn1);
            acc_s[nt][3] = __expf(acc_s[nt][3] - mn1);
            rs0 += acc_s[nt][0] + acc_s[nt][1];
            rs1 += acc_s[nt][2] + acc_s[nt][3];
        }
        #pragma unroll
        for (int o = 1; o < 4; o <<= 1) {
            rs0 += __shfl_xor_sync(0xffffffffu, rs0, o);
            rs1 += __shfl_xor_sync(0xffffffffu, rs1, o);
        }
        l_r[0] = l_r[0] * al0 + rs0;  m_r[0] = mn0;
        l_r[1] = l_r[1] * al1 + rs1;  m_r[1] = mn1;
        #pragma unroll
        for (int nt = 0; nt < 8; nt++) {
            acc_o[nt][0] *= al0; acc_o[nt][1] *= al0;
            acc_o[nt][2] *= al1; acc_o[nt][3] *= al1;
        }

        // ---- P -> smem fp16 (warp-private rows) ----
        const int pr0 = wid * 16 + gr, pr1 = pr0 + 8;
        #pragma unroll
        for (int nt = 0; nt < 8; nt++) {
            int c0 = nt * 8 + gc;
            *(__half2*)&Ps[pr0 * SQ + c0] = __floats2half2_rn(acc_s[nt][0], acc_s[nt][1]);
            *(__half2*)&Ps[pr1 * SQ + c0] = __floats2half2_rn(acc_s[nt][2], acc_s[nt][3]);
        }
        __syncwarp();

        // ---- O += P @ V (4 k16-steps) ----
        #pragma unroll
        for (int ks4 = 0; ks4 < 4; ks4++) {
            uint32_t af[4];
            ldmatrix_x4(af, ps_u + pa_off + (uint32_t)(ks4 * 32));
            uint32_t bf[4][4];
            #pragma unroll
            for (int g = 0; g < 4; g++)
                ldmatrix_x4_trans(bf[g], vcur + vb_off
                                  + (uint32_t)(ks4 * 16 * SQ * 2 + g * 32));
            #pragma unroll
            for (int g = 0; g < 4; g++) {
                mma_16816(acc_o[g * 2 + 0], af, bf[g][0], bf[g][1]);
                mma_16816(acc_o[g * 2 + 1], af, bf[g][2], bf[g][3]);
            }
        }
        __syncthreads();   // WAR: protect buf before next iteration's issue
    }

    // ---- epilogue: normalize + write fp16 rows [M, 1024] ----
    float inv0 = 1.0f / l_r[0], inv1 = 1.0f / l_r[1];
    const int qrow0 = qt * AQ + wid * 16 + gr;
    __half* p0 = outk + ((size_t)(b * LQ_ + qrow0)) * D_ + h * HD_;
    __half* p1 = p0 + (size_t)8 * D_;
    #pragma unroll
    for (int nt = 0; nt < 8; nt++) {
        int col = nt * 8 + gc;
        *(__half2*)(p0 + col) = __floats2half2_rn(acc_o[nt][0] * inv0,
                                                  acc_o[nt][1] * inv0);
        *(__half2*)(p1 + col) = __floats2half2_rn(acc_o[nt][2] * inv1,
                                                  acc_o[nt][3] * inv1);
    }
}

// ================= host launcher =================
extern "C" void kernel_launch(void* const* d_in, const int* in_sizes, int n_in,
                              void* d_out, int out_size) {
    const float*         q    = (const float*)d_in[0];
    const float*         kv   = (const float*)d_in[1];
    const unsigned char* mask = (const unsigned char*)d_in[2];
    const float*         nqw  = (const float*)d_in[3];
    const float*         nqb  = (const float*)d_in[4];
    const float*         nkw  = (const float*)d_in[5];
    const float*         nkb  = (const float*)d_in[6];
    const float*         Wq   = (const float*)d_in[7];
    const float*         bq   = (const float*)d_in[8];
    const float*         Wkv  = (const float*)d_in[9];
    const float*         bkv  = (const float*)d_in[10];
    const float*         Wo   = (const float*)d_in[11];
    const float*         bo   = (const float*)d_in[12];
    float* out = (float*)d_out;

    __half *qk, *kvk, *ak, *wq, *wkv, *wo, *q1, *k1, *v1;
    cudaGetSymbolAddress((void**)&qk,  g_qk);
    cudaGetSymbolAddress((void**)&kvk, g_kvk);
    cudaGetSymbolAddress((void**)&ak,  g_ak);
    cudaGetSymbolAddress((void**)&wq,  g_wq);
    cudaGetSymbolAddress((void**)&wkv, g_wkv);
    cudaGetSymbolAddress((void**)&wo,  g_wo);
    cudaGetSymbolAddress((void**)&q1,  g_q1);
    cudaGetSymbolAddress((void**)&k1,  g_k1);
    cudaGetSymbolAddress((void**)&v1,  g_v1);

    cudaFuncSetAttribute(flash_attn_mma_kernel,
                         cudaFuncAttributeMaxDynamicSharedMemorySize, FA_SMEM_BYTES);
    cudaFuncSetAttribute(gemm_fp16_mma_kernel,
                         cudaFuncAttributeMaxDynamicSharedMemorySize, GEMM_SMEM);

    compute_lengths_kernel<<<1, 256>>>(mask);                              // 0
    weight_fp16_all_kernel<<<(4 * D_ * D_) / 1024, 256>>>(Wq, Wkv, Wo,
                                                          wq, wkv, wo);    // 1
    layernorm_all_kernel<<<B_ * (LQ_ + LKV_), 256>>>(q, kv, nqw, nqb,
                                                     nkw, nkb, qk, kvk);   // 2

    dim3 gkv((2 * D_) / 128, (B_ * LKV_) / 128);  // (16, 64)
    gemm_fp16_mma_kernel<<<gkv, 256, GEMM_SMEM>>>(kvk, wkv, bkv, nullptr,
                                                  nullptr, B_ * LKV_, 2 * D_, 2); // 3

    dim3 gq(D_ / 128, (B_ * LQ_) / 128);          // (8, 32)
    gemm_fp16_mma_kernel<<<gq, 256, GEMM_SMEM>>>(qk, wq, bq, nullptr,
                                                 nullptr, B_ * LQ_, D_, 1);   // 4

    flash_attn_mma_kernel<<<dim3(LQ_ / AQ, H_, B_), 256, FA_SMEM_BYTES>>>(
        q1, k1, v1, ak);                                                    // 5

    gemm_fp16_mma_kernel<<<gq, 256, GEMM_SMEM>>>(ak, wo, bo, q, out,
                                                 B_ * LQ_, D_, 0);          // 6
}

// round 12
// speedup vs baseline: 6.6615x; 1.0811x over previous
#include <cuda_runtime.h>
#include <cuda_fp16.h>
#include <math.h>
#include <stdint.h>

// Problem dims
#define B_   4
#define LQ_  1024
#define LKV_ 2048
#define D_   1024
#define H_   16
#define HD_  64

// ================= warp-MMA helpers (baseline PTX, sm_80+) =================
__device__ __forceinline__ uint32_t smem_to_u32(const void* p) {
    uint32_t a;
    asm("{ .reg .u64 t; cvta.to.shared.u64 t, %1; cvt.u32.u64 %0, t; }"
        : "=r"(a) : "l"(p));
    return a;
}
__device__ __forceinline__ void ldmatrix_x4(uint32_t* r, uint32_t addr) {
    asm volatile("ldmatrix.sync.aligned.m8n8.x4.shared.b16 {%0,%1,%2,%3}, [%4];"
        : "=r"(r[0]), "=r"(r[1]), "=r"(r[2]), "=r"(r[3]) : "r"(addr));
}
__device__ __forceinline__ void ldmatrix_x4_trans(uint32_t* r, uint32_t addr) {
    asm volatile("ldmatrix.sync.aligned.m8n8.x4.trans.shared.b16 {%0,%1,%2,%3}, [%4];"
        : "=r"(r[0]), "=r"(r[1]), "=r"(r[2]), "=r"(r[3]) : "r"(addr));
}
__device__ __forceinline__ void mma_16816(float* d, const uint32_t* a,
                                          uint32_t b0, uint32_t b1) {
    asm volatile("mma.sync.aligned.m16n8k16.row.col.f32.f16.f16.f32 "
        "{%0,%1,%2,%3}, {%4,%5,%6,%7}, {%8,%9}, {%0,%1,%2,%3};"
        : "+f"(d[0]), "+f"(d[1]), "+f"(d[2]), "+f"(d[3])
        : "r"(a[0]), "r"(a[1]), "r"(a[2]), "r"(a[3]), "r"(b0), "r"(b1));
}
__device__ __forceinline__ void cp_async16(uint32_t smem_addr, const void* gptr) {
    asm volatile("cp.async.cg.shared.global [%0], [%1], 16;"
        :: "r"(smem_addr), "l"(gptr));
}
#define CP_ASYNC_COMMIT() asm volatile("cp.async.commit_group;" ::: "memory")
#define CP_ASYNC_WAIT(N)  asm volatile("cp.async.wait_group %0;" :: "n"(N) : "memory")

// ================= scratch =================
__device__ __half g_qk  [B_ * LQ_  * D_];        // LN(q)  fp16 (GEMM A)
__device__ __half g_kvk [B_ * LKV_ * D_];        // LN(kv) fp16 (GEMM A)
__device__ __half g_ak  [B_ * LQ_  * D_];        // attn out fp16 (GEMM A)
__device__ __half g_wq  [D_ * D_];
__device__ __half g_wkv [2 * D_ * D_];
__device__ __half g_wo  [D_ * D_];
__device__ __half g_q1 [B_ * H_ * LQ_  * HD_];   // Q per head
__device__ __half g_k1 [B_ * H_ * LKV_ * HD_];   // K per head
__device__ __half g_v1 [B_ * H_ * LKV_ * HD_];   // V per head
__device__ int g_len[B_];

// ================= mask lengths (dtype-sniffing) =================
__global__ void compute_lengths_kernel(const unsigned char* __restrict__ mask) {
    __shared__ int det[4];
    __shared__ int cnt[4];
    __shared__ int mode;
    int tid = threadIdx.x;
    if (tid < 4) { det[tid] = 0; cnt[tid] = 0; }
    __syncthreads();
    for (int i = tid; i < B_ * LKV_; i += blockDim.x)
        if (mask[i]) atomicOr(&det[i & 3], 1);
    __syncthreads();
    if (tid == 0) {
        if (det[1])                mode = 0;
        else if (det[2] || det[3]) mode = det[0] ? 0 : 2;
        else if (det[0])           mode = 1;
        else                       mode = 0;
    }
    __syncthreads();
    int md = mode;
    for (int b = 0; b < B_; b++) {
        int local = 0;
        for (int k = tid; k < LKV_; k += blockDim.x) {
            int idx = b * LKV_ + k;
            bool t;
            if      (md == 0) t = mask[idx] != 0;
            else if (md == 1) t = ((const int*)  mask)[idx] != 0;
            else              t = ((const float*)mask)[idx] != 0.0f;
            if (!t) local++;
        }
        atomicAdd(&cnt[b], local);
    }
    __syncthreads();
    if (tid < B_) g_len[tid] = cnt[tid];
}

// ================= fused layernorm (q rows then kv rows) -> fp16 =================
__global__ void __launch_bounds__(256) layernorm_all_kernel(
    const float* __restrict__ xq, const float* __restrict__ xkv,
    const float* __restrict__ nqw, const float* __restrict__ nqb,
    const float* __restrict__ nkw, const float* __restrict__ nkb,
    __half* __restrict__ yq, __half* __restrict__ ykv)
{
    const bool is_q = (blockIdx.x < B_ * LQ_);
    const int  row  = is_q ? blockIdx.x : blockIdx.x - B_ * LQ_;
    const float* x  = is_q ? xq  : xkv;
    const float* w  = is_q ? nqw : nkw;
    const float* bb = is_q ? nqb : nkb;
    __half* y       = is_q ? yq  : ykv;

    int tid = threadIdx.x;
    const float* xr = x + (size_t)row * D_;
    float4 v = *(const float4*)(xr + tid * 4);
    float s  = v.x + v.y + v.z + v.w;
    float sq = v.x * v.x + v.y * v.y + v.z * v.z + v.w * v.w;
    #pragma unroll
    for (int o = 16; o; o >>= 1) {
        s  += __shfl_xor_sync(0xffffffffu, s,  o);
        sq += __shfl_xor_sync(0xffffffffu, sq, o);
    }
    __shared__ float ss[8], ssq[8];
    int wid = tid >> 5, ln = tid & 31;
    if (ln == 0) { ss[wid] = s; ssq[wid] = sq; }
    __syncthreads();
    if (tid == 0) {
        float S = 0.f, SQ = 0.f;
        #pragma unroll
        for (int i = 0; i < 8; i++) { S += ss[i]; SQ += ssq[i]; }
        float mu  = S * (1.0f / D_);
        float var = SQ * (1.0f / D_) - mu * mu;
        ss[0]  = mu;
        ssq[0] = rsqrtf(fmaxf(var, 0.0f) + 1e-5f);
    }
    __syncthreads();
    float mu = ss[0], inv = ssq[0];
    float4 wv = *(const float4*)(w  + tid * 4);
    float4 bv = *(const float4*)(bb + tid * 4);
    __half* yr = y + (size_t)row * D_ + tid * 4;
    *(__half2*)(yr)     = __floats2half2_rn((v.x - mu) * inv * wv.x + bv.x,
                                            (v.y - mu) * inv * wv.y + bv.y);
    *(__half2*)(yr + 2) = __floats2half2_rn((v.z - mu) * inv * wv.z + bv.z,
                                            (v.w - mu) * inv * wv.w + bv.w);
}

// ================= fused weight convert fp32 -> fp16 (Wq | Wkv | Wo) =================
__global__ void __launch_bounds__(256) weight_fp16_all_kernel(
    const float* __restrict__ Wq, const float* __restrict__ Wkv,
    const float* __restrict__ Wo,
    __half* __restrict__ wq, __half* __restrict__ wkv, __half* __restrict__ wo)
{
    int idx4 = (blockIdx.x * 256 + threadIdx.x) * 4;
    const float* src;
    __half* dst;
    if (idx4 < D_ * D_)              { src = Wq;  dst = wq;  }
    else if (idx4 < 3 * D_ * D_)     { src = Wkv; dst = wkv; idx4 -= D_ * D_; }
    else                             { src = Wo;  dst = wo;  idx4 -= 3 * D_ * D_; }
    float4 v = *(const float4*)(src + idx4);
    *(__half2*)(dst + idx4)     = __floats2half2_rn(v.x, v.y);
    *(__half2*)(dst + idx4 + 2) = __floats2half2_rn(v.z, v.w);
}

// ========== per-head write helpers for GEMM epilogues ==========
__device__ __forceinline__ void write_q_pair(int mrow, int n, float2 v) {
    int b = mrow >> 10, qr = mrow & 1023, h = n >> 6, d = n & 63;
    __half* dst = g_q1 + ((size_t)((b * H_ + h) * LQ_ + qr)) * HD_ + d;
    *(__half2*)dst = __floats2half2_rn(v.x, v.y);
}
__device__ __forceinline__ void write_kv_pair(int mrow, int n, float2 v) {
    int b = mrow >> 11, kr = mrow & 2047;
    int h2 = n >> 6, d = n & 63;
    __half* dst = (h2 < H_)
        ? g_k1 + ((size_t)((b * H_ + h2) * LKV_ + kr)) * HD_ + d
        : g_v1 + ((size_t)((b * H_ + (h2 - H_)) * LKV_ + kr)) * HD_ + d;
    *(__half2*)dst = __floats2half2_rn(v.x, v.y);
}

// ================= fp16 warp-MMA GEMM body (3-stage cp.async) =================
// C-tile = A[m0:+128,1024] @ W[n0:+128,1024]^T. 8 warps 32x64, BK=32, NK=32.
// MODE 0: fp32 C + bias + residual; MODE 1: Q per-head; MODE 2: KV per-head.
#define SSTRIDE 40                      // fp16 per smem row (80B)
#define GSTAGE_BYTES (128 * SSTRIDE * 2)
#define GSTAGES 3
#define GEMM_SMEM (2 * GSTAGES * GSTAGE_BYTES)  // 61440 B
#define NKG (D_ / 32)   // 32

template <int MODE>
__device__ __forceinline__ void gemm_body(
    const __half* __restrict__ A, const __half* __restrict__ W,
    const float* __restrict__ bias, const float* __restrict__ R,
    float* __restrict__ C, int N, int m0, int n0, char* gsm)
{
    const uint32_t smem_u = smem_to_u32(gsm);
    const uint32_t sa_u = smem_u;
    const uint32_t sb_u = smem_u + GSTAGES * GSTAGE_BYTES;

    const int tid  = threadIdx.x;
    const int lane = tid & 31;
    const int wid  = tid >> 5;
    const int warp_m = wid & 3;
    const int warp_n = wid >> 2;

    const int lr = tid >> 2;            // 0..63
    const int lu = tid & 3;             // 16B unit
    const __half* ag = A + (size_t)(m0 + lr) * D_ + lu * 8;
    const __half* bg = W + (size_t)(n0 + lr) * D_ + lu * 8;
    const uint32_t row_b  = (uint32_t)(lr * SSTRIDE * 2 + lu * 16);
    const uint32_t row_b2 = row_b + (uint32_t)(64 * SSTRIDE * 2);

    float acc[2][8][4];
    #pragma unroll
    for (int i = 0; i < 2; i++)
        #pragma unroll
        for (int j = 0; j < 8; j++)
            #pragma unroll
            for (int t = 0; t < 4; t++) acc[i][j][t] = 0.0f;

    const uint32_t a_off = (uint32_t)((warp_m * 32 + (lane & 15)) * SSTRIDE * 2
                                      + (lane >> 4) * 16);
    const uint32_t b_off = (uint32_t)((warp_n * 64 + ((lane >> 4) & 1) * 8 + (lane & 7)) * SSTRIDE * 2
                                      + ((lane >> 3) & 1) * 16);

    // prologue: stages 0..1
    #pragma unroll
    for (int s = 0; s < 2; s++) {
        const size_t koff = (size_t)s * 32;
        const uint32_t sa_s = sa_u + (uint32_t)(s * GSTAGE_BYTES);
        const uint32_t sb_s = sb_u + (uint32_t)(s * GSTAGE_BYTES);
        cp_async16(sa_s + row_b,  ag + koff);
        cp_async16(sa_s + row_b2, ag + (size_t)64 * D_ + koff);
        cp_async16(sb_s + row_b,  bg + koff);
        cp_async16(sb_s + row_b2, bg + (size_t)64 * D_ + koff);
        CP_ASYNC_COMMIT();
    }

    int sidx = 2;   // next stage slot to fill (mod 3)
    for (int kt = 0; kt < NKG; kt++) {
        CP_ASYNC_WAIT(1);
        __syncthreads();
        if (kt + 2 < NKG) {
            const size_t koff = (size_t)(kt + 2) * 32;
            const uint32_t sa_s = sa_u + (uint32_t)(sidx * GSTAGE_BYTES);
            const uint32_t sb_s = sb_u + (uint32_t)(sidx * GSTAGE_BYTES);
            cp_async16(sa_s + row_b,  ag + koff);
            cp_async16(sa_s + row_b2, ag + (size_t)64 * D_ + koff);
            cp_async16(sb_s + row_b,  bg + koff);
            cp_async16(sb_s + row_b2, bg + (size_t)64 * D_ + koff);
            if (++sidx == 3) sidx = 0;
        }
        CP_ASYNC_COMMIT();

        const int cur = kt % 3;
        const uint32_t sa_cur = sa_u + (uint32_t)(cur * GSTAGE_BYTES);
        const uint32_t sb_cur = sb_u + (uint32_t)(cur * GSTAGE_BYTES);
        #pragma unroll
        for (int ks = 0; ks < 2; ks++) {
            uint32_t a_frag[2][4];
            #pragma unroll
            for (int im = 0; im < 2; im++)
                ldmatrix_x4(a_frag[im], sa_cur + a_off
                            + (uint32_t)(im * 16 * SSTRIDE * 2 + ks * 32));
            uint32_t b_frag[4][4];
            #pragma unroll
            for (int iu = 0; iu < 4; iu++)
                ldmatrix_x4(b_frag[iu], sb_cur + b_off
                            + (uint32_t)(iu * 16 * SSTRIDE * 2 + ks * 32));
            #pragma unroll
            for (int im = 0; im < 2; im++)
                #pragma unroll
                for (int iu = 0; iu < 4; iu++) {
                    mma_16816(acc[im][iu * 2 + 0], a_frag[im], b_frag[iu][0], b_frag[iu][1]);
                    mma_16816(acc[im][iu * 2 + 1], a_frag[im], b_frag[iu][2], b_frag[iu][3]);
                }
        }
    }

    const int gr = lane >> 2;
    const int gc = (lane & 3) * 2;
    #pragma unroll
    for (int im = 0; im < 2; im++) {
        const int mrow = m0 + warp_m * 32 + im * 16 + gr;
        #pragma unroll
        for (int in = 0; in < 8; in++) {
            const int n = n0 + warp_n * 64 + in * 8 + gc;
            float b0 = bias[n], b1 = bias[n + 1];
            float2 v0 = make_float2(acc[im][in][0] + b0, acc[im][in][1] + b1);
            float2 v1 = make_float2(acc[im][in][2] + b0, acc[im][in][3] + b1);
            if (MODE == 0) {
                float2 r0 = *(const float2*)(R + (size_t)mrow * N + n);
                float2 r1 = *(const float2*)(R + (size_t)(mrow + 8) * N + n);
                v0.x += r0.x; v0.y += r0.y;
                v1.x += r1.x; v1.y += r1.y;
                *(float2*)(C + (size_t)mrow * N + n)       = v0;
                *(float2*)(C + (size_t)(mrow + 8) * N + n) = v1;
            } else if (MODE == 1) {
                write_q_pair(mrow,     n, v0);
                write_q_pair(mrow + 8, n, v1);
            } else {
                write_kv_pair(mrow,     n, v0);
                write_kv_pair(mrow + 8, n, v1);
            }
        }
    }
}

// fused Q+KV projection: blocks [0,1024) = KV tiles, [1024,1280) = Q tiles.
__global__ void __launch_bounds__(256, 2) proj_qkv_kernel(
    const __half* __restrict__ qk, const __half* __restrict__ kvk,
    const __half* __restrict__ wq, const __half* __restrict__ wkv,
    const float* __restrict__ bq, const float* __restrict__ bkv)
{
    extern __shared__ char gsm[];
    const int bid = blockIdx.x;
    if (bid < 1024) {
        const int m0 = (bid >> 4) * 128, n0 = (bid & 15) * 128;
        const int b = m0 >> 11, kr0 = m0 & 2047;
        if (kr0 >= g_len[b]) return;   // attention never reads these kv rows
        gemm_body<2>(kvk, wkv, bkv, nullptr, nullptr, 2 * D_, m0, n0, gsm);
    } else {
        const int r = bid - 1024;
        const int m0 = (r >> 3) * 128, n0 = (r & 7) * 128;
        gemm_body<1>(qk, wq, bq, nullptr, nullptr, D_, m0, n0, gsm);
    }
}

// O projection + residual
__global__ void __launch_bounds__(256, 2) proj_o_kernel(
    const __half* __restrict__ ak, const __half* __restrict__ wo,
    const float* __restrict__ bo, const float* __restrict__ R,
    float* __restrict__ out)
{
    extern __shared__ char gsm[];
    const int bid = blockIdx.x;
    const int m0 = (bid >> 3) * 128, n0 = (bid & 7) * 128;
    gemm_body<0>(ak, wo, bo, R, out, D_, m0, n0, gsm);
}

// ================= fp16 HMMA flash attention =================
// P kept in registers (C-frag == A-frag layout); 2 CTAs/SM (54KB smem).
#define AQ  128
#define SQ  72     // smem row stride in fp16 (144B)
// smem (fp16 elem offsets): Ks[2]: 0, 4608   Vs[2]: 9216, 13824   Qs: 18432..27648
#define KTILE 4608             // 64 * SQ
#define FA_SMEM_BYTES (27648 * 2)   // 55296

__global__ void __launch_bounds__(256, 2) flash_attn_mma_kernel(
    const __half* __restrict__ q1, const __half* __restrict__ k1,
    const __half* __restrict__ v1, __half* __restrict__ outk)
{
    extern __shared__ __half smem_h[];
    __half* Qs = smem_h + 18432;

    const int b = blockIdx.z, h = blockIdx.y, qt = blockIdx.x;
    const int tid = threadIdx.x, lane = tid & 31, wid = tid >> 5;
    const int gr = lane >> 2, gc = (lane & 3) * 2;

    const uint32_t smem_u = smem_to_u32(smem_h);
    const uint32_t ks_u = smem_u;
    const uint32_t vs_u = smem_u + 9216 * 2;
    const uint32_t qs_u = smem_u + 18432 * 2;

    // ---- load Q tile [128][64] ----
    const __half* qg = q1 + ((size_t)((b * H_ + h) * LQ_ + qt * AQ)) * HD_;
    #pragma unroll
    for (int rep = 0; rep < 4; rep++) {
        int idx = rep * 256 + tid;
        int r = idx >> 3, u = idx & 7;
        *(uint4*)&Qs[r * SQ + u * 8] = *(const uint4*)(qg + (size_t)r * HD_ + u * 8);
    }
    __syncthreads();

    // ---- preload Q a-frags (4 k16-steps) ----
    uint32_t qfrag[4][4];
    const uint32_t a_base = qs_u + (uint32_t)((wid * 16 + (lane & 15)) * SQ * 2
                                              + (lane >> 4) * 16);
    #pragma unroll
    for (int ks = 0; ks < 4; ks++)
        ldmatrix_x4(qfrag[ks], a_base + (uint32_t)(ks * 32));

    const uint32_t kb_off = (uint32_t)((((lane >> 4) & 1) * 8 + (lane & 7)) * SQ * 2
                                       + ((lane >> 3) & 1) * 16);
    const uint32_t vb_off = (uint32_t)(((lane & 7) + ((lane >> 3) & 1) * 8) * SQ * 2
                                       + (lane >> 4) * 16);

    const int len   = g_len[b];
    const int ntile = (len + 63) >> 6;

    const __half* kbase = k1 + ((size_t)((b * H_ + h) * LKV_)) * HD_;
    const __half* vbase = v1 + ((size_t)((b * H_ + h) * LKV_)) * HD_;

    auto issue_tile = [&](int kt, int buf) {
        const __half* kg = kbase + (size_t)(kt * 64) * HD_;
        const __half* vg = vbase + (size_t)(kt * 64) * HD_;
        const uint32_t kdst = ks_u + (uint32_t)(buf * KTILE * 2);
        const uint32_t vdst = vs_u + (uint32_t)(buf * KTILE * 2);
        #pragma unroll
        for (int rep = 0; rep < 2; rep++) {
            int idx = rep * 256 + tid;
            int r = idx >> 3, u = idx & 7;
            uint32_t off = (uint32_t)((r * SQ + u * 8) * 2);
            cp_async16(kdst + off, kg + (size_t)r * HD_ + u * 8);
            cp_async16(vdst + off, vg + (size_t)r * HD_ + u * 8);
        }
    };

    float m_r[2] = {-1e30f, -1e30f};
    float l_r[2] = {0.0f, 0.0f};
    float acc_o[8][4];
    #pragma unroll
    for (int i = 0; i < 8; i++)
        #pragma unroll
        for (int j = 0; j < 4; j++) acc_o[i][j] = 0.0f;

    issue_tile(0, 0);
    CP_ASYNC_COMMIT();

    for (int kt = 0; kt < ntile; kt++) {
        const int buf = kt & 1;
        if (kt + 1 < ntile) issue_tile(kt + 1, buf ^ 1);
        CP_ASYNC_COMMIT();
        CP_ASYNC_WAIT(1);
        __syncthreads();

        const uint32_t kcur = ks_u + (uint32_t)(buf * KTILE * 2);
        const uint32_t vcur = vs_u + (uint32_t)(buf * KTILE * 2);

        // ---- S = Q @ K^T (4 k16-steps) ----
        float acc_s[8][4];
        #pragma unroll
        for (int i = 0; i < 8; i++)
            #pragma unroll
            for (int j = 0; j < 4; j++) acc_s[i][j] = 0.0f;

        #pragma unroll
        for (int ks = 0; ks < 4; ks++) {
            uint32_t bf[4][4];
            #pragma unroll
            for (int nt4 = 0; nt4 < 4; nt4++)
                ldmatrix_x4(bf[nt4], kcur + kb_off
                            + (uint32_t)(nt4 * 16 * SQ * 2 + ks * 32));
            #pragma unroll
            for (int nt4 = 0; nt4 < 4; nt4++) {
                mma_16816(acc_s[nt4 * 2 + 0], qfrag[ks], bf[nt4][0], bf[nt4][1]);
                mma_16816(acc_s[nt4 * 2 + 1], qfrag[ks], bf[nt4][2], bf[nt4][3]);
            }
        }

        // ---- scale + mask ----
        const int rem = len - kt * 64;
        #pragma unroll
        for (int nt = 0; nt < 8; nt++) {
            int c0 = nt * 8 + gc;
            bool k0 = (c0 >= rem), k1m = (c0 + 1 >= rem);
            acc_s[nt][0] = k0  ? -1e9f : acc_s[nt][0] * 0.125f;
            acc_s[nt][1] = k1m ? -1e9f : acc_s[nt][1] * 0.125f;
            acc_s[nt][2] = k0  ? -1e9f : acc_s[nt][2] * 0.125f;
            acc_s[nt][3] = k1m ? -1e9f : acc_s[nt][3] * 0.125f;
        }

        // ---- online softmax (rows gr, gr+8; reduce over lane&3 group) ----
        float tmax0 = -1e30f, tmax1 = -1e30f;
        #pragma unroll
        for (int nt = 0; nt < 8; nt++) {
            tmax0 = fmaxf(tmax0, fmaxf(acc_s[nt][0], acc_s[nt][1]));
            tmax1 = fmaxf(tmax1, fmaxf(acc_s[nt][2], acc_s[nt][3]));
        }
        #pragma unroll
        for (int o = 1; o < 4; o <<= 1) {
            tmax0 = fmaxf(tmax0, __shfl_xor_sync(0xffffffffu, tmax0, o));
            tmax1 = fmaxf(tmax1, __shfl_xor_sync(0xffffffffu, tmax1, o));
        }
        float mn0 = fmaxf(m_r[0], tmax0), mn1 = fmaxf(m_r[1], tmax1);
        float al0 = __expf(m_r[0] - mn0), al1 = __expf(m_r[1] - mn1);
        float rs0 = 0.0f, rs1 = 0.0f;
        #pragma unroll
        for (int nt = 0; nt < 8; nt++) {
            acc_s[nt][0] = __expf(acc_s[nt][0] - mn0);
            acc_s[nt][1] = __expf(acc_s[nt][1] - mn0);
            acc_s[nt][2] = __expf(acc_s[nt][2] - mn1);
            acc_s[nt][3] = __expf(acc_s[nt][3] - mn1);
            rs0 += acc_s[nt][0] + acc_s[nt][1];
            rs1 += acc_s[nt][2] + acc_s[nt][3];
        }
        #pragma unroll
        for (int o = 1; o < 4; o <<= 1) {
            rs0 += __shfl_xor_sync(0xffffffffu, rs0, o);
            rs1 += __shfl_xor_sync(0xffffffffu, rs1, o);
        }
        l_r[0] = l_r[0] * al0 + rs0;  m_r[0] = mn0;
        l_r[1] = l_r[1] * al1 + rs1;  m_r[1] = mn1;
        #pragma unroll
        for (int nt = 0; nt < 8; nt++) {
            acc_o[nt][0] *= al0; acc_o[nt][1] *= al0;
            acc_o[nt][2] *= al1; acc_o[nt][3] *= al1;
        }

        // ---- O += P @ V, P converted in registers (C-frag == A-frag layout) ----
        #pragma unroll
        for (int ks4 = 0; ks4 < 4; ks4++) {
            uint32_t af[4];
            __half2 t0 = __floats2half2_rn(acc_s[2 * ks4][0],     acc_s[2 * ks4][1]);
            __half2 t1 = __floats2half2_rn(acc_s[2 * ks4][2],     acc_s[2 * ks4][3]);
            __half2 t2 = __floats2half2_rn(acc_s[2 * ks4 + 1][0], acc_s[2 * ks4 + 1][1]);
            __half2 t3 = __floats2half2_rn(acc_s[2 * ks4 + 1][2], acc_s[2 * ks4 + 1][3]);
            af[0] = *(uint32_t*)&t0;
            af[1] = *(uint32_t*)&t1;
            af[2] = *(uint32_t*)&t2;
            af[3] = *(uint32_t*)&t3;
            uint32_t bf[4][4];
            #pragma unroll
            for (int g = 0; g < 4; g++)
                ldmatrix_x4_trans(bf[g], vcur + vb_off
                                  + (uint32_t)(ks4 * 16 * SQ * 2 + g * 32));
            #pragma unroll
            for (int g = 0; g < 4; g++) {
                mma_16816(acc_o[g * 2 + 0], af, bf[g][0], bf[g][1]);
                mma_16816(acc_o[g * 2 + 1], af, bf[g][2], bf[g][3]);
            }
        }
        __syncthreads();   // WAR: protect buf before next iteration's issue
    }

    // ---- epilogue: normalize + write fp16 rows [M, 1024] ----
    float inv0 = 1.0f / l_r[0], inv1 = 1.0f / l_r[1];
    const int qrow0 = qt * AQ + wid * 16 + gr;
    __half* p0 = outk + ((size_t)(b * LQ_ + qrow0)) * D_ + h * HD_;
    __half* p1 = p0 + (size_t)8 * D_;
    #pragma unroll
    for (int nt = 0; nt < 8; nt++) {
        int col = nt * 8 + gc;
        *(__half2*)(p0 + col) = __floats2half2_rn(acc_o[nt][0] * inv0,
                                                  acc_o[nt][1] * inv0);
        *(__half2*)(p1 + col) = __floats2half2_rn(acc_o[nt][2] * inv1,
                                                  acc_o[nt][3] * inv1);
    }
}

// ================= host launcher =================
extern "C" void kernel_launch(void* const* d_in, const int* in_sizes, int n_in,
                              void* d_out, int out_size) {
    const float*         q    = (const float*)d_in[0];
    const float*         kv   = (const float*)d_in[1];
    const unsigned char* mask = (const unsigned char*)d_in[2];
    const float*         nqw  = (const float*)d_in[3];
    const float*         nqb  = (const float*)d_in[4];
    const float*         nkw  = (const float*)d_in[5];
    const float*         nkb  = (const float*)d_in[6];
    const float*         Wq   = (const float*)d_in[7];
    const float*         bq   = (const float*)d_in[8];
    const float*         Wkv  = (const float*)d_in[9];
    const float*         bkv  = (const float*)d_in[10];
    const float*         Wo   = (const float*)d_in[11];
    const float*         bo   = (const float*)d_in[12];
    float* out = (float*)d_out;

    __half *qk, *kvk, *ak, *wq, *wkv, *wo, *q1, *k1, *v1;
    cudaGetSymbolAddress((void**)&qk,  g_qk);
    cudaGetSymbolAddress((void**)&kvk, g_kvk);
    cudaGetSymbolAddress((void**)&ak,  g_ak);
    cudaGetSymbolAddress((void**)&wq,  g_wq);
    cudaGetSymbolAddress((void**)&wkv, g_wkv);
    cudaGetSymbolAddress((void**)&wo,  g_wo);
    cudaGetSymbolAddress((void**)&q1,  g_q1);
    cudaGetSymbolAddress((void**)&k1,  g_k1);
    cudaGetSymbolAddress((void**)&v1,  g_v1);

    cudaFuncSetAttribute(flash_attn_mma_kernel,
                         cudaFuncAttributeMaxDynamicSharedMemorySize, FA_SMEM_BYTES);
    cudaFuncSetAttribute(proj_qkv_kernel,
                         cudaFuncAttributeMaxDynamicSharedMemorySize, GEMM_SMEM);
    cudaFuncSetAttribute(proj_o_kernel,
                         cudaFuncAttributeMaxDynamicSharedMemorySize, GEMM_SMEM);

    compute_lengths_kernel<<<1, 256>>>(mask);                              // 0
    weight_fp16_all_kernel<<<(4 * D_ * D_) / 1024, 256>>>(Wq, Wkv, Wo,
                                                          wq, wkv, wo);    // 1
    layernorm_all_kernel<<<B_ * (LQ_ + LKV_), 256>>>(q, kv, nqw, nqb,
                                                     nkw, nkb, qk, kvk);   // 2

    proj_qkv_kernel<<<1280, 256, GEMM_SMEM>>>(qk, kvk, wq, wkv, bq, bkv);  // 3

    flash_attn_mma_kernel<<<dim3(LQ_ / AQ, H_, B_), 256, FA_SMEM_BYTES>>>(
        q1, k1, v1, ak);                                                    // 4

    proj_o_kernel<<<256, 256, GEMM_SMEM>>>(ak, wo, bo, q, out);             // 5
}

// round 13
// speedup vs baseline: 6.8867x; 1.0338x over previous
#include <cuda_runtime.h>
#include <cuda_fp16.h>
#include <math.h>
#include <stdint.h>

// Problem dims
#define B_   4
#define LQ_  1024
#define LKV_ 2048
#define D_   1024
#define H_   16
#define HD_  64

// ================= warp-MMA helpers (baseline PTX, sm_80+) =================
__device__ __forceinline__ uint32_t smem_to_u32(const void* p) {
    uint32_t a;
    asm("{ .reg .u64 t; cvta.to.shared.u64 t, %1; cvt.u32.u64 %0, t; }"
        : "=r"(a) : "l"(p));
    return a;
}
__device__ __forceinline__ void ldmatrix_x4(uint32_t* r, uint32_t addr) {
    asm volatile("ldmatrix.sync.aligned.m8n8.x4.shared.b16 {%0,%1,%2,%3}, [%4];"
        : "=r"(r[0]), "=r"(r[1]), "=r"(r[2]), "=r"(r[3]) : "r"(addr));
}
__device__ __forceinline__ void ldmatrix_x4_trans(uint32_t* r, uint32_t addr) {
    asm volatile("ldmatrix.sync.aligned.m8n8.x4.trans.shared.b16 {%0,%1,%2,%3}, [%4];"
        : "=r"(r[0]), "=r"(r[1]), "=r"(r[2]), "=r"(r[3]) : "r"(addr));
}
__device__ __forceinline__ void mma_16816(float* d, const uint32_t* a,
                                          uint32_t b0, uint32_t b1) {
    asm volatile("mma.sync.aligned.m16n8k16.row.col.f32.f16.f16.f32 "
        "{%0,%1,%2,%3}, {%4,%5,%6,%7}, {%8,%9}, {%0,%1,%2,%3};"
        : "+f"(d[0]), "+f"(d[1]), "+f"(d[2]), "+f"(d[3])
        : "r"(a[0]), "r"(a[1]), "r"(a[2]), "r"(a[3]), "r"(b0), "r"(b1));
}
__device__ __forceinline__ void cp_async16(uint32_t smem_addr, const void* gptr) {
    asm volatile("cp.async.cg.shared.global [%0], [%1], 16;"
        :: "r"(smem_addr), "l"(gptr));
}
#define CP_ASYNC_COMMIT() asm volatile("cp.async.commit_group;" ::: "memory")
#define CP_ASYNC_WAIT(N)  asm volatile("cp.async.wait_group %0;" :: "n"(N) : "memory")

// ================= scratch =================
__device__ __half g_qk  [B_ * LQ_  * D_];        // LN(q)  fp16 (GEMM A)
__device__ __half g_kvk [B_ * LKV_ * D_];        // LN(kv) fp16 (GEMM A)
__device__ __half g_ak  [B_ * LQ_  * D_];        // attn out fp16 (GEMM A)
__device__ __half g_wq  [D_ * D_];
__device__ __half g_wkv [2 * D_ * D_];
__device__ __half g_wo  [D_ * D_];
__device__ __half g_q1 [B_ * H_ * LQ_  * HD_];   // Q per head
__device__ __half g_k1 [B_ * H_ * LKV_ * HD_];   // K per head
__device__ __half g_v1 [B_ * H_ * LKV_ * HD_];   // V per head
__device__ int g_len[B_];

// ================= mask lengths (dtype-sniffing) =================
__global__ void compute_lengths_kernel(const unsigned char* __restrict__ mask) {
    __shared__ int det[4];
    __shared__ int cnt[4];
    __shared__ int mode;
    int tid = threadIdx.x;
    if (tid < 4) { det[tid] = 0; cnt[tid] = 0; }
    __syncthreads();
    for (int i = tid; i < B_ * LKV_; i += blockDim.x)
        if (mask[i]) atomicOr(&det[i & 3], 1);
    __syncthreads();
    if (tid == 0) {
        if (det[1])                mode = 0;
        else if (det[2] || det[3]) mode = det[0] ? 0 : 2;
        else if (det[0])           mode = 1;
        else                       mode = 0;
    }
    __syncthreads();
    int md = mode;
    for (int b = 0; b < B_; b++) {
        int local = 0;
        for (int k = tid; k < LKV_; k += blockDim.x) {
            int idx = b * LKV_ + k;
            bool t;
            if      (md == 0) t = mask[idx] != 0;
            else if (md == 1) t = ((const int*)  mask)[idx] != 0;
            else              t = ((const float*)mask)[idx] != 0.0f;
            if (!t) local++;
        }
        atomicAdd(&cnt[b], local);
    }
    __syncthreads();
    if (tid < B_) g_len[tid] = cnt[tid];
}

// ================= fused layernorm (q rows then kv rows) -> fp16 =================
__global__ void __launch_bounds__(256) layernorm_all_kernel(
    const float* __restrict__ xq, const float* __restrict__ xkv,
    const float* __restrict__ nqw, const float* __restrict__ nqb,
    const float* __restrict__ nkw, const float* __restrict__ nkb,
    __half* __restrict__ yq, __half* __restrict__ ykv)
{
    const bool is_q = (blockIdx.x < B_ * LQ_);
    const int  row  = is_q ? blockIdx.x : blockIdx.x - B_ * LQ_;
    const float* x  = is_q ? xq  : xkv;
    const float* w  = is_q ? nqw : nkw;
    const float* bb = is_q ? nqb : nkb;
    __half* y       = is_q ? yq  : ykv;

    int tid = threadIdx.x;
    const float* xr = x + (size_t)row * D_;
    float4 v = *(const float4*)(xr + tid * 4);
    float s  = v.x + v.y + v.z + v.w;
    float sq = v.x * v.x + v.y * v.y + v.z * v.z + v.w * v.w;
    #pragma unroll
    for (int o = 16; o; o >>= 1) {
        s  += __shfl_xor_sync(0xffffffffu, s,  o);
        sq += __shfl_xor_sync(0xffffffffu, sq, o);
    }
    __shared__ float ss[8], ssq[8];
    int wid = tid >> 5, ln = tid & 31;
    if (ln == 0) { ss[wid] = s; ssq[wid] = sq; }
    __syncthreads();
    if (tid == 0) {
        float S = 0.f, SQ = 0.f;
        #pragma unroll
        for (int i = 0; i < 8; i++) { S += ss[i]; SQ += ssq[i]; }
        float mu  = S * (1.0f / D_);
        float var = SQ * (1.0f / D_) - mu * mu;
        ss[0]  = mu;
        ssq[0] = rsqrtf(fmaxf(var, 0.0f) + 1e-5f);
    }
    __syncthreads();
    float mu = ss[0], inv = ssq[0];
    float4 wv = *(const float4*)(w  + tid * 4);
    float4 bv = *(const float4*)(bb + tid * 4);
    __half* yr = y + (size_t)row * D_ + tid * 4;
    *(__half2*)(yr)     = __floats2half2_rn((v.x - mu) * inv * wv.x + bv.x,
                                            (v.y - mu) * inv * wv.y + bv.y);
    *(__half2*)(yr + 2) = __floats2half2_rn((v.z - mu) * inv * wv.z + bv.z,
                                            (v.w - mu) * inv * wv.w + bv.w);
}

// ================= fused weight convert fp32 -> fp16 (Wq | Wkv | Wo) =================
__global__ void __launch_bounds__(256) weight_fp16_all_kernel(
    const float* __restrict__ Wq, const float* __restrict__ Wkv,
    const float* __restrict__ Wo,
    __half* __restrict__ wq, __half* __restrict__ wkv, __half* __restrict__ wo)
{
    int idx4 = (blockIdx.x * 256 + threadIdx.x) * 4;
    const float* src;
    __half* dst;
    if (idx4 < D_ * D_)              { src = Wq;  dst = wq;  }
    else if (idx4 < 3 * D_ * D_)     { src = Wkv; dst = wkv; idx4 -= D_ * D_; }
    else                             { src = Wo;  dst = wo;  idx4 -= 3 * D_ * D_; }
    float4 v = *(const float4*)(src + idx4);
    *(__half2*)(dst + idx4)     = __floats2half2_rn(v.x, v.y);
    *(__half2*)(dst + idx4 + 2) = __floats2half2_rn(v.z, v.w);
}

// ========== per-head write helpers for GEMM epilogues ==========
__device__ __forceinline__ void write_q_pair(int mrow, int n, float2 v) {
    int b = mrow >> 10, qr = mrow & 1023, h = n >> 6, d = n & 63;
    __half* dst = g_q1 + ((size_t)((b * H_ + h) * LQ_ + qr)) * HD_ + d;
    *(__half2*)dst = __floats2half2_rn(v.x, v.y);
}
__device__ __forceinline__ void write_kv_pair(int mrow, int n, float2 v) {
    int b = mrow >> 11, kr = mrow & 2047;
    int h2 = n >> 6, d = n & 63;
    __half* dst = (h2 < H_)
        ? g_k1 + ((size_t)((b * H_ + h2) * LKV_ + kr)) * HD_ + d
        : g_v1 + ((size_t)((b * H_ + (h2 - H_)) * LKV_ + kr)) * HD_ + d;
    *(__half2*)dst = __floats2half2_rn(v.x, v.y);
}

// ================= fp16 warp-MMA GEMM body (BK=64, 2-stage cp.async) =================
// C-tile = A[m0:+128,1024] @ W[n0:+128,1024]^T. 8 warps 32x64, BK=64, NK=16.
// MODE 0: fp32 C + bias + residual; MODE 1: Q per-head; MODE 2: KV per-head.
#define SST2 72                          // fp16 per smem row (144B, conflict-free)
#define GST2_BYTES (128 * SST2 * 2)      // 18432 B per operand per stage
#define GEMM_SMEM (4 * GST2_BYTES)       // 73728 B (2 stages x {A,B})
#define NKG (D_ / 64)   // 16

template <int MODE>
__device__ __forceinline__ void gemm_body(
    const __half* __restrict__ A, const __half* __restrict__ W,
    const float* __restrict__ bias, const float* __restrict__ R,
    float* __restrict__ C, int N, int m0, int n0, char* gsm)
{
    const uint32_t smem_u = smem_to_u32(gsm);
    const uint32_t sa_u = smem_u;                         // stages 0,1
    const uint32_t sb_u = smem_u + 2 * GST2_BYTES;        // stages 0,1

    const int tid  = threadIdx.x;
    const int lane = tid & 31;
    const int wid  = tid >> 5;
    const int warp_m = wid & 3;
    const int warp_n = wid >> 2;

    // loader: 1024 16B-units per operand per stage; 4 per thread
    const int lr = tid >> 1;             // 0..127 over 2 reps of rows? (row = idx>>3)
    (void)lr;

    float acc[2][8][4];
    #pragma unroll
    for (int i = 0; i < 2; i++)
        #pragma unroll
        for (int j = 0; j < 8; j++)
            #pragma unroll
            for (int t = 0; t < 4; t++) acc[i][j][t] = 0.0f;

    const uint32_t a_off = (uint32_t)((warp_m * 32 + (lane & 15)) * SST2 * 2
                                      + (lane >> 4) * 16);
    const uint32_t b_off = (uint32_t)((warp_n * 64 + ((lane >> 4) & 1) * 8 + (lane & 7)) * SST2 * 2
                                      + ((lane >> 3) & 1) * 16);

    auto issue_stage = [&](int kt, int buf) {
        const size_t koff = (size_t)kt * 64;
        const uint32_t sa_s = sa_u + (uint32_t)(buf * GST2_BYTES);
        const uint32_t sb_s = sb_u + (uint32_t)(buf * GST2_BYTES);
        #pragma unroll
        for (int rep = 0; rep < 4; rep++) {
            int idx = rep * 256 + tid;
            int r = idx >> 3, u = idx & 7;
            uint32_t off = (uint32_t)((r * SST2 + u * 8) * 2);
            cp_async16(sa_s + off, A + (size_t)(m0 + r) * D_ + koff + u * 8);
            cp_async16(sb_s + off, W + (size_t)(n0 + r) * D_ + koff + u * 8);
        }
        CP_ASYNC_COMMIT();
    };

    issue_stage(0, 0);

    for (int kt = 0; kt < NKG; kt++) {
        CP_ASYNC_WAIT(0);
        __syncthreads();
        if (kt + 1 < NKG) issue_stage(kt + 1, (kt + 1) & 1);   // overlaps compute

        const uint32_t sa_cur = sa_u + (uint32_t)((kt & 1) * GST2_BYTES);
        const uint32_t sb_cur = sb_u + (uint32_t)((kt & 1) * GST2_BYTES);
        #pragma unroll
        for (int ks = 0; ks < 4; ks++) {
            uint32_t a_frag[2][4];
            #pragma unroll
            for (int im = 0; im < 2; im++)
                ldmatrix_x4(a_frag[im], sa_cur + a_off
                            + (uint32_t)(im * 16 * SST2 * 2 + ks * 32));
            uint32_t b_frag[4][4];
            #pragma unroll
            for (int iu = 0; iu < 4; iu++)
                ldmatrix_x4(b_frag[iu], sb_cur + b_off
                            + (uint32_t)(iu * 16 * SST2 * 2 + ks * 32));
            #pragma unroll
            for (int im = 0; im < 2; im++)
                #pragma unroll
                for (int iu = 0; iu < 4; iu++) {
                    mma_16816(acc[im][iu * 2 + 0], a_frag[im], b_frag[iu][0], b_frag[iu][1]);
                    mma_16816(acc[im][iu * 2 + 1], a_frag[im], b_frag[iu][2], b_frag[iu][3]);
                }
        }
        __syncthreads();   // WAR: stage buf is re-filled next iteration
    }

    const int gr = lane >> 2;
    const int gc = (lane & 3) * 2;
    #pragma unroll
    for (int im = 0; im < 2; im++) {
        const int mrow = m0 + warp_m * 32 + im * 16 + gr;
        #pragma unroll
        for (int in = 0; in < 8; in++) {
            const int n = n0 + warp_n * 64 + in * 8 + gc;
            float b0 = bias[n], b1 = bias[n + 1];
            float2 v0 = make_float2(acc[im][in][0] + b0, acc[im][in][1] + b1);
            float2 v1 = make_float2(acc[im][in][2] + b0, acc[im][in][3] + b1);
            if (MODE == 0) {
                float2 r0 = *(const float2*)(R + (size_t)mrow * N + n);
                float2 r1 = *(const float2*)(R + (size_t)(mrow + 8) * N + n);
                v0.x += r0.x; v0.y += r0.y;
                v1.x += r1.x; v1.y += r1.y;
                *(float2*)(C + (size_t)mrow * N + n)       = v0;
                *(float2*)(C + (size_t)(mrow + 8) * N + n) = v1;
            } else if (MODE == 1) {
                write_q_pair(mrow,     n, v0);
                write_q_pair(mrow + 8, n, v1);
            } else {
                write_kv_pair(mrow,     n, v0);
                write_kv_pair(mrow + 8, n, v1);
            }
        }
    }
}

// fused Q+KV projection: blocks [0,1024) = KV tiles, [1024,1280) = Q tiles.
__global__ void __launch_bounds__(256, 2) proj_qkv_kernel(
    const __half* __restrict__ qk, const __half* __restrict__ kvk,
    const __half* __restrict__ wq, const __half* __restrict__ wkv,
    const float* __restrict__ bq, const float* __restrict__ bkv)
{
    extern __shared__ char gsm[];
    const int bid = blockIdx.x;
    if (bid < 1024) {
        const int m0 = (bid >> 4) * 128, n0 = (bid & 15) * 128;
        const int b = m0 >> 11, kr0 = m0 & 2047;
        if (kr0 >= g_len[b]) return;   // attention never reads these kv rows
        gemm_body<2>(kvk, wkv, bkv, nullptr, nullptr, 2 * D_, m0, n0, gsm);
    } else {
        const int r = bid - 1024;
        const int m0 = (r >> 3) * 128, n0 = (r & 7) * 128;
        gemm_body<1>(qk, wq, bq, nullptr, nullptr, D_, m0, n0, gsm);
    }
}

// O projection + residual
__global__ void __launch_bounds__(256, 2) proj_o_kernel(
    const __half* __restrict__ ak, const __half* __restrict__ wo,
    const float* __restrict__ bo, const float* __restrict__ R,
    float* __restrict__ out)
{
    extern __shared__ char gsm[];
    const int bid = blockIdx.x;
    const int m0 = (bid >> 3) * 128, n0 = (bid & 7) * 128;
    gemm_body<0>(ak, wo, bo, R, out, D_, m0, n0, gsm);
}

// ================= fp16 HMMA flash attention =================
// P in registers; 3 KV buffers (one barrier per tile); 2 CTAs/SM.
#define AQ  128
#define SQ  72     // smem row stride in fp16 (144B)
#define KTILE 4608             // 64 * SQ (halfs)
// smem (fp16 elem offsets): Ks[3]: 0,4608,9216  Vs[3]: 13824,18432,23040  Qs: 27648
#define FA_SMEM_BYTES ((27648 + 9216) * 2)   // 73728

__global__ void __launch_bounds__(256, 2) flash_attn_mma_kernel(
    const __half* __restrict__ q1, const __half* __restrict__ k1,
    const __half* __restrict__ v1, __half* __restrict__ outk)
{
    extern __shared__ __half smem_h[];
    __half* Qs = smem_h + 27648;

    const int b = blockIdx.z, h = blockIdx.y, qt = blockIdx.x;
    const int tid = threadIdx.x, lane = tid & 31, wid = tid >> 5;
    const int gr = lane >> 2, gc = (lane & 3) * 2;

    const uint32_t smem_u = smem_to_u32(smem_h);
    const uint32_t ks_u = smem_u;
    const uint32_t vs_u = smem_u + 3 * KTILE * 2;
    const uint32_t qs_u = smem_u + 27648 * 2;

    // ---- load Q tile [128][64] ----
    const __half* qg = q1 + ((size_t)((b * H_ + h) * LQ_ + qt * AQ)) * HD_;
    #pragma unroll
    for (int rep = 0; rep < 4; rep++) {
        int idx = rep * 256 + tid;
        int r = idx >> 3, u = idx & 7;
        *(uint4*)&Qs[r * SQ + u * 8] = *(const uint4*)(qg + (size_t)r * HD_ + u * 8);
    }
    __syncthreads();

    // ---- preload Q a-frags (4 k16-steps) ----
    uint32_t qfrag[4][4];
    const uint32_t a_base = qs_u + (uint32_t)((wid * 16 + (lane & 15)) * SQ * 2
                                              + (lane >> 4) * 16);
    #pragma unroll
    for (int ks = 0; ks < 4; ks++)
        ldmatrix_x4(qfrag[ks], a_base + (uint32_t)(ks * 32));

    const uint32_t kb_off = (uint32_t)((((lane >> 4) & 1) * 8 + (lane & 7)) * SQ * 2
                                       + ((lane >> 3) & 1) * 16);
    const uint32_t vb_off = (uint32_t)(((lane & 7) + ((lane >> 3) & 1) * 8) * SQ * 2
                                       + (lane >> 4) * 16);

    const int len   = g_len[b];
    const int ntile = (len + 63) >> 6;

    const __half* kbase = k1 + ((size_t)((b * H_ + h) * LKV_)) * HD_;
    const __half* vbase = v1 + ((size_t)((b * H_ + h) * LKV_)) * HD_;

    auto issue_tile = [&](int kt, int buf) {
        const __half* kg = kbase + (size_t)(kt * 64) * HD_;
        const __half* vg = vbase + (size_t)(kt * 64) * HD_;
        const uint32_t kdst = ks_u + (uint32_t)(buf * KTILE * 2);
        const uint32_t vdst = vs_u + (uint32_t)(buf * KTILE * 2);
        #pragma unroll
        for (int rep = 0; rep < 2; rep++) {
            int idx = rep * 256 + tid;
            int r = idx >> 3, u = idx & 7;
            uint32_t off = (uint32_t)((r * SQ + u * 8) * 2);
            cp_async16(kdst + off, kg + (size_t)r * HD_ + u * 8);
            cp_async16(vdst + off, vg + (size_t)r * HD_ + u * 8);
        }
        CP_ASYNC_COMMIT();
    };

    float m_r[2] = {-1e30f, -1e30f};
    float l_r[2] = {0.0f, 0.0f};
    float acc_o[8][4];
    #pragma unroll
    for (int i = 0; i < 8; i++)
        #pragma unroll
        for (int j = 0; j < 4; j++) acc_o[i][j] = 0.0f;

    issue_tile(0, 0);

    for (int kt = 0; kt < ntile; kt++) {
        const int buf = kt % 3;
        if (kt + 1 < ntile) issue_tile(kt + 1, (kt + 1) % 3);
        CP_ASYNC_WAIT(1);
        __syncthreads();   // single barrier per tile (3 buffers -> no WAR sync)

        const uint32_t kcur = ks_u + (uint32_t)(buf * KTILE * 2);
        const uint32_t vcur = vs_u + (uint32_t)(buf * KTILE * 2);

        // ---- S = Q @ K^T (4 k16-steps) ----
        float acc_s[8][4];
        #pragma unroll
        for (int i = 0; i < 8; i++)
            #pragma unroll
            for (int j = 0; j < 4; j++) acc_s[i][j] = 0.0f;

        #pragma unroll
        for (int ks = 0; ks < 4; ks++) {
            uint32_t bf[4][4];
            #pragma unroll
            for (int nt4 = 0; nt4 < 4; nt4++)
                ldmatrix_x4(bf[nt4], kcur + kb_off
                            + (uint32_t)(nt4 * 16 * SQ * 2 + ks * 32));
            #pragma unroll
            for (int nt4 = 0; nt4 < 4; nt4++) {
                mma_16816(acc_s[nt4 * 2 + 0], qfrag[ks], bf[nt4][0], bf[nt4][1]);
                mma_16816(acc_s[nt4 * 2 + 1], qfrag[ks], bf[nt4][2], bf[nt4][3]);
            }
        }

        // ---- scale + mask ----
        const int rem = len - kt * 64;
        #pragma unroll
        for (int nt = 0; nt < 8; nt++) {
            int c0 = nt * 8 + gc;
            bool k0 = (c0 >= rem), k1m = (c0 + 1 >= rem);
            acc_s[nt][0] = k0  ? -1e9f : acc_s[nt][0] * 0.125f;
            acc_s[nt][1] = k1m ? -1e9f : acc_s[nt][1] * 0.125f;
            acc_s[nt][2] = k0  ? -1e9f : acc_s[nt][2] * 0.125f;
            acc_s[nt][3] = k1m ? -1e9f : acc_s[nt][3] * 0.125f;
        }

        // ---- online softmax (rows gr, gr+8; reduce over lane&3 group) ----
        float tmax0 = -1e30f, tmax1 = -1e30f;
        #pragma unroll
        for (int nt = 0; nt < 8; nt++) {
            tmax0 = fmaxf(tmax0, fmaxf(acc_s[nt][0], acc_s[nt][1]));
            tmax1 = fmaxf(tmax1, fmaxf(acc_s[nt][2], acc_s[nt][3]));
        }
        #pragma unroll
        for (int o = 1; o < 4; o <<= 1) {
            tmax0 = fmaxf(tmax0, __shfl_xor_sync(0xffffffffu, tmax0, o));
            tmax1 = fmaxf(tmax1, __shfl_xor_sync(0xffffffffu, tmax1, o));
        }
        float mn0 = fmaxf(m_r[0], tmax0), mn1 = fmaxf(m_r[1], tmax1);
        float al0 = __expf(m_r[0] - mn0), al1 = __expf(m_r[1] - mn1);
        float rs0 = 0.0f, rs1 = 0.0f;
        #pragma unroll
        for (int nt = 0; nt < 8; nt++) {
            acc_s[nt][0] = __expf(acc_s[nt][0] - mn0);
            acc_s[nt][1] = __expf(acc_s[nt][1] - mn0);
            acc_s[nt][2] = __expf(acc_s[nt][2] - mn1);
            acc_s[nt][3] = __expf(acc_s[nt][3] - mn1);
            rs0 += acc_s[nt][0] + acc_s[nt][1];
            rs1 += acc_s[nt][2] + acc_s[nt][3];
        }
        #pragma unroll
        for (int o = 1; o < 4; o <<= 1) {
            rs0 += __shfl_xor_sync(0xffffffffu, rs0, o);
            rs1 += __shfl_xor_sync(0xffffffffu, rs1, o);
        }
        l_r[0] = l_r[0] * al0 + rs0;  m_r[0] = mn0;
        l_r[1] = l_r[1] * al1 + rs1;  m_r[1] = mn1;
        #pragma unroll
        for (int nt = 0; nt < 8; nt++) {
            acc_o[nt][0] *= al0; acc_o[nt][1] *= al0;
            acc_o[nt][2] *= al1; acc_o[nt][3] *= al1;
        }

        // ---- O += P @ V, P converted in registers (C-frag == A-frag layout) ----
        #pragma unroll
        for (int ks4 = 0; ks4 < 4; ks4++) {
            uint32_t af[4];
            __half2 t0 = __floats2half2_rn(acc_s[2 * ks4][0],     acc_s[2 * ks4][1]);
            __half2 t1 = __floats2half2_rn(acc_s[2 * ks4][2],     acc_s[2 * ks4][3]);
            __half2 t2 = __floats2half2_rn(acc_s[2 * ks4 + 1][0], acc_s[2 * ks4 + 1][1]);
            __half2 t3 = __floats2half2_rn(acc_s[2 * ks4 + 1][2], acc_s[2 * ks4 + 1][3]);
            af[0] = *(uint32_t*)&t0;
            af[1] = *(uint32_t*)&t1;
            af[2] = *(uint32_t*)&t2;
            af[3] = *(uint32_t*)&t3;
            uint32_t bf[4][4];
            #pragma unroll
            for (int g = 0; g < 4; g++)
                ldmatrix_x4_trans(bf[g], vcur + vb_off
                                  + (uint32_t)(ks4 * 16 * SQ * 2 + g * 32));
            #pragma unroll
            for (int g = 0; g < 4; g++) {
                mma_16816(acc_o[g * 2 + 0], af, bf[g][0], bf[g][1]);
                mma_16816(acc_o[g * 2 + 1], af, bf[g][2], bf[g][3]);
            }
        }
    }

    // ---- epilogue: normalize + write fp16 rows [M, 1024] ----
    float inv0 = 1.0f / l_r[0], inv1 = 1.0f / l_r[1];
    const int qrow0 = qt * AQ + wid * 16 + gr;
    __half* p0 = outk + ((size_t)(b * LQ_ + qrow0)) * D_ + h * HD_;
    __half* p1 = p0 + (size_t)8 * D_;
    #pragma unroll
    for (int nt = 0; nt < 8; nt++) {
        int col = nt * 8 + gc;
        *(__half2*)(p0 + col) = __floats2half2_rn(acc_o[nt][0] * inv0,
                                                  acc_o[nt][1] * inv0);
        *(__half2*)(p1 + col) = __floats2half2_rn(acc_o[nt][2] * inv1,
                                                  acc_o[nt][3] * inv1);
    }
}

// ================= host launcher =================
extern "C" void kernel_launch(void* const* d_in, const int* in_sizes, int n_in,
                              void* d_out, int out_size) {
    const float*         q    = (const float*)d_in[0];
    const float*         kv   = (const float*)d_in[1];
    const unsigned char* mask = (const unsigned char*)d_in[2];
    const float*         nqw  = (const float*)d_in[3];
    const float*         nqb  = (const float*)d_in[4];
    const float*         nkw  = (const float*)d_in[5];
    const float*         nkb  = (const float*)d_in[6];
    const float*         Wq   = (const float*)d_in[7];
    const float*         bq   = (const float*)d_in[8];
    const float*         Wkv  = (const float*)d_in[9];
    const float*         bkv  = (const float*)d_in[10];
    const float*         Wo   = (const float*)d_in[11];
    const float*         bo   = (const float*)d_in[12];
    float* out = (float*)d_out;

    __half *qk, *kvk, *ak, *wq, *wkv, *wo, *q1, *k1, *v1;
    cudaGetSymbolAddress((void**)&qk,  g_qk);
    cudaGetSymbolAddress((void**)&kvk, g_kvk);
    cudaGetSymbolAddress((void**)&ak,  g_ak);
    cudaGetSymbolAddress((void**)&wq,  g_wq);
    cudaGetSymbolAddress((void**)&wkv, g_wkv);
    cudaGetSymbolAddress((void**)&wo,  g_wo);
    cudaGetSymbolAddress((void**)&q1,  g_q1);
    cudaGetSymbolAddress((void**)&k1,  g_k1);
    cudaGetSymbolAddress((void**)&v1,  g_v1);

    cudaFuncSetAttribute(flash_attn_mma_kernel,
                         cudaFuncAttributeMaxDynamicSharedMemorySize, FA_SMEM_BYTES);
    cudaFuncSetAttribute(proj_qkv_kernel,
                         cudaFuncAttributeMaxDynamicSharedMemorySize, GEMM_SMEM);
    cudaFuncSetAttribute(proj_o_kernel,
                         cudaFuncAttributeMaxDynamicSharedMemorySize, GEMM_SMEM);

    compute_lengths_kernel<<<1, 256>>>(mask);                              // 0
    weight_fp16_all_kernel<<<(4 * D_ * D_) / 1024, 256>>>(Wq, Wkv, Wo,
                                                          wq, wkv, wo);    // 1
    layernorm_all_kernel<<<B_ * (LQ_ + LKV_), 256>>>(q, kv, nqw, nqb,
                                                     nkw, nkb, qk, kvk);   // 2

    proj_qkv_kernel<<<1280, 256, GEMM_SMEM>>>(qk, kvk, wq, wkv, bq, bkv);  // 3

    flash_attn_mma_kernel<<<dim3(LQ_ / AQ, H_, B_), 256, FA_SMEM_BYTES>>>(
        q1, k1, v1, ak);                                                    // 4

    proj_o_kernel<<<256, 256, GEMM_SMEM>>>(ak, wo, bo, q, out);             // 5
}